// round 3
// baseline (speedup 1.0000x reference)
#include <cuda_runtime.h>

// ---------------- problem constants ----------------
#define BATCH 8
#define C 768
#define S 729               // 9^3
#define NH 8
#define DH 96               // C / NH
#define HID 2048
#define NEXP 3
#define BS (BATCH * S)      // 5832 tokens
#define EPS 1e-5f

// ---------------- static device scratch (no allocs allowed) ----------------
__device__ float g_tok1[(long)BS * C];            // LN output, token-major (b*s, c)
__device__ float g_qkv [(long)BS * 3 * C];        // qkv GEMM output (b*s, 3C)
__device__ float g_attn[(long)BATCH * NH * S * S];// attention scores / probs
__device__ float g_o   [(long)BS * C];            // attention output, token-major
__device__ float g_tok2[(long)BS * C];            // proj output, then x+proj (tok2)
__device__ float g_gbuf[(long)BS * HID];          // gate GEMM out, then hid
__device__ float g_ubuf[(long)BS * HID];          // up GEMM out
__device__ float g_acc [(long)BS * C];            // MoE accumulator (b*s, c)
__device__ float g_w   [(long)BS * NEXP];         // routing weights
__device__ float g_stats[BATCH * 2];              // mean, var per batch

// ---------------- LayerNorm statistics (one block per batch) ----------------
__global__ void stats_kernel(const float* __restrict__ x) {
    int b = blockIdx.x;
    const float* xb = x + (long)b * C * S;
    const int N = C * S;
    float s = 0.f, s2 = 0.f;
    for (int i = threadIdx.x; i < N; i += blockDim.x) {
        float v = xb[i];
        s += v; s2 += v * v;
    }
    __shared__ float sh[256], sh2[256];
    int tid = threadIdx.x;
    sh[tid] = s; sh2[tid] = s2;
    __syncthreads();
    for (int st = 128; st > 0; st >>= 1) {
        if (tid < st) { sh[tid] += sh[tid + st]; sh2[tid] += sh2[tid + st]; }
        __syncthreads();
    }
    if (tid == 0) {
        float m = sh[0] / (float)N;
        g_stats[b * 2 + 0] = m;
        g_stats[b * 2 + 1] = sh2[0] / (float)N - m * m;  // biased var (jnp.var)
    }
}

// ---------------- LN apply + transpose to token-major ----------------
__global__ void ln_kernel(const float* __restrict__ x,
                          const float* __restrict__ w,
                          const float* __restrict__ bia) {
    long idx = (long)blockIdx.x * blockDim.x + threadIdx.x;
    if (idx >= (long)BATCH * C * S) return;
    int b   = (int)(idx / ((long)C * S));
    int rem = (int)(idx % ((long)C * S));
    int c = rem / S, s = rem % S;
    float m   = g_stats[b * 2 + 0];
    float var = g_stats[b * 2 + 1];
    float y = (x[idx] - m) * rsqrtf(var + EPS) * w[rem] + bia[rem];
    g_tok1[((long)b * S + s) * C + c] = y;
}

// ---------------- generic register-blocked SGEMM ----------------
// C[m,n] = sum_k A[m,k] * B'[k,n],   B' = B (NN) or B^T (TB=true, B stored (N,K))
// Two-level batch offsets: z1 = z/div, z2 = z%div, ptr += z1*stride + z2*stride2.
// VMODE: 0 = scalar; 1 = NN-vec (float4 A along K, float4 B along N; needs
//        K%BK==0, N%BN==0, 16B-aligned rows); 2 = TB-vec (float4 along K for
//        both tiles; needs K%BK==0, 16B-aligned rows, M/N edge zero-fill).
template<int BM, int BN, int BK, int TM, int TN, bool TB, bool ACC, int VMODE>
__global__ void __launch_bounds__((BM / TM) * (BN / TN))
sgemm_kernel(const float* __restrict__ A, const float* __restrict__ B,
             float* __restrict__ Cm,
             int M, int N, int K, int lda, int ldb, int ldc,
             long sA, long sA2, long sB, long sB2, long sC, long sC2, int div) {
    const int RT = BM / TM;          // thread rows
    const int CT = BN / TN;          // thread cols
    const int THREADS = RT * CT;

    int z  = blockIdx.z;
    int z1 = z / div, z2 = z % div;
    A  += z1 * sA + z2 * sA2;
    B  += z1 * sB + z2 * sB2;
    Cm += z1 * sC + z2 * sC2;

    __shared__ float As[BK][BM];
    __shared__ float Bs[BK][BN];

    int tid = threadIdx.x;
    int tx = tid % CT;
    int ty = tid / CT;
    int row0 = blockIdx.y * BM;
    int col0 = blockIdx.x * BN;

    float acc[TM][TN];
#pragma unroll
    for (int i = 0; i < TM; i++)
#pragma unroll
        for (int j = 0; j < TN; j++) acc[i][j] = 0.f;

    for (int k0 = 0; k0 < K; k0 += BK) {
        if (VMODE == 1) {
            // A tile: one float4 along K per thread
            {
                int m  = tid / (BK / 4);
                int kv = (tid % (BK / 4)) * 4;
                int gm = row0 + m;
                float4 v = make_float4(0.f, 0.f, 0.f, 0.f);
                if (gm < M)
                    v = *reinterpret_cast<const float4*>(&A[(long)gm * lda + k0 + kv]);
                As[kv + 0][m] = v.x;
                As[kv + 1][m] = v.y;
                As[kv + 2][m] = v.z;
                As[kv + 3][m] = v.w;
            }
            // B tile: one float4 along N per thread (no bounds needed)
            {
                int kk = tid / (BN / 4);
                int n0 = (tid % (BN / 4)) * 4;
                float4 v = *reinterpret_cast<const float4*>(&B[(long)(k0 + kk) * ldb + col0 + n0]);
                *reinterpret_cast<float4*>(&Bs[kk][n0]) = v;
            }
        } else if (VMODE == 2) {
            // A tile: float4 along K
            {
                int m  = tid / (BK / 4);
                int kv = (tid % (BK / 4)) * 4;
                int gm = row0 + m;
                float4 v = make_float4(0.f, 0.f, 0.f, 0.f);
                if (gm < M)
                    v = *reinterpret_cast<const float4*>(&A[(long)gm * lda + k0 + kv]);
                As[kv + 0][m] = v.x;
                As[kv + 1][m] = v.y;
                As[kv + 2][m] = v.z;
                As[kv + 3][m] = v.w;
            }
            // B tile (stored (N,K)): float4 along K
            {
                int n  = tid / (BK / 4);
                int kv = (tid % (BK / 4)) * 4;
                int gn = col0 + n;
                float4 v = make_float4(0.f, 0.f, 0.f, 0.f);
                if (gn < N)
                    v = *reinterpret_cast<const float4*>(&B[(long)gn * ldb + k0 + kv]);
                Bs[kv + 0][n] = v.x;
                Bs[kv + 1][n] = v.y;
                Bs[kv + 2][n] = v.z;
                Bs[kv + 3][n] = v.w;
            }
        } else {
            // load A tile (BM x BK) -> As[k][m]
            for (int i = tid; i < BM * BK; i += THREADS) {
                int m = i / BK, kk = i % BK;
                int gm = row0 + m, gk = k0 + kk;
                As[kk][m] = (gm < M && gk < K) ? A[(long)gm * lda + gk] : 0.f;
            }
            // load B tile (BK x BN) -> Bs[k][n]
            if (!TB) {
                for (int i = tid; i < BK * BN; i += THREADS) {
                    int kk = i / BN, n = i % BN;
                    int gk = k0 + kk, gn = col0 + n;
                    Bs[kk][n] = (gk < K && gn < N) ? B[(long)gk * ldb + gn] : 0.f;
                }
            } else {
                for (int i = tid; i < BK * BN; i += THREADS) {
                    int n = i / BK, kk = i % BK;
                    int gk = k0 + kk, gn = col0 + n;
                    Bs[kk][n] = (gk < K && gn < N) ? B[(long)gn * ldb + gk] : 0.f;
                }
            }
        }
        __syncthreads();

#pragma unroll
        for (int kk = 0; kk < BK; kk++) {
            float af[TM], bf[TN];
#pragma unroll
            for (int i = 0; i < TM; i++) af[i] = As[kk][ty + i * RT];
#pragma unroll
            for (int j = 0; j < TN; j++) bf[j] = Bs[kk][tx + j * CT];
#pragma unroll
            for (int i = 0; i < TM; i++)
#pragma unroll
                for (int j = 0; j < TN; j++) acc[i][j] += af[i] * bf[j];
        }
        __syncthreads();
    }

#pragma unroll
    for (int i = 0; i < TM; i++) {
        int gm = row0 + ty + i * RT;
        if (gm >= M) continue;
#pragma unroll
        for (int j = 0; j < TN; j++) {
            int gn = col0 + tx + j * CT;
            if (gn < N) {
                long o = (long)gm * ldc + gn;
                if (ACC) Cm[o] += acc[i][j];
                else     Cm[o]  = acc[i][j];
            }
        }
    }
}

// ---------------- row softmax over attention scores ----------------
__global__ void softmax_kernel(float* __restrict__ attn) {
    long row = blockIdx.x;
    float* p = attn + row * (long)S;
    int tid = threadIdx.x;
    __shared__ float sh[256];

    float mx = -1e30f;
    for (int i = tid; i < S; i += blockDim.x) mx = fmaxf(mx, p[i]);
    sh[tid] = mx; __syncthreads();
    for (int st = 128; st > 0; st >>= 1) {
        if (tid < st) sh[tid] = fmaxf(sh[tid], sh[tid + st]);
        __syncthreads();
    }
    mx = sh[0]; __syncthreads();

    float sum = 0.f;
    for (int i = tid; i < S; i += blockDim.x) {
        float e = __expf(p[i] - mx);
        p[i] = e; sum += e;
    }
    sh[tid] = sum; __syncthreads();
    for (int st = 128; st > 0; st >>= 1) {
        if (tid < st) sh[tid] += sh[tid + st];
        __syncthreads();
    }
    float inv = 1.f / sh[0];
    for (int i = tid; i < S; i += blockDim.x) p[i] *= inv;
}

// ---------------- residual: out(b,c,s) = x + proj; tok2(b,s,c) = same ----------------
__global__ void residual_kernel(const float* __restrict__ x, float* __restrict__ out) {
    long idx = (long)blockIdx.x * blockDim.x + threadIdx.x;
    if (idx >= (long)BATCH * C * S) return;
    int b   = (int)(idx / ((long)C * S));
    int rem = (int)(idx % ((long)C * S));
    int c = rem / S, s = rem % S;
    long t = ((long)b * S + s) * C + c;
    float v = x[idx] + g_tok2[t];
    out[idx] = v;
    g_tok2[t] = v;
}

// ---------------- router: softmax over 3 logits, top-2, renormalize ----------------
__global__ void router_kernel(const float* __restrict__ rw) {
    int t = blockIdx.x * blockDim.y + threadIdx.y;
    if (t >= BS) return;
    const float* tok = g_tok2 + (long)t * C;
    float l0 = 0.f, l1 = 0.f, l2 = 0.f;
    for (int c = threadIdx.x; c < C; c += 32) {
        float v = tok[c];
        l0 += v * rw[c * 3 + 0];
        l1 += v * rw[c * 3 + 1];
        l2 += v * rw[c * 3 + 2];
    }
#pragma unroll
    for (int off = 16; off > 0; off >>= 1) {
        l0 += __shfl_down_sync(0xFFFFFFFFu, l0, off);
        l1 += __shfl_down_sync(0xFFFFFFFFu, l1, off);
        l2 += __shfl_down_sync(0xFFFFFFFFu, l2, off);
    }
    if (threadIdx.x == 0) {
        float mx = fmaxf(l0, fmaxf(l1, l2));
        float e0 = __expf(l0 - mx), e1 = __expf(l1 - mx), e2 = __expf(l2 - mx);
        float tot = e0 + e1 + e2;
        float p[3] = { e0 / tot, e1 / tot, e2 / tot };
        int i1 = 0;
        if (p[1] > p[i1]) i1 = 1;
        if (p[2] > p[i1]) i1 = 2;
        int i2 = -1;
        for (int i = 0; i < 3; i++) {
            if (i == i1) continue;
            if (i2 < 0 || p[i] > p[i2]) i2 = i;
        }
        float den = p[i1] + p[i2];
        float w[3] = { 0.f, 0.f, 0.f };
        w[i1] = p[i1] / den;
        w[i2] = p[i2] / den;
        g_w[t * 3 + 0] = w[0];
        g_w[t * 3 + 1] = w[1];
        g_w[t * 3 + 2] = w[2];
    }
}

// ---------------- hid = silu(g) * u * route_weight (in place into g_gbuf) ----------------
__global__ void swiglu_kernel(int e) {
    long idx = (long)blockIdx.x * blockDim.x + threadIdx.x;
    if (idx >= (long)BS * HID) return;
    int t = (int)(idx / HID);
    float g = g_gbuf[idx];
    float u = g_ubuf[idx];
    float sig = 1.f / (1.f + __expf(-g));
    g_gbuf[idx] = g * sig * u * g_w[t * 3 + e];
}

// ---------------- out(b,c,s) += acc(b,s,c) ----------------
__global__ void final_kernel(float* __restrict__ out) {
    long idx = (long)blockIdx.x * blockDim.x + threadIdx.x;
    if (idx >= (long)BATCH * C * S) return;
    int b   = (int)(idx / ((long)C * S));
    int rem = (int)(idx % ((long)C * S));
    int c = rem / S, s = rem % S;
    out[idx] += g_acc[((long)b * S + s) * C + c];
}

// ---------------- launcher ----------------
extern "C" void kernel_launch(void* const* d_in, const int* in_sizes, int n_in,
                              void* d_out, int out_size) {
    const float* x        = (const float*)d_in[0];
    const float* ln_w     = (const float*)d_in[1];
    const float* ln_b     = (const float*)d_in[2];
    const float* qkv_w    = (const float*)d_in[3];
    const float* proj_w   = (const float*)d_in[4];
    const float* router_w = (const float*)d_in[5];
    const float* gate_w   = (const float*)d_in[6];
    const float* up_w     = (const float*)d_in[7];
    const float* down_w   = (const float*)d_in[8];
    float* out = (float*)d_out;

    float *p_tok1, *p_qkv, *p_attn, *p_o, *p_tok2, *p_gbuf, *p_ubuf, *p_acc;
    cudaGetSymbolAddress((void**)&p_tok1, g_tok1);
    cudaGetSymbolAddress((void**)&p_qkv,  g_qkv);
    cudaGetSymbolAddress((void**)&p_attn, g_attn);
    cudaGetSymbolAddress((void**)&p_o,    g_o);
    cudaGetSymbolAddress((void**)&p_tok2, g_tok2);
    cudaGetSymbolAddress((void**)&p_gbuf, g_gbuf);
    cudaGetSymbolAddress((void**)&p_ubuf, g_ubuf);
    cudaGetSymbolAddress((void**)&p_acc,  g_acc);

    const long n_elem = (long)BATCH * C * S;

    // 1) LayerNorm
    stats_kernel<<<BATCH, 256>>>(x);
    ln_kernel<<<(int)((n_elem + 255) / 256), 256>>>(x, ln_w, ln_b);

    // 2) qkv GEMM: (BS,3C) = tok1(BS,C) @ qkv_w(C,3C)
    {
        dim3 grid((3 * C + 127) / 128, (BS + 127) / 128, 1);
        sgemm_kernel<128, 128, 8, 8, 8, false, false, 1><<<grid, 256>>>(
            p_tok1, qkv_w, p_qkv, BS, 3 * C, C, C, 3 * C, 3 * C,
            0, 0, 0, 0, 0, 0, 1);
    }

    // 3) attention scores: per (b,h)  S x S = q @ k^T   (NT, K = DH, vectorized)
    {
        dim3 grid((S + 63) / 64, (S + 63) / 64, BATCH * NH);
        sgemm_kernel<64, 64, 16, 4, 4, true, false, 2><<<grid, 256>>>(
            p_qkv, p_qkv + C, p_attn, S, S, DH, 3 * C, 3 * C, S,
            (long)S * 3 * C, DH,                 // A offsets: b, h
            (long)S * 3 * C, DH,                 // B offsets: b, h
            (long)NH * S * S, (long)S * S,       // C offsets: b, h
            NH);
    }

    // 4) softmax per row
    softmax_kernel<<<BATCH * NH * S, 256>>>(p_attn);

    // 5) PV: per (b,h)  S x DH = attn(S,S) @ v(S,DH)   (NN, scalar: lda=729 unaligned)
    {
        dim3 grid((DH + 63) / 64, (S + 63) / 64, BATCH * NH);
        sgemm_kernel<64, 64, 16, 4, 4, false, false, 0><<<grid, 256>>>(
            p_attn, p_qkv + 2 * C, p_o, S, DH, S, S, 3 * C, C,
            (long)NH * S * S, (long)S * S,
            (long)S * 3 * C, DH,
            (long)S * C, DH,
            NH);
    }

    // 6) proj GEMM: (BS,C) = o @ proj_w
    {
        dim3 grid((C + 127) / 128, (BS + 127) / 128, 1);
        sgemm_kernel<128, 128, 8, 8, 8, false, false, 1><<<grid, 256>>>(
            p_o, proj_w, p_tok2, BS, C, C, C, C, C,
            0, 0, 0, 0, 0, 0, 1);
    }

    // 7) residual + tok2
    residual_kernel<<<(int)((n_elem + 255) / 256), 256>>>(x, out);

    // 8) router
    {
        dim3 blk(32, 8);
        router_kernel<<<(BS + 7) / 8, blk>>>(router_w);
    }

    // 9) MoE experts
    for (int e = 0; e < NEXP; e++) {
        dim3 g_gu((HID + 127) / 128, (BS + 127) / 128, 1);
        sgemm_kernel<128, 128, 8, 8, 8, false, false, 1><<<g_gu, 256>>>(
            p_tok2, gate_w + (long)e * C * HID, p_gbuf, BS, HID, C, C, HID, HID,
            0, 0, 0, 0, 0, 0, 1);
        sgemm_kernel<128, 128, 8, 8, 8, false, false, 1><<<g_gu, 256>>>(
            p_tok2, up_w + (long)e * C * HID, p_ubuf, BS, HID, C, C, HID, HID,
            0, 0, 0, 0, 0, 0, 1);

        long nh_elem = (long)BS * HID;
        swiglu_kernel<<<(int)((nh_elem + 255) / 256), 256>>>(e);

        dim3 g_dn((C + 127) / 128, (BS + 127) / 128, 1);
        if (e == 0) {
            sgemm_kernel<128, 128, 8, 8, 8, false, false, 1><<<g_dn, 256>>>(
                p_gbuf, down_w + (long)e * HID * C, p_acc, BS, C, HID, HID, C, C,
                0, 0, 0, 0, 0, 0, 1);
        } else {
            sgemm_kernel<128, 128, 8, 8, 8, false, true, 1><<<g_dn, 256>>>(
                p_gbuf, down_w + (long)e * HID * C, p_acc, BS, C, HID, HID, C, C,
                0, 0, 0, 0, 0, 0, 1);
        }
    }

    // 10) final add (transpose)
    final_kernel<<<(int)((n_elem + 255) / 256), 256>>>(out);
}

// round 5
// speedup vs baseline: 1.4455x; 1.4455x over previous
#include <cuda_runtime.h>
#include <cuda_bf16.h>
#include <cstdint>

// ---------------- problem constants ----------------
#define BATCH 8
#define C 768
#define S 729               // 9^3
#define NH 8
#define DH 96               // C / NH
#define HID 2048
#define NEXP 3
#define BS (BATCH * S)      // 5832 tokens
#define EPS 1e-5f

// ---------------- static device scratch (no allocs allowed) ----------------
__device__ float g_tok1[(long)BS * C];
__device__ float g_qkv [(long)BS * 3 * C];
__device__ float g_attn[(long)BATCH * NH * S * S];
__device__ float g_o   [(long)BS * C];
__device__ float g_tok2[(long)BS * C];
__device__ float g_gbuf[(long)BS * HID];
__device__ float g_ubuf[(long)BS * HID];
__device__ float g_acc [(long)BS * C];
__device__ float g_w   [(long)BS * NEXP];
__device__ float g_stats[BATCH * 2];

// split x,y into bf16 hi-pair and lo-pair (packed b32, x in low 16 bits)
__device__ __forceinline__ void hilo2(float x, float y, uint32_t& hi, uint32_t& lo) {
    __nv_bfloat16 hx = __float2bfloat16(x);
    __nv_bfloat16 hy = __float2bfloat16(y);
    __nv_bfloat162 hh; hh.x = hx; hh.y = hy;
    hi = *reinterpret_cast<uint32_t*>(&hh);
    float lx = x - __bfloat162float(hx);
    float ly = y - __bfloat162float(hy);
    __nv_bfloat162 ll = __floats2bfloat162_rn(lx, ly);
    lo = *reinterpret_cast<uint32_t*>(&ll);
}

__device__ __forceinline__ void mma16816(float* c, const uint32_t* a, const uint32_t* b) {
    asm volatile(
        "mma.sync.aligned.m16n8k16.row.col.f32.bf16.bf16.f32 "
        "{%0,%1,%2,%3}, {%4,%5,%6,%7}, {%8,%9}, {%0,%1,%2,%3};"
        : "+f"(c[0]), "+f"(c[1]), "+f"(c[2]), "+f"(c[3])
        : "r"(a[0]), "r"(a[1]), "r"(a[2]), "r"(a[3]), "r"(b[0]), "r"(b[1]));
}

// ================== HMMA bf16x3 GEMM ==================
// C(M,N) = A(M,K) @ W(K,N), fp32 row-major. K%32==0, N%128==0, M edge guarded.
// SMEM tiles hold b32 k-pairs: As2[m][kp] = {A[m][2kp], A[m][2kp+1]} (bf16x2),
// Bs2[n][kp] = {W[2kp][n], W[2kp+1][n]}.  Row stride 20 u32 (conflict-free).
#define KP 16           // k-pairs per 32-wide k chunk
#define LDT 20          // padded row stride in u32
template<bool ACC>
__global__ void __launch_bounds__(256)
hmma_gemm_kernel(const float* __restrict__ A, const float* __restrict__ W,
                 float* __restrict__ Cm, int M, int N, int K)
{
    __shared__ uint32_t sAhi[128 * LDT], sAlo[128 * LDT];
    __shared__ uint32_t sBhi[128 * LDT], sBlo[128 * LDT];

    const int tid = threadIdx.x;
    const int lane = tid & 31;
    const int w = tid >> 5;          // 0..7
    const int wm = w & 3;            // 4 m-groups of 32 rows
    const int wn = w >> 2;           // 2 n-groups of 64 cols
    const int gid = lane >> 2;       // 0..7
    const int tig = lane & 3;        // 0..3
    const int m0 = blockIdx.y * 128;
    const int n0 = blockIdx.x * 128;

    // A-load assignment: row = tid/2, khalf = tid&1 (16 fp32)
    const int arow = tid >> 1;
    const int akh = tid & 1;
    const bool aval = (m0 + arow) < M;
    const float* aptr = A + (long)(m0 + arow) * K + akh * 16;

    float acc[2][8][4];
#pragma unroll
    for (int i = 0; i < 2; i++)
#pragma unroll
        for (int j = 0; j < 8; j++)
#pragma unroll
            for (int q = 0; q < 4; q++) acc[i][j][q] = 0.f;

    for (int k0 = 0; k0 < K; k0 += 32) {
        // ---- load A tile 128x32 fp32 -> hi/lo k-pair b32 ----
        {
            uint32_t hi[8], lo[8];
            if (aval) {
                const float* p = aptr + k0;
#pragma unroll
                for (int q = 0; q < 4; q++) {
                    float4 v = *reinterpret_cast<const float4*>(p + q * 4);
                    hilo2(v.x, v.y, hi[q * 2], lo[q * 2]);
                    hilo2(v.z, v.w, hi[q * 2 + 1], lo[q * 2 + 1]);
                }
            } else {
#pragma unroll
                for (int q = 0; q < 8; q++) { hi[q] = 0u; lo[q] = 0u; }
            }
            uint32_t off = arow * LDT + akh * 8;
            *reinterpret_cast<uint4*>(&sAhi[off])     = *reinterpret_cast<uint4*>(&hi[0]);
            *reinterpret_cast<uint4*>(&sAhi[off + 4]) = *reinterpret_cast<uint4*>(&hi[4]);
            *reinterpret_cast<uint4*>(&sAlo[off])     = *reinterpret_cast<uint4*>(&lo[0]);
            *reinterpret_cast<uint4*>(&sAlo[off + 4]) = *reinterpret_cast<uint4*>(&lo[4]);
        }
        // ---- load B tile 32x128 fp32 (W rows k, cols n) -> transposed k-pair b32 ----
#pragma unroll
        for (int rep = 0; rep < 2; rep++) {
            int a = tid + rep * 256;       // 0..511
            int kp = a >> 5;               // 0..15
            int nn = (a & 31) * 4;         // 0..124
            const float* p0 = W + (long)(k0 + 2 * kp) * N + n0 + nn;
            float4 r0 = *reinterpret_cast<const float4*>(p0);
            float4 r1 = *reinterpret_cast<const float4*>(p0 + N);
            uint32_t hi, lo;
            hilo2(r0.x, r1.x, hi, lo);
            sBhi[(nn + 0) * LDT + kp] = hi; sBlo[(nn + 0) * LDT + kp] = lo;
            hilo2(r0.y, r1.y, hi, lo);
            sBhi[(nn + 1) * LDT + kp] = hi; sBlo[(nn + 1) * LDT + kp] = lo;
            hilo2(r0.z, r1.z, hi, lo);
            sBhi[(nn + 2) * LDT + kp] = hi; sBlo[(nn + 2) * LDT + kp] = lo;
            hilo2(r0.w, r1.w, hi, lo);
            sBhi[(nn + 3) * LDT + kp] = hi; sBlo[(nn + 3) * LDT + kp] = lo;
        }
        __syncthreads();

        // ---- compute: 2 k16 steps x 3 precision segments ----
#pragma unroll
        for (int k16 = 0; k16 < 2; k16++) {
            const int kb = k16 * 8;     // kpair base of this k16 window
            // A fragments (hi and lo) for both m-tiles
            uint32_t ahi[2][4], alo[2][4];
#pragma unroll
            for (int mt = 0; mt < 2; mt++) {
                int r0 = (wm * 32 + mt * 16 + gid) * LDT;
                int r8 = r0 + 8 * LDT;
                ahi[mt][0] = sAhi[r0 + kb + tig];
                ahi[mt][1] = sAhi[r8 + kb + tig];
                ahi[mt][2] = sAhi[r0 + kb + 4 + tig];
                ahi[mt][3] = sAhi[r8 + kb + 4 + tig];
                alo[mt][0] = sAlo[r0 + kb + tig];
                alo[mt][1] = sAlo[r8 + kb + tig];
                alo[mt][2] = sAlo[r0 + kb + 4 + tig];
                alo[mt][3] = sAlo[r8 + kb + 4 + tig];
            }
#pragma unroll
            for (int nt = 0; nt < 8; nt++) {
                int nr = (wn * 64 + nt * 8 + gid) * LDT;
                uint32_t bhi[2], blo[2];
                bhi[0] = sBhi[nr + kb + tig];
                bhi[1] = sBhi[nr + kb + 4 + tig];
                blo[0] = sBlo[nr + kb + tig];
                blo[1] = sBlo[nr + kb + 4 + tig];
#pragma unroll
                for (int mt = 0; mt < 2; mt++) {
                    mma16816(acc[mt][nt], ahi[mt], bhi);   // hi*hi
                    mma16816(acc[mt][nt], ahi[mt], blo);   // hi*lo
                    mma16816(acc[mt][nt], alo[mt], bhi);   // lo*hi
                }
            }
        }
        __syncthreads();
    }

    // ---- epilogue ----
#pragma unroll
    for (int mt = 0; mt < 2; mt++) {
        int row = m0 + wm * 32 + mt * 16 + gid;
#pragma unroll
        for (int nt = 0; nt < 8; nt++) {
            int col = n0 + wn * 64 + nt * 8 + tig * 2;
            if (row < M) {
                float2* p = reinterpret_cast<float2*>(Cm + (long)row * N + col);
                if (ACC) { float2 o = *p; o.x += acc[mt][nt][0]; o.y += acc[mt][nt][1]; *p = o; }
                else     { *p = make_float2(acc[mt][nt][0], acc[mt][nt][1]); }
            }
            if (row + 8 < M) {
                float2* p = reinterpret_cast<float2*>(Cm + (long)(row + 8) * N + col);
                if (ACC) { float2 o = *p; o.x += acc[mt][nt][2]; o.y += acc[mt][nt][3]; *p = o; }
                else     { *p = make_float2(acc[mt][nt][2], acc[mt][nt][3]); }
            }
        }
    }
}

// ---------------- LayerNorm statistics (one block per batch) ----------------
__global__ void stats_kernel(const float* __restrict__ x) {
    int b = blockIdx.x;
    const float* xb = x + (long)b * C * S;
    const int N = C * S;
    float s = 0.f, s2 = 0.f;
    for (int i = threadIdx.x; i < N; i += blockDim.x) {
        float v = xb[i];
        s += v; s2 += v * v;
    }
    __shared__ float sh[256], sh2[256];
    int tid = threadIdx.x;
    sh[tid] = s; sh2[tid] = s2;
    __syncthreads();
    for (int st = 128; st > 0; st >>= 1) {
        if (tid < st) { sh[tid] += sh[tid + st]; sh2[tid] += sh2[tid + st]; }
        __syncthreads();
    }
    if (tid == 0) {
        float m = sh[0] / (float)N;
        g_stats[b * 2 + 0] = m;
        g_stats[b * 2 + 1] = sh2[0] / (float)N - m * m;  // biased var (jnp.var)
    }
}

// ---------------- LN apply + transpose to token-major ----------------
__global__ void ln_kernel(const float* __restrict__ x,
                          const float* __restrict__ w,
                          const float* __restrict__ bia) {
    long idx = (long)blockIdx.x * blockDim.x + threadIdx.x;
    if (idx >= (long)BATCH * C * S) return;
    int b   = (int)(idx / ((long)C * S));
    int rem = (int)(idx % ((long)C * S));
    int c = rem / S, s = rem % S;
    float m   = g_stats[b * 2 + 0];
    float var = g_stats[b * 2 + 1];
    float y = (x[idx] - m) * rsqrtf(var + EPS) * w[rem] + bia[rem];
    g_tok1[((long)b * S + s) * C + c] = y;
}

// ---------------- generic register-blocked SGEMM (attention only) ----------------
template<int BM, int BN, int BK, int TM, int TN, bool TB, bool ACC, int VMODE>
__global__ void __launch_bounds__((BM / TM) * (BN / TN))
sgemm_kernel(const float* __restrict__ A, const float* __restrict__ B,
             float* __restrict__ Cm,
             int M, int N, int K, int lda, int ldb, int ldc,
             long sA, long sA2, long sB, long sB2, long sC, long sC2, int div) {
    const int RT = BM / TM;
    const int CT = BN / TN;
    const int THREADS = RT * CT;

    int z  = blockIdx.z;
    int z1 = z / div, z2 = z % div;
    A  += z1 * sA + z2 * sA2;
    B  += z1 * sB + z2 * sB2;
    Cm += z1 * sC + z2 * sC2;

    __shared__ float As[BK][BM];
    __shared__ float Bs[BK][BN];

    int tid = threadIdx.x;
    int tx = tid % CT;
    int ty = tid / CT;
    int row0 = blockIdx.y * BM;
    int col0 = blockIdx.x * BN;

    float acc[TM][TN];
#pragma unroll
    for (int i = 0; i < TM; i++)
#pragma unroll
        for (int j = 0; j < TN; j++) acc[i][j] = 0.f;

    for (int k0 = 0; k0 < K; k0 += BK) {
        if (VMODE == 2) {
            {
                int m  = tid / (BK / 4);
                int kv = (tid % (BK / 4)) * 4;
                int gm = row0 + m;
                float4 v = make_float4(0.f, 0.f, 0.f, 0.f);
                if (gm < M)
                    v = *reinterpret_cast<const float4*>(&A[(long)gm * lda + k0 + kv]);
                As[kv + 0][m] = v.x;
                As[kv + 1][m] = v.y;
                As[kv + 2][m] = v.z;
                As[kv + 3][m] = v.w;
            }
            {
                int n  = tid / (BK / 4);
                int kv = (tid % (BK / 4)) * 4;
                int gn = col0 + n;
                float4 v = make_float4(0.f, 0.f, 0.f, 0.f);
                if (gn < N)
                    v = *reinterpret_cast<const float4*>(&B[(long)gn * ldb + k0 + kv]);
                Bs[kv + 0][n] = v.x;
                Bs[kv + 1][n] = v.y;
                Bs[kv + 2][n] = v.z;
                Bs[kv + 3][n] = v.w;
            }
        } else {
            for (int i = tid; i < BM * BK; i += THREADS) {
                int m = i / BK, kk = i % BK;
                int gm = row0 + m, gk = k0 + kk;
                As[kk][m] = (gm < M && gk < K) ? A[(long)gm * lda + gk] : 0.f;
            }
            if (!TB) {
                for (int i = tid; i < BK * BN; i += THREADS) {
                    int kk = i / BN, n = i % BN;
                    int gk = k0 + kk, gn = col0 + n;
                    Bs[kk][n] = (gk < K && gn < N) ? B[(long)gk * ldb + gn] : 0.f;
                }
            } else {
                for (int i = tid; i < BK * BN; i += THREADS) {
                    int n = i / BK, kk = i % BK;
                    int gk = k0 + kk, gn = col0 + n;
                    Bs[kk][n] = (gk < K && gn < N) ? B[(long)gn * ldb + gk] : 0.f;
                }
            }
        }
        __syncthreads();

#pragma unroll
        for (int kk = 0; kk < BK; kk++) {
            float af[TM], bf[TN];
#pragma unroll
            for (int i = 0; i < TM; i++) af[i] = As[kk][ty + i * RT];
#pragma unroll
            for (int j = 0; j < TN; j++) bf[j] = Bs[kk][tx + j * CT];
#pragma unroll
            for (int i = 0; i < TM; i++)
#pragma unroll
                for (int j = 0; j < TN; j++) acc[i][j] += af[i] * bf[j];
        }
        __syncthreads();
    }

#pragma unroll
    for (int i = 0; i < TM; i++) {
        int gm = row0 + ty + i * RT;
        if (gm >= M) continue;
#pragma unroll
        for (int j = 0; j < TN; j++) {
            int gn = col0 + tx + j * CT;
            if (gn < N) {
                long o = (long)gm * ldc + gn;
                if (ACC) Cm[o] += acc[i][j];
                else     Cm[o]  = acc[i][j];
            }
        }
    }
}

// ---------------- row softmax over attention scores ----------------
__global__ void softmax_kernel(float* __restrict__ attn) {
    long row = blockIdx.x;
    float* p = attn + row * (long)S;
    int tid = threadIdx.x;
    __shared__ float sh[256];

    float mx = -1e30f;
    for (int i = tid; i < S; i += blockDim.x) mx = fmaxf(mx, p[i]);
    sh[tid] = mx; __syncthreads();
    for (int st = 128; st > 0; st >>= 1) {
        if (tid < st) sh[tid] = fmaxf(sh[tid], sh[tid + st]);
        __syncthreads();
    }
    mx = sh[0]; __syncthreads();

    float sum = 0.f;
    for (int i = tid; i < S; i += blockDim.x) {
        float e = __expf(p[i] - mx);
        p[i] = e; sum += e;
    }
    sh[tid] = sum; __syncthreads();
    for (int st = 128; st > 0; st >>= 1) {
        if (tid < st) sh[tid] += sh[tid + st];
        __syncthreads();
    }
    float inv = 1.f / sh[0];
    for (int i = tid; i < S; i += blockDim.x) p[i] *= inv;
}

// ---------------- residual: out(b,c,s) = x + proj; tok2(b,s,c) = same ----------------
__global__ void residual_kernel(const float* __restrict__ x, float* __restrict__ out) {
    long idx = (long)blockIdx.x * blockDim.x + threadIdx.x;
    if (idx >= (long)BATCH * C * S) return;
    int b   = (int)(idx / ((long)C * S));
    int rem = (int)(idx % ((long)C * S));
    int c = rem / S, s = rem % S;
    long t = ((long)b * S + s) * C + c;
    float v = x[idx] + g_tok2[t];
    out[idx] = v;
    g_tok2[t] = v;
}

// ---------------- router: softmax over 3 logits, top-2, renormalize ----------------
__global__ void router_kernel(const float* __restrict__ rw) {
    int t = blockIdx.x * blockDim.y + threadIdx.y;
    if (t >= BS) return;
    const float* tok = g_tok2 + (long)t * C;
    float l0 = 0.f, l1 = 0.f, l2 = 0.f;
    for (int c = threadIdx.x; c < C; c += 32) {
        float v = tok[c];
        l0 += v * rw[c * 3 + 0];
        l1 += v * rw[c * 3 + 1];
        l2 += v * rw[c * 3 + 2];
    }
#pragma unroll
    for (int off = 16; off > 0; off >>= 1) {
        l0 += __shfl_down_sync(0xFFFFFFFFu, l0, off);
        l1 += __shfl_down_sync(0xFFFFFFFFu, l1, off);
        l2 += __shfl_down_sync(0xFFFFFFFFu, l2, off);
    }
    if (threadIdx.x == 0) {
        float mx = fmaxf(l0, fmaxf(l1, l2));
        float e0 = __expf(l0 - mx), e1 = __expf(l1 - mx), e2 = __expf(l2 - mx);
        float tot = e0 + e1 + e2;
        float p[3] = { e0 / tot, e1 / tot, e2 / tot };
        int i1 = 0;
        if (p[1] > p[i1]) i1 = 1;
        if (p[2] > p[i1]) i1 = 2;
        int i2 = -1;
        for (int i = 0; i < 3; i++) {
            if (i == i1) continue;
            if (i2 < 0 || p[i] > p[i2]) i2 = i;
        }
        float den = p[i1] + p[i2];
        float w[3] = { 0.f, 0.f, 0.f };
        w[i1] = p[i1] / den;
        w[i2] = p[i2] / den;
        g_w[t * 3 + 0] = w[0];
        g_w[t * 3 + 1] = w[1];
        g_w[t * 3 + 2] = w[2];
    }
}

// ---------------- hid = silu(g) * u * route_weight (in place into g_gbuf) ----------------
__global__ void swiglu_kernel(int e) {
    long idx = (long)blockIdx.x * blockDim.x + threadIdx.x;
    if (idx >= (long)BS * HID) return;
    int t = (int)(idx / HID);
    float g = g_gbuf[idx];
    float u = g_ubuf[idx];
    float sig = 1.f / (1.f + __expf(-g));
    g_gbuf[idx] = g * sig * u * g_w[t * 3 + e];
}

// ---------------- out(b,c,s) += acc(b,s,c) ----------------
__global__ void final_kernel(float* __restrict__ out) {
    long idx = (long)blockIdx.x * blockDim.x + threadIdx.x;
    if (idx >= (long)BATCH * C * S) return;
    int b   = (int)(idx / ((long)C * S));
    int rem = (int)(idx % ((long)C * S));
    int c = rem / S, s = rem % S;
    out[idx] += g_acc[((long)b * S + s) * C + c];
}

// ---------------- launcher ----------------
extern "C" void kernel_launch(void* const* d_in, const int* in_sizes, int n_in,
                              void* d_out, int out_size) {
    const float* x        = (const float*)d_in[0];
    const float* ln_w     = (const float*)d_in[1];
    const float* ln_b     = (const float*)d_in[2];
    const float* qkv_w    = (const float*)d_in[3];
    const float* proj_w   = (const float*)d_in[4];
    const float* router_w = (const float*)d_in[5];
    const float* gate_w   = (const float*)d_in[6];
    const float* up_w     = (const float*)d_in[7];
    const float* down_w   = (const float*)d_in[8];
    float* out = (float*)d_out;

    float *p_tok1, *p_qkv, *p_attn, *p_o, *p_tok2, *p_gbuf, *p_ubuf, *p_acc;
    cudaGetSymbolAddress((void**)&p_tok1, g_tok1);
    cudaGetSymbolAddress((void**)&p_qkv,  g_qkv);
    cudaGetSymbolAddress((void**)&p_attn, g_attn);
    cudaGetSymbolAddress((void**)&p_o,    g_o);
    cudaGetSymbolAddress((void**)&p_tok2, g_tok2);
    cudaGetSymbolAddress((void**)&p_gbuf, g_gbuf);
    cudaGetSymbolAddress((void**)&p_ubuf, g_ubuf);
    cudaGetSymbolAddress((void**)&p_acc,  g_acc);

    const long n_elem = (long)BATCH * C * S;
    const int MT = (BS + 127) / 128;   // 46 row tiles

    // 1) LayerNorm
    stats_kernel<<<BATCH, 256>>>(x);
    ln_kernel<<<(int)((n_elem + 255) / 256), 256>>>(x, ln_w, ln_b);

    // 2) qkv GEMM: (BS,3C) = tok1 @ qkv_w     [HMMA bf16x3]
    hmma_gemm_kernel<false><<<dim3(3 * C / 128, MT), 256>>>(
        p_tok1, qkv_w, p_qkv, BS, 3 * C, C);

    // 3) attention scores: per (b,h)  S x S = q @ k^T
    {
        dim3 grid((S + 63) / 64, (S + 63) / 64, BATCH * NH);
        sgemm_kernel<64, 64, 16, 4, 4, true, false, 2><<<grid, 256>>>(
            p_qkv, p_qkv + C, p_attn, S, S, DH, 3 * C, 3 * C, S,
            (long)S * 3 * C, DH,
            (long)S * 3 * C, DH,
            (long)NH * S * S, (long)S * S,
            NH);
    }

    // 4) softmax per row
    softmax_kernel<<<BATCH * NH * S, 256>>>(p_attn);

    // 5) PV: per (b,h)  S x DH = attn @ v
    {
        dim3 grid((DH + 63) / 64, (S + 63) / 64, BATCH * NH);
        sgemm_kernel<64, 64, 16, 4, 4, false, false, 0><<<grid, 256>>>(
            p_attn, p_qkv + 2 * C, p_o, S, DH, S, S, 3 * C, C,
            (long)NH * S * S, (long)S * S,
            (long)S * 3 * C, DH,
            (long)S * C, DH,
            NH);
    }

    // 6) proj GEMM: (BS,C) = o @ proj_w       [HMMA bf16x3]
    hmma_gemm_kernel<false><<<dim3(C / 128, MT), 256>>>(
        p_o, proj_w, p_tok2, BS, C, C);

    // 7) residual + tok2
    residual_kernel<<<(int)((n_elem + 255) / 256), 256>>>(x, out);

    // 8) router
    {
        dim3 blk(32, 8);
        router_kernel<<<(BS + 7) / 8, blk>>>(router_w);
    }

    // 9) MoE experts                          [HMMA bf16x3]
    for (int e = 0; e < NEXP; e++) {
        hmma_gemm_kernel<false><<<dim3(HID / 128, MT), 256>>>(
            p_tok2, gate_w + (long)e * C * HID, p_gbuf, BS, HID, C);
        hmma_gemm_kernel<false><<<dim3(HID / 128, MT), 256>>>(
            p_tok2, up_w + (long)e * C * HID, p_ubuf, BS, HID, C);

        long nh_elem = (long)BS * HID;
        swiglu_kernel<<<(int)((nh_elem + 255) / 256), 256>>>(e);

        if (e == 0)
            hmma_gemm_kernel<false><<<dim3(C / 128, MT), 256>>>(
                p_gbuf, down_w + (long)e * HID * C, p_acc, BS, C, HID);
        else
            hmma_gemm_kernel<true><<<dim3(C / 128, MT), 256>>>(
                p_gbuf, down_w + (long)e * HID * C, p_acc, BS, C, HID);
    }

    // 10) final add (transpose)
    final_kernel<<<(int)((n_elem + 255) / 256), 256>>>(out);
}

// round 6
// speedup vs baseline: 1.8156x; 1.2560x over previous
#include <cuda_runtime.h>
#include <cuda_bf16.h>
#include <cstdint>

// ---------------- problem constants ----------------
#define BATCH 8
#define C 768
#define S 729               // 9^3
#define NH 8
#define DH 96               // C / NH
#define HID 2048
#define NEXP 3
#define BS (BATCH * S)      // 5832 tokens
#define EPS 1e-5f

// weight pool offsets (elements) in transposed (N,K) bf16 hi/lo pools
#define OFF_QKV  0L
#define OFF_PROJ 1769472L
#define OFF_GATE 2359296L
#define WSZ_GU   1572864L
#define OFF_UP   7077888L
#define OFF_DOWN 11796480L
#define WPOOL    16515072L

// ---------------- static device scratch (no allocs allowed) ----------------
__device__ __nv_bfloat16 g_tok1h[(long)BS * C], g_tok1l[(long)BS * C];
__device__ float g_qkv [(long)BS * 3 * C];
__device__ float g_attn[(long)BATCH * NH * S * S];
__device__ float g_o   [(long)BS * C];
__device__ __nv_bfloat16 g_oh[(long)BS * C], g_ol[(long)BS * C];
__device__ float g_tok2[(long)BS * C];
__device__ __nv_bfloat16 g_tok2h[(long)BS * C], g_tok2l[(long)BS * C];
__device__ float g_gbuf[(long)BS * HID];
__device__ float g_ubuf[(long)BS * HID];
__device__ __nv_bfloat16 g_hidh[(long)BS * HID], g_hidl[(long)BS * HID];
__device__ float g_acc [(long)BS * C];
__device__ float g_w   [(long)BS * NEXP];
__device__ float g_stats[BATCH * 2];
__device__ __nv_bfloat16 g_wth[WPOOL], g_wtl[WPOOL];

__device__ __forceinline__ void hilo1(float x, __nv_bfloat16& h, __nv_bfloat16& l) {
    h = __float2bfloat16(x);
    l = __float2bfloat16(x - __bfloat162float(h));
}

__device__ __forceinline__ void mma16816(float* c, const uint32_t* a, const uint32_t* b) {
    asm volatile(
        "mma.sync.aligned.m16n8k16.row.col.f32.bf16.bf16.f32 "
        "{%0,%1,%2,%3}, {%4,%5,%6,%7}, {%8,%9}, {%0,%1,%2,%3};"
        : "+f"(c[0]), "+f"(c[1]), "+f"(c[2]), "+f"(c[3])
        : "r"(a[0]), "r"(a[1]), "r"(a[2]), "r"(a[3]), "r"(b[0]), "r"(b[1]));
}

// ================== weight transpose+split: W(K,N) fp32 -> Wt(N,K) bf16 hi/lo ==================
__global__ void wconv_kernel(const float* __restrict__ W,
                             __nv_bfloat16* __restrict__ th,
                             __nv_bfloat16* __restrict__ tl,
                             int K, int N) {
    __shared__ float t[32][33];
    int nt = blockIdx.x * 32, kt = blockIdx.y * 32;
    int tx = threadIdx.x & 31, ty = threadIdx.x >> 5;   // 256 thr: ty 0..7
    for (int r = ty; r < 32; r += 8)
        t[r][tx] = W[(long)(kt + r) * N + nt + tx];
    __syncthreads();
    for (int r = ty; r < 32; r += 8) {
        float v = t[tx][r];
        __nv_bfloat16 h, l;
        hilo1(v, h, l);
        long o = (long)(nt + r) * K + kt + tx;
        th[o] = h;
        tl[o] = l;
    }
}

// ================== elementwise fp32 -> bf16 hi/lo ==================
__global__ void aconv_kernel(const float* __restrict__ src,
                             __nv_bfloat16* __restrict__ h,
                             __nv_bfloat16* __restrict__ l, long n) {
    long i = (long)blockIdx.x * blockDim.x + threadIdx.x;
    if (i >= n) return;
    hilo1(src[i], h[i], l[i]);
}

// ================== pipelined HMMA bf16x3 GEMM (pre-split operands) ==================
// C(M,N) = A(M,K) @ B^T  with A,B pre-split bf16 hi/lo; A row-major (M,K),
// B stored transposed (N,K).  K%32==0, N%128==0, M edge guarded.
#define LDT 20
#define TSZ (128 * LDT)

__device__ __forceinline__ void load_chunks(
    uint32_t sb32, int stage, int k0, int tid, int m0, int n0, int M, int K,
    const __nv_bfloat16* __restrict__ Ah, const __nv_bfloat16* __restrict__ Al,
    const __nv_bfloat16* __restrict__ Bh, const __nv_bfloat16* __restrict__ Bl)
{
#pragma unroll
    for (int j = 0; j < 8; j++) {
        int c = tid + j * 256;
        int mat = c >> 9;          // 0:Ah 1:Al 2:Bh 3:Bl
        int idx = c & 511;
        int row = idx >> 2;        // 0..127
        int seg = idx & 3;         // 16B segment within 64B row chunk
        const __nv_bfloat16* g;
        int vb = 16;
        if (mat < 2) {
            int r = m0 + row;
            if (r >= M) { r = M - 1; vb = 0; }
            g = ((mat == 0) ? Ah : Al) + (long)r * K;
        } else {
            g = ((mat == 2) ? Bh : Bl) + (long)(n0 + row) * K;
        }
        g += k0 + seg * 8;
        uint32_t dst = sb32 + (uint32_t)((stage * 4 * TSZ + mat * TSZ + row * LDT + seg * 4) * 4);
        asm volatile("cp.async.ca.shared.global [%0], [%1], 16, %2;"
                     :: "r"(dst), "l"(g), "r"(vb) : "memory");
    }
}

template<bool ACC>
__global__ void __launch_bounds__(256)
hmma2_gemm_kernel(const __nv_bfloat16* __restrict__ Ah, const __nv_bfloat16* __restrict__ Al,
                  const __nv_bfloat16* __restrict__ Bh, const __nv_bfloat16* __restrict__ Bl,
                  float* __restrict__ Cm, int M, int N, int K)
{
    extern __shared__ uint32_t smp[];
    const int tid = threadIdx.x;
    const int lane = tid & 31;
    const int w = tid >> 5;
    const int wm = w & 3;
    const int wn = w >> 2;
    const int gid = lane >> 2;
    const int tig = lane & 3;
    const int m0 = blockIdx.y * 128;
    const int n0 = blockIdx.x * 128;
    uint32_t sb32 = (uint32_t)__cvta_generic_to_shared(smp);

    float acc[2][8][4];
#pragma unroll
    for (int i = 0; i < 2; i++)
#pragma unroll
        for (int j = 0; j < 8; j++)
#pragma unroll
            for (int q = 0; q < 4; q++) acc[i][j][q] = 0.f;

    const int NKB = K >> 5;
    load_chunks(sb32, 0, 0, tid, m0, n0, M, K, Ah, Al, Bh, Bl);
    asm volatile("cp.async.commit_group;" ::: "memory");

    for (int kb = 0; kb < NKB; kb++) {
        if (kb + 1 < NKB) {
            load_chunks(sb32, (kb + 1) & 1, (kb + 1) << 5, tid, m0, n0, M, K, Ah, Al, Bh, Bl);
            asm volatile("cp.async.commit_group;" ::: "memory");
            asm volatile("cp.async.wait_group 1;" ::: "memory");
        } else {
            asm volatile("cp.async.wait_group 0;" ::: "memory");
        }
        __syncthreads();

        const uint32_t* sAhi = smp + (kb & 1) * 4 * TSZ;
        const uint32_t* sAlo = sAhi + TSZ;
        const uint32_t* sBhi = sAhi + 2 * TSZ;
        const uint32_t* sBlo = sAhi + 3 * TSZ;

#pragma unroll
        for (int k16 = 0; k16 < 2; k16++) {
            const int kb8 = k16 * 8;
            uint32_t ahi[2][4], alo[2][4];
#pragma unroll
            for (int mt = 0; mt < 2; mt++) {
                int r0 = (wm * 32 + mt * 16 + gid) * LDT;
                int r8 = r0 + 8 * LDT;
                ahi[mt][0] = sAhi[r0 + kb8 + tig];
                ahi[mt][1] = sAhi[r8 + kb8 + tig];
                ahi[mt][2] = sAhi[r0 + kb8 + 4 + tig];
                ahi[mt][3] = sAhi[r8 + kb8 + 4 + tig];
                alo[mt][0] = sAlo[r0 + kb8 + tig];
                alo[mt][1] = sAlo[r8 + kb8 + tig];
                alo[mt][2] = sAlo[r0 + kb8 + 4 + tig];
                alo[mt][3] = sAlo[r8 + kb8 + 4 + tig];
            }
#pragma unroll
            for (int nt = 0; nt < 8; nt++) {
                int nr = (wn * 64 + nt * 8 + gid) * LDT;
                uint32_t bhi[2], blo[2];
                bhi[0] = sBhi[nr + kb8 + tig];
                bhi[1] = sBhi[nr + kb8 + 4 + tig];
                blo[0] = sBlo[nr + kb8 + tig];
                blo[1] = sBlo[nr + kb8 + 4 + tig];
#pragma unroll
                for (int mt = 0; mt < 2; mt++) {
                    mma16816(acc[mt][nt], ahi[mt], bhi);
                    mma16816(acc[mt][nt], ahi[mt], blo);
                    mma16816(acc[mt][nt], alo[mt], bhi);
                }
            }
        }
        __syncthreads();
    }

    // ---- epilogue ----
#pragma unroll
    for (int mt = 0; mt < 2; mt++) {
        int row = m0 + wm * 32 + mt * 16 + gid;
#pragma unroll
        for (int nt = 0; nt < 8; nt++) {
            int col = n0 + wn * 64 + nt * 8 + tig * 2;
            if (row < M) {
                float2* p = reinterpret_cast<float2*>(Cm + (long)row * N + col);
                if (ACC) { float2 o = *p; o.x += acc[mt][nt][0]; o.y += acc[mt][nt][1]; *p = o; }
                else     { *p = make_float2(acc[mt][nt][0], acc[mt][nt][1]); }
            }
            if (row + 8 < M) {
                float2* p = reinterpret_cast<float2*>(Cm + (long)(row + 8) * N + col);
                if (ACC) { float2 o = *p; o.x += acc[mt][nt][2]; o.y += acc[mt][nt][3]; *p = o; }
                else     { *p = make_float2(acc[mt][nt][2], acc[mt][nt][3]); }
            }
        }
    }
}

// ---------------- LayerNorm statistics ----------------
__global__ void stats_kernel(const float* __restrict__ x) {
    int b = blockIdx.x;
    const float* xb = x + (long)b * C * S;
    const int N = C * S;
    float s = 0.f, s2 = 0.f;
    for (int i = threadIdx.x; i < N; i += blockDim.x) {
        float v = xb[i];
        s += v; s2 += v * v;
    }
    __shared__ float sh[256], sh2[256];
    int tid = threadIdx.x;
    sh[tid] = s; sh2[tid] = s2;
    __syncthreads();
    for (int st = 128; st > 0; st >>= 1) {
        if (tid < st) { sh[tid] += sh[tid + st]; sh2[tid] += sh2[tid + st]; }
        __syncthreads();
    }
    if (tid == 0) {
        float m = sh[0] / (float)N;
        g_stats[b * 2 + 0] = m;
        g_stats[b * 2 + 1] = sh2[0] / (float)N - m * m;
    }
}

// ---------------- LN apply + transpose + bf16 split ----------------
__global__ void ln_kernel(const float* __restrict__ x,
                          const float* __restrict__ w,
                          const float* __restrict__ bia) {
    long idx = (long)blockIdx.x * blockDim.x + threadIdx.x;
    if (idx >= (long)BATCH * C * S) return;
    int b   = (int)(idx / ((long)C * S));
    int rem = (int)(idx % ((long)C * S));
    int c = rem / S, s = rem % S;
    float m   = g_stats[b * 2 + 0];
    float var = g_stats[b * 2 + 1];
    float y = (x[idx] - m) * rsqrtf(var + EPS) * w[rem] + bia[rem];
    long t = ((long)b * S + s) * C + c;
    __nv_bfloat16 h, l;
    hilo1(y, h, l);
    g_tok1h[t] = h;
    g_tok1l[t] = l;
}

// ---------------- generic register-blocked SGEMM (attention only) ----------------
template<int BM, int BN, int BK, int TM, int TN, bool TB, bool ACC, int VMODE>
__global__ void __launch_bounds__((BM / TM) * (BN / TN))
sgemm_kernel(const float* __restrict__ A, const float* __restrict__ B,
             float* __restrict__ Cm,
             int M, int N, int K, int lda, int ldb, int ldc,
             long sA, long sA2, long sB, long sB2, long sC, long sC2, int div) {
    const int RT = BM / TM;
    const int CT = BN / TN;
    const int THREADS = RT * CT;

    int z  = blockIdx.z;
    int z1 = z / div, z2 = z % div;
    A  += z1 * sA + z2 * sA2;
    B  += z1 * sB + z2 * sB2;
    Cm += z1 * sC + z2 * sC2;

    __shared__ float As[BK][BM];
    __shared__ float Bs[BK][BN];

    int tid = threadIdx.x;
    int tx = tid % CT;
    int ty = tid / CT;
    int row0 = blockIdx.y * BM;
    int col0 = blockIdx.x * BN;

    float acc[TM][TN];
#pragma unroll
    for (int i = 0; i < TM; i++)
#pragma unroll
        for (int j = 0; j < TN; j++) acc[i][j] = 0.f;

    for (int k0 = 0; k0 < K; k0 += BK) {
        if (VMODE == 2) {
            {
                int m  = tid / (BK / 4);
                int kv = (tid % (BK / 4)) * 4;
                int gm = row0 + m;
                float4 v = make_float4(0.f, 0.f, 0.f, 0.f);
                if (gm < M)
                    v = *reinterpret_cast<const float4*>(&A[(long)gm * lda + k0 + kv]);
                As[kv + 0][m] = v.x;
                As[kv + 1][m] = v.y;
                As[kv + 2][m] = v.z;
                As[kv + 3][m] = v.w;
            }
            {
                int n  = tid / (BK / 4);
                int kv = (tid % (BK / 4)) * 4;
                int gn = col0 + n;
                float4 v = make_float4(0.f, 0.f, 0.f, 0.f);
                if (gn < N)
                    v = *reinterpret_cast<const float4*>(&B[(long)gn * ldb + k0 + kv]);
                Bs[kv + 0][n] = v.x;
                Bs[kv + 1][n] = v.y;
                Bs[kv + 2][n] = v.z;
                Bs[kv + 3][n] = v.w;
            }
        } else {
            for (int i = tid; i < BM * BK; i += THREADS) {
                int m = i / BK, kk = i % BK;
                int gm = row0 + m, gk = k0 + kk;
                As[kk][m] = (gm < M && gk < K) ? A[(long)gm * lda + gk] : 0.f;
            }
            if (!TB) {
                for (int i = tid; i < BK * BN; i += THREADS) {
                    int kk = i / BN, n = i % BN;
                    int gk = k0 + kk, gn = col0 + n;
                    Bs[kk][n] = (gk < K && gn < N) ? B[(long)gk * ldb + gn] : 0.f;
                }
            } else {
                for (int i = tid; i < BK * BN; i += THREADS) {
                    int n = i / BK, kk = i % BK;
                    int gk = k0 + kk, gn = col0 + n;
                    Bs[kk][n] = (gk < K && gn < N) ? B[(long)gn * ldb + gk] : 0.f;
                }
            }
        }
        __syncthreads();

#pragma unroll
        for (int kk = 0; kk < BK; kk++) {
            float af[TM], bf[TN];
#pragma unroll
            for (int i = 0; i < TM; i++) af[i] = As[kk][ty + i * RT];
#pragma unroll
            for (int j = 0; j < TN; j++) bf[j] = Bs[kk][tx + j * CT];
#pragma unroll
            for (int i = 0; i < TM; i++)
#pragma unroll
                for (int j = 0; j < TN; j++) acc[i][j] += af[i] * bf[j];
        }
        __syncthreads();
    }

#pragma unroll
    for (int i = 0; i < TM; i++) {
        int gm = row0 + ty + i * RT;
        if (gm >= M) continue;
#pragma unroll
        for (int j = 0; j < TN; j++) {
            int gn = col0 + tx + j * CT;
            if (gn < N) {
                long o = (long)gm * ldc + gn;
                if (ACC) Cm[o] += acc[i][j];
                else     Cm[o]  = acc[i][j];
            }
        }
    }
}

// ---------------- row softmax ----------------
__global__ void softmax_kernel(float* __restrict__ attn) {
    long row = blockIdx.x;
    float* p = attn + row * (long)S;
    int tid = threadIdx.x;
    __shared__ float sh[256];

    float mx = -1e30f;
    for (int i = tid; i < S; i += blockDim.x) mx = fmaxf(mx, p[i]);
    sh[tid] = mx; __syncthreads();
    for (int st = 128; st > 0; st >>= 1) {
        if (tid < st) sh[tid] = fmaxf(sh[tid], sh[tid + st]);
        __syncthreads();
    }
    mx = sh[0]; __syncthreads();

    float sum = 0.f;
    for (int i = tid; i < S; i += blockDim.x) {
        float e = __expf(p[i] - mx);
        p[i] = e; sum += e;
    }
    sh[tid] = sum; __syncthreads();
    for (int st = 128; st > 0; st >>= 1) {
        if (tid < st) sh[tid] += sh[tid + st];
        __syncthreads();
    }
    float inv = 1.f / sh[0];
    for (int i = tid; i < S; i += blockDim.x) p[i] *= inv;
}

// ---------------- residual: out = x + proj; tok2 fp32 + hi/lo ----------------
__global__ void residual_kernel(const float* __restrict__ x, float* __restrict__ out) {
    long idx = (long)blockIdx.x * blockDim.x + threadIdx.x;
    if (idx >= (long)BATCH * C * S) return;
    int b   = (int)(idx / ((long)C * S));
    int rem = (int)(idx % ((long)C * S));
    int c = rem / S, s = rem % S;
    long t = ((long)b * S + s) * C + c;
    float v = x[idx] + g_tok2[t];
    out[idx] = v;
    g_tok2[t] = v;
    __nv_bfloat16 h, l;
    hilo1(v, h, l);
    g_tok2h[t] = h;
    g_tok2l[t] = l;
}

// ---------------- router ----------------
__global__ void router_kernel(const float* __restrict__ rw) {
    int t = blockIdx.x * blockDim.y + threadIdx.y;
    if (t >= BS) return;
    const float* tok = g_tok2 + (long)t * C;
    float l0 = 0.f, l1 = 0.f, l2 = 0.f;
    for (int c = threadIdx.x; c < C; c += 32) {
        float v = tok[c];
        l0 += v * rw[c * 3 + 0];
        l1 += v * rw[c * 3 + 1];
        l2 += v * rw[c * 3 + 2];
    }
#pragma unroll
    for (int off = 16; off > 0; off >>= 1) {
        l0 += __shfl_down_sync(0xFFFFFFFFu, l0, off);
        l1 += __shfl_down_sync(0xFFFFFFFFu, l1, off);
        l2 += __shfl_down_sync(0xFFFFFFFFu, l2, off);
    }
    if (threadIdx.x == 0) {
        float mx = fmaxf(l0, fmaxf(l1, l2));
        float e0 = __expf(l0 - mx), e1 = __expf(l1 - mx), e2 = __expf(l2 - mx);
        float tot = e0 + e1 + e2;
        float p[3] = { e0 / tot, e1 / tot, e2 / tot };
        int i1 = 0;
        if (p[1] > p[i1]) i1 = 1;
        if (p[2] > p[i1]) i1 = 2;
        int i2 = -1;
        for (int i = 0; i < 3; i++) {
            if (i == i1) continue;
            if (i2 < 0 || p[i] > p[i2]) i2 = i;
        }
        float den = p[i1] + p[i2];
        float w[3] = { 0.f, 0.f, 0.f };
        w[i1] = p[i1] / den;
        w[i2] = p[i2] / den;
        g_w[t * 3 + 0] = w[0];
        g_w[t * 3 + 1] = w[1];
        g_w[t * 3 + 2] = w[2];
    }
}

// ---------------- hid = silu(g)*u*route_w -> bf16 hi/lo ----------------
__global__ void swiglu_kernel(int e) {
    long idx = (long)blockIdx.x * blockDim.x + threadIdx.x;
    if (idx >= (long)BS * HID) return;
    int t = (int)(idx / HID);
    float g = g_gbuf[idx];
    float u = g_ubuf[idx];
    float sig = 1.f / (1.f + __expf(-g));
    float v = g * sig * u * g_w[t * 3 + e];
    __nv_bfloat16 h, l;
    hilo1(v, h, l);
    g_hidh[idx] = h;
    g_hidl[idx] = l;
}

// ---------------- out(b,c,s) += acc(b,s,c) ----------------
__global__ void final_kernel(float* __restrict__ out) {
    long idx = (long)blockIdx.x * blockDim.x + threadIdx.x;
    if (idx >= (long)BATCH * C * S) return;
    int b   = (int)(idx / ((long)C * S));
    int rem = (int)(idx % ((long)C * S));
    int c = rem / S, s = rem % S;
    out[idx] += g_acc[((long)b * S + s) * C + c];
}

// ---------------- launcher ----------------
extern "C" void kernel_launch(void* const* d_in, const int* in_sizes, int n_in,
                              void* d_out, int out_size) {
    const float* x        = (const float*)d_in[0];
    const float* ln_w     = (const float*)d_in[1];
    const float* ln_b     = (const float*)d_in[2];
    const float* qkv_w    = (const float*)d_in[3];
    const float* proj_w   = (const float*)d_in[4];
    const float* router_w = (const float*)d_in[5];
    const float* gate_w   = (const float*)d_in[6];
    const float* up_w     = (const float*)d_in[7];
    const float* down_w   = (const float*)d_in[8];
    float* out = (float*)d_out;

    float *p_qkv, *p_attn, *p_o, *p_tok2, *p_gbuf, *p_ubuf, *p_acc;
    __nv_bfloat16 *p_t1h, *p_t1l, *p_oh, *p_ol, *p_t2h, *p_t2l, *p_hh, *p_hl, *p_wh, *p_wl;
    cudaGetSymbolAddress((void**)&p_qkv,  g_qkv);
    cudaGetSymbolAddress((void**)&p_attn, g_attn);
    cudaGetSymbolAddress((void**)&p_o,    g_o);
    cudaGetSymbolAddress((void**)&p_tok2, g_tok2);
    cudaGetSymbolAddress((void**)&p_gbuf, g_gbuf);
    cudaGetSymbolAddress((void**)&p_ubuf, g_ubuf);
    cudaGetSymbolAddress((void**)&p_acc,  g_acc);
    cudaGetSymbolAddress((void**)&p_t1h, g_tok1h);
    cudaGetSymbolAddress((void**)&p_t1l, g_tok1l);
    cudaGetSymbolAddress((void**)&p_oh,  g_oh);
    cudaGetSymbolAddress((void**)&p_ol,  g_ol);
    cudaGetSymbolAddress((void**)&p_t2h, g_tok2h);
    cudaGetSymbolAddress((void**)&p_t2l, g_tok2l);
    cudaGetSymbolAddress((void**)&p_hh,  g_hidh);
    cudaGetSymbolAddress((void**)&p_hl,  g_hidl);
    cudaGetSymbolAddress((void**)&p_wh,  g_wth);
    cudaGetSymbolAddress((void**)&p_wl,  g_wtl);

    const int SMEM_GEMM = 2 * 4 * TSZ * 4;   // 81920 B
    cudaFuncSetAttribute(hmma2_gemm_kernel<false>,
                         cudaFuncAttributeMaxDynamicSharedMemorySize, SMEM_GEMM);
    cudaFuncSetAttribute(hmma2_gemm_kernel<true>,
                         cudaFuncAttributeMaxDynamicSharedMemorySize, SMEM_GEMM);

    const long n_elem = (long)BATCH * C * S;
    const int MT = (BS + 127) / 128;   // 46 row tiles

    // 0) weight conversions (transpose + hi/lo split)
    wconv_kernel<<<dim3(3 * C / 32, C / 32), 256>>>(qkv_w,  p_wh + OFF_QKV,  p_wl + OFF_QKV,  C, 3 * C);
    wconv_kernel<<<dim3(C / 32, C / 32),     256>>>(proj_w, p_wh + OFF_PROJ, p_wl + OFF_PROJ, C, C);
    for (int e = 0; e < NEXP; e++) {
        wconv_kernel<<<dim3(HID / 32, C / 32), 256>>>(
            gate_w + (long)e * C * HID, p_wh + OFF_GATE + e * WSZ_GU, p_wl + OFF_GATE + e * WSZ_GU, C, HID);
        wconv_kernel<<<dim3(HID / 32, C / 32), 256>>>(
            up_w + (long)e * C * HID,   p_wh + OFF_UP + e * WSZ_GU,   p_wl + OFF_UP + e * WSZ_GU,   C, HID);
        wconv_kernel<<<dim3(C / 32, HID / 32), 256>>>(
            down_w + (long)e * HID * C, p_wh + OFF_DOWN + e * WSZ_GU, p_wl + OFF_DOWN + e * WSZ_GU, HID, C);
    }

    // 1) LayerNorm -> tok1 hi/lo
    stats_kernel<<<BATCH, 256>>>(x);
    ln_kernel<<<(int)((n_elem + 255) / 256), 256>>>(x, ln_w, ln_b);

    // 2) qkv GEMM
    hmma2_gemm_kernel<false><<<dim3(3 * C / 128, MT), 256, SMEM_GEMM>>>(
        p_t1h, p_t1l, p_wh + OFF_QKV, p_wl + OFF_QKV, p_qkv, BS, 3 * C, C);

    // 3) attention scores: per (b,h)  S x S = q @ k^T
    {
        dim3 grid((S + 63) / 64, (S + 63) / 64, BATCH * NH);
        sgemm_kernel<64, 64, 16, 4, 4, true, false, 2><<<grid, 256>>>(
            p_qkv, p_qkv + C, p_attn, S, S, DH, 3 * C, 3 * C, S,
            (long)S * 3 * C, DH,
            (long)S * 3 * C, DH,
            (long)NH * S * S, (long)S * S,
            NH);
    }

    // 4) softmax
    softmax_kernel<<<BATCH * NH * S, 256>>>(p_attn);

    // 5) PV
    {
        dim3 grid((DH + 63) / 64, (S + 63) / 64, BATCH * NH);
        sgemm_kernel<64, 64, 16, 4, 4, false, false, 0><<<grid, 256>>>(
            p_attn, p_qkv + 2 * C, p_o, S, DH, S, S, 3 * C, C,
            (long)NH * S * S, (long)S * S,
            (long)S * 3 * C, DH,
            (long)S * C, DH,
            NH);
    }

    // 5b) o -> hi/lo
    aconv_kernel<<<(int)((n_elem + 255) / 256), 256>>>(p_o, p_oh, p_ol, n_elem);

    // 6) proj GEMM
    hmma2_gemm_kernel<false><<<dim3(C / 128, MT), 256, SMEM_GEMM>>>(
        p_oh, p_ol, p_wh + OFF_PROJ, p_wl + OFF_PROJ, p_tok2, BS, C, C);

    // 7) residual + tok2 (fp32 + hi/lo)
    residual_kernel<<<(int)((n_elem + 255) / 256), 256>>>(x, out);

    // 8) router
    {
        dim3 blk(32, 8);
        router_kernel<<<(BS + 7) / 8, blk>>>(router_w);
    }

    // 9) MoE experts
    for (int e = 0; e < NEXP; e++) {
        hmma2_gemm_kernel<false><<<dim3(HID / 128, MT), 256, SMEM_GEMM>>>(
            p_t2h, p_t2l, p_wh + OFF_GATE + e * WSZ_GU, p_wl + OFF_GATE + e * WSZ_GU,
            p_gbuf, BS, HID, C);
        hmma2_gemm_kernel<false><<<dim3(HID / 128, MT), 256, SMEM_GEMM>>>(
            p_t2h, p_t2l, p_wh + OFF_UP + e * WSZ_GU, p_wl + OFF_UP + e * WSZ_GU,
            p_ubuf, BS, HID, C);

        long nh_elem = (long)BS * HID;
        swiglu_kernel<<<(int)((nh_elem + 255) / 256), 256>>>(e);

        if (e == 0)
            hmma2_gemm_kernel<false><<<dim3(C / 128, MT), 256, SMEM_GEMM>>>(
                p_hh, p_hl, p_wh + OFF_DOWN + e * WSZ_GU, p_wl + OFF_DOWN + e * WSZ_GU,
                p_acc, BS, C, HID);
        else
            hmma2_gemm_kernel<true><<<dim3(C / 128, MT), 256, SMEM_GEMM>>>(
                p_hh, p_hl, p_wh + OFF_DOWN + e * WSZ_GU, p_wl + OFF_DOWN + e * WSZ_GU,
                p_acc, BS, C, HID);
    }

    // 10) final add
    final_kernel<<<(int)((n_elem + 255) / 256), 256>>>(out);
}

// round 7
// speedup vs baseline: 2.2028x; 1.2133x over previous
#include <cuda_runtime.h>
#include <cuda_bf16.h>
#include <cstdint>

// ---------------- problem constants ----------------
#define BATCH 8
#define C 768
#define S 729               // 9^3
#define SP 736              // S padded to multiple of 32
#define NH 8
#define DH 96               // C / NH
#define HID 2048
#define NEXP 3
#define BS (BATCH * S)      // 5832 tokens
#define BH (BATCH * NH)     // 64
#define EPS 1e-5f

// weight pool offsets (elements) in transposed (N,K) bf16 hi/lo pools
#define OFF_QKV  0L
#define OFF_PROJ 1769472L
#define OFF_GATE 2359296L
#define WSZ_GU   1572864L
#define OFF_UP   7077888L
#define OFF_DOWN 11796480L
#define WPOOL    16515072L

// ---------------- static device scratch (no allocs allowed) ----------------
__device__ __nv_bfloat16 g_tok1h[(long)BS * C], g_tok1l[(long)BS * C];
__device__ float g_qkv [(long)BS * 3 * C];
__device__ float g_attn[(long)BH * S * SP];               // scores, padded cols
__device__ __nv_bfloat16 g_ph[(long)BH * S * SP], g_pl[(long)BH * S * SP];
__device__ __nv_bfloat16 g_qh[(long)BH * S * DH], g_ql[(long)BH * S * DH];
__device__ __nv_bfloat16 g_kh[(long)BH * S * DH], g_kl[(long)BH * S * DH];
__device__ __nv_bfloat16 g_vth[(long)BH * DH * SP], g_vtl[(long)BH * DH * SP];
__device__ float g_o   [(long)BS * C];
__device__ __nv_bfloat16 g_oh[(long)BS * C], g_ol[(long)BS * C];
__device__ float g_tok2[(long)BS * C];
__device__ __nv_bfloat16 g_tok2h[(long)BS * C], g_tok2l[(long)BS * C];
__device__ float g_gbuf[(long)BS * HID];
__device__ float g_ubuf[(long)BS * HID];
__device__ __nv_bfloat16 g_hidh[(long)BS * HID], g_hidl[(long)BS * HID];
__device__ float g_acc [(long)BS * C];
__device__ float g_w   [(long)BS * NEXP];
__device__ float g_stats[BATCH * 2];
__device__ __nv_bfloat16 g_wth[WPOOL], g_wtl[WPOOL];

__device__ __forceinline__ void hilo1(float x, __nv_bfloat16& h, __nv_bfloat16& l) {
    h = __float2bfloat16(x);
    l = __float2bfloat16(x - __bfloat162float(h));
}

__device__ __forceinline__ void mma16816(float* c, const uint32_t* a, const uint32_t* b) {
    asm volatile(
        "mma.sync.aligned.m16n8k16.row.col.f32.bf16.bf16.f32 "
        "{%0,%1,%2,%3}, {%4,%5,%6,%7}, {%8,%9}, {%0,%1,%2,%3};"
        : "+f"(c[0]), "+f"(c[1]), "+f"(c[2]), "+f"(c[3])
        : "r"(a[0]), "r"(a[1]), "r"(a[2]), "r"(a[3]), "r"(b[0]), "r"(b[1]));
}

// ================== weight transpose+split ==================
__global__ void wconv_kernel(const float* __restrict__ W,
                             __nv_bfloat16* __restrict__ th,
                             __nv_bfloat16* __restrict__ tl,
                             int K, int N) {
    __shared__ float t[32][33];
    int nt = blockIdx.x * 32, kt = blockIdx.y * 32;
    int tx = threadIdx.x & 31, ty = threadIdx.x >> 5;
    for (int r = ty; r < 32; r += 8)
        t[r][tx] = W[(long)(kt + r) * N + nt + tx];
    __syncthreads();
    for (int r = ty; r < 32; r += 8) {
        float v = t[tx][r];
        __nv_bfloat16 h, l;
        hilo1(v, h, l);
        long o = (long)(nt + r) * K + kt + tx;
        th[o] = h;
        tl[o] = l;
    }
}

// ================== elementwise fp32 -> bf16 hi/lo ==================
__global__ void aconv_kernel(const float* __restrict__ src,
                             __nv_bfloat16* __restrict__ h,
                             __nv_bfloat16* __restrict__ l, long n) {
    long i = (long)blockIdx.x * blockDim.x + threadIdx.x;
    if (i >= n) return;
    hilo1(src[i], h[i], l[i]);
}

// ================== q,k split: g_qkv -> (b,h,s,d) hi/lo ==================
__global__ void qkconv_kernel() {
    long i = (long)blockIdx.x * blockDim.x + threadIdx.x;
    if (i >= (long)BS * 2 * C) return;
    int t = (int)(i / (2 * C));
    int j = (int)(i % (2 * C));
    int which = j / C;          // 0=q, 1=k
    int hd = j % C;
    int h = hd / DH, d = hd % DH;
    float v = g_qkv[(long)t * 3 * C + which * C + hd];
    int b = t / S, s = t % S;
    long o = ((long)(b * NH + h) * S + s) * DH + d;
    __nv_bfloat16 bh_, bl_;
    hilo1(v, bh_, bl_);
    if (which == 0) { g_qh[o] = bh_; g_ql[o] = bl_; }
    else            { g_kh[o] = bh_; g_kl[o] = bl_; }
}

// ================== v transpose+split: (b,h,s,d) -> (b,h,d,s_pad) hi/lo ==================
__global__ void vconv_kernel() {
    __shared__ float t[32][33];
    int s0 = blockIdx.x * 32, d0 = blockIdx.y * 32, z = blockIdx.z;
    int b = z / NH, h = z % NH;
    int tx = threadIdx.x & 31, ty = threadIdx.x >> 5;
    for (int r = ty; r < 32; r += 8) {
        int s = s0 + r;
        t[r][tx] = (s < S) ? g_qkv[(long)(b * S + s) * 3 * C + 2 * C + h * DH + d0 + tx] : 0.f;
    }
    __syncthreads();
    for (int r = ty; r < 32; r += 8) {
        int d = d0 + r, s = s0 + tx;
        __nv_bfloat16 bh_, bl_;
        hilo1(t[tx][r], bh_, bl_);
        long o = ((long)z * DH + d) * SP + s;
        g_vth[o] = bh_;
        g_vtl[o] = bl_;
    }
}

// ================== generalized pipelined HMMA bf16x3 GEMM ==================
// C(M,N) = A(M,K) @ B^T, A (M x K) lda, B transposed (N x K) ldb, C ldc.
// Two-level batch: z1=z/div, z2=z%div.  K%32==0; M,N edge guarded.
#define LDT 20
#define TSZ (128 * LDT)

__device__ __forceinline__ void load_chunks(
    uint32_t sb32, int stage, int k0, int tid, int m0, int n0, int M, int N,
    int lda, int ldb,
    const __nv_bfloat16* __restrict__ Ah, const __nv_bfloat16* __restrict__ Al,
    const __nv_bfloat16* __restrict__ Bh, const __nv_bfloat16* __restrict__ Bl)
{
#pragma unroll
    for (int j = 0; j < 8; j++) {
        int c = tid + j * 256;
        int mat = c >> 9;          // 0:Ah 1:Al 2:Bh 3:Bl
        int idx = c & 511;
        int row = idx >> 2;
        int seg = idx & 3;
        const __nv_bfloat16* g;
        int vb = 16;
        if (mat < 2) {
            int r = m0 + row;
            if (r >= M) { r = M - 1; vb = 0; }
            g = ((mat == 0) ? Ah : Al) + (long)r * lda;
        } else {
            int r = n0 + row;
            if (r >= N) { r = N - 1; vb = 0; }
            g = ((mat == 2) ? Bh : Bl) + (long)r * ldb;
        }
        g += k0 + seg * 8;
        uint32_t dst = sb32 + (uint32_t)((stage * 4 * TSZ + mat * TSZ + row * LDT + seg * 4) * 4);
        asm volatile("cp.async.ca.shared.global [%0], [%1], 16, %2;"
                     :: "r"(dst), "l"(g), "r"(vb) : "memory");
    }
}

template<bool ACC>
__global__ void __launch_bounds__(256)
hmma3_gemm_kernel(const __nv_bfloat16* __restrict__ Ah, const __nv_bfloat16* __restrict__ Al,
                  const __nv_bfloat16* __restrict__ Bh, const __nv_bfloat16* __restrict__ Bl,
                  float* __restrict__ Cm, int M, int N, int K,
                  int lda, int ldb, int ldc,
                  long sA1, long sA2, long sB1, long sB2, long sC1, long sC2, int div)
{
    extern __shared__ uint32_t smp[];
    const int tid = threadIdx.x;
    const int lane = tid & 31;
    const int w = tid >> 5;
    const int wm = w & 3;
    const int wn = w >> 2;
    const int gid = lane >> 2;
    const int tig = lane & 3;
    const int m0 = blockIdx.y * 128;
    const int n0 = blockIdx.x * 128;
    uint32_t sb32 = (uint32_t)__cvta_generic_to_shared(smp);

    int z = blockIdx.z;
    int z1 = z / div, z2 = z % div;
    Ah += z1 * sA1 + z2 * sA2;  Al += z1 * sA1 + z2 * sA2;
    Bh += z1 * sB1 + z2 * sB2;  Bl += z1 * sB1 + z2 * sB2;
    Cm += z1 * sC1 + z2 * sC2;

    float acc[2][8][4];
#pragma unroll
    for (int i = 0; i < 2; i++)
#pragma unroll
        for (int j = 0; j < 8; j++)
#pragma unroll
            for (int q = 0; q < 4; q++) acc[i][j][q] = 0.f;

    const int NKB = K >> 5;
    load_chunks(sb32, 0, 0, tid, m0, n0, M, N, lda, ldb, Ah, Al, Bh, Bl);
    asm volatile("cp.async.commit_group;" ::: "memory");

    for (int kb = 0; kb < NKB; kb++) {
        if (kb + 1 < NKB) {
            load_chunks(sb32, (kb + 1) & 1, (kb + 1) << 5, tid, m0, n0, M, N, lda, ldb, Ah, Al, Bh, Bl);
            asm volatile("cp.async.commit_group;" ::: "memory");
            asm volatile("cp.async.wait_group 1;" ::: "memory");
        } else {
            asm volatile("cp.async.wait_group 0;" ::: "memory");
        }
        __syncthreads();

        const uint32_t* sAhi = smp + (kb & 1) * 4 * TSZ;
        const uint32_t* sAlo = sAhi + TSZ;
        const uint32_t* sBhi = sAhi + 2 * TSZ;
        const uint32_t* sBlo = sAhi + 3 * TSZ;

#pragma unroll
        for (int k16 = 0; k16 < 2; k16++) {
            const int kb8 = k16 * 8;
            uint32_t ahi[2][4], alo[2][4];
#pragma unroll
            for (int mt = 0; mt < 2; mt++) {
                int r0 = (wm * 32 + mt * 16 + gid) * LDT;
                int r8 = r0 + 8 * LDT;
                ahi[mt][0] = sAhi[r0 + kb8 + tig];
                ahi[mt][1] = sAhi[r8 + kb8 + tig];
                ahi[mt][2] = sAhi[r0 + kb8 + 4 + tig];
                ahi[mt][3] = sAhi[r8 + kb8 + 4 + tig];
                alo[mt][0] = sAlo[r0 + kb8 + tig];
                alo[mt][1] = sAlo[r8 + kb8 + tig];
                alo[mt][2] = sAlo[r0 + kb8 + 4 + tig];
                alo[mt][3] = sAlo[r8 + kb8 + 4 + tig];
            }
#pragma unroll
            for (int nt = 0; nt < 8; nt++) {
                int nr = (wn * 64 + nt * 8 + gid) * LDT;
                uint32_t bhi[2], blo[2];
                bhi[0] = sBhi[nr + kb8 + tig];
                bhi[1] = sBhi[nr + kb8 + 4 + tig];
                blo[0] = sBlo[nr + kb8 + tig];
                blo[1] = sBlo[nr + kb8 + 4 + tig];
#pragma unroll
                for (int mt = 0; mt < 2; mt++) {
                    mma16816(acc[mt][nt], ahi[mt], bhi);
                    mma16816(acc[mt][nt], ahi[mt], blo);
                    mma16816(acc[mt][nt], alo[mt], bhi);
                }
            }
        }
        __syncthreads();
    }

    // ---- epilogue ----
#pragma unroll
    for (int mt = 0; mt < 2; mt++) {
        int row = m0 + wm * 32 + mt * 16 + gid;
#pragma unroll
        for (int nt = 0; nt < 8; nt++) {
            int col = n0 + wn * 64 + nt * 8 + tig * 2;
            if (col >= N) continue;
            if (row < M) {
                float2* p = reinterpret_cast<float2*>(Cm + (long)row * ldc + col);
                if (ACC) { float2 o = *p; o.x += acc[mt][nt][0]; o.y += acc[mt][nt][1]; *p = o; }
                else     { *p = make_float2(acc[mt][nt][0], acc[mt][nt][1]); }
            }
            if (row + 8 < M) {
                float2* p = reinterpret_cast<float2*>(Cm + (long)(row + 8) * ldc + col);
                if (ACC) { float2 o = *p; o.x += acc[mt][nt][2]; o.y += acc[mt][nt][3]; *p = o; }
                else     { *p = make_float2(acc[mt][nt][2], acc[mt][nt][3]); }
            }
        }
    }
}

// ---------------- LayerNorm statistics ----------------
__global__ void stats_kernel(const float* __restrict__ x) {
    int b = blockIdx.x;
    const float* xb = x + (long)b * C * S;
    const int N = C * S;
    float s = 0.f, s2 = 0.f;
    for (int i = threadIdx.x; i < N; i += blockDim.x) {
        float v = xb[i];
        s += v; s2 += v * v;
    }
    __shared__ float sh[256], sh2[256];
    int tid = threadIdx.x;
    sh[tid] = s; sh2[tid] = s2;
    __syncthreads();
    for (int st = 128; st > 0; st >>= 1) {
        if (tid < st) { sh[tid] += sh[tid + st]; sh2[tid] += sh2[tid + st]; }
        __syncthreads();
    }
    if (tid == 0) {
        float m = sh[0] / (float)N;
        g_stats[b * 2 + 0] = m;
        g_stats[b * 2 + 1] = sh2[0] / (float)N - m * m;
    }
}

// ---------------- LN apply + transpose + bf16 split ----------------
__global__ void ln_kernel(const float* __restrict__ x,
                          const float* __restrict__ w,
                          const float* __restrict__ bia) {
    long idx = (long)blockIdx.x * blockDim.x + threadIdx.x;
    if (idx >= (long)BATCH * C * S) return;
    int b   = (int)(idx / ((long)C * S));
    int rem = (int)(idx % ((long)C * S));
    int c = rem / S, s = rem % S;
    float m   = g_stats[b * 2 + 0];
    float var = g_stats[b * 2 + 1];
    float y = (x[idx] - m) * rsqrtf(var + EPS) * w[rem] + bia[rem];
    long t = ((long)b * S + s) * C + c;
    __nv_bfloat16 h, l;
    hilo1(y, h, l);
    g_tok1h[t] = h;
    g_tok1l[t] = l;
}

// ---------------- fused one-pass softmax -> bf16 hi/lo P (padded) ----------------
__global__ void softmax_bf_kernel() {
    long row = blockIdx.x;                    // BH * S rows
    const float* p = g_attn + row * SP;
    __nv_bfloat16* ph = g_ph + row * SP;
    __nv_bfloat16* pl = g_pl + row * SP;
    int tid = threadIdx.x;
    __shared__ float sw[8];

    int i2 = tid + 512;
    float v0 = p[tid];
    float v1 = p[tid + 256];
    float v2 = (i2 < S) ? p[i2] : -1e30f;

    float mx = fmaxf(v0, fmaxf(v1, v2));
#pragma unroll
    for (int o = 16; o > 0; o >>= 1) mx = fmaxf(mx, __shfl_xor_sync(~0u, mx, o));
    if ((tid & 31) == 0) sw[tid >> 5] = mx;
    __syncthreads();
    if (tid < 32) {
        float m = (tid < 8) ? sw[tid] : -1e30f;
#pragma unroll
        for (int o = 4; o > 0; o >>= 1) m = fmaxf(m, __shfl_xor_sync(~0u, m, o));
        if (tid == 0) sw[0] = m;
    }
    __syncthreads();
    mx = sw[0];
    __syncthreads();

    float e0 = __expf(v0 - mx);
    float e1 = __expf(v1 - mx);
    float e2 = (i2 < S) ? __expf(v2 - mx) : 0.f;
    float sum = e0 + e1 + e2;
#pragma unroll
    for (int o = 16; o > 0; o >>= 1) sum += __shfl_xor_sync(~0u, sum, o);
    if ((tid & 31) == 0) sw[tid >> 5] = sum;
    __syncthreads();
    if (tid < 32) {
        float s = (tid < 8) ? sw[tid] : 0.f;
#pragma unroll
        for (int o = 4; o > 0; o >>= 1) s += __shfl_xor_sync(~0u, s, o);
        if (tid == 0) sw[0] = s;
    }
    __syncthreads();
    float inv = 1.f / sw[0];

    __nv_bfloat16 h, l;
    hilo1(e0 * inv, h, l); ph[tid] = h;       pl[tid] = l;
    hilo1(e1 * inv, h, l); ph[tid + 256] = h; pl[tid + 256] = l;
    if (i2 < SP) {
        float v = (i2 < S) ? e2 * inv : 0.f;
        hilo1(v, h, l); ph[i2] = h; pl[i2] = l;
    }
}

// ---------------- residual: out = x + proj; tok2 fp32 + hi/lo ----------------
__global__ void residual_kernel(const float* __restrict__ x, float* __restrict__ out) {
    long idx = (long)blockIdx.x * blockDim.x + threadIdx.x;
    if (idx >= (long)BATCH * C * S) return;
    int b   = (int)(idx / ((long)C * S));
    int rem = (int)(idx % ((long)C * S));
    int c = rem / S, s = rem % S;
    long t = ((long)b * S + s) * C + c;
    float v = x[idx] + g_tok2[t];
    out[idx] = v;
    g_tok2[t] = v;
    __nv_bfloat16 h, l;
    hilo1(v, h, l);
    g_tok2h[t] = h;
    g_tok2l[t] = l;
}

// ---------------- router ----------------
__global__ void router_kernel(const float* __restrict__ rw) {
    int t = blockIdx.x * blockDim.y + threadIdx.y;
    if (t >= BS) return;
    const float* tok = g_tok2 + (long)t * C;
    float l0 = 0.f, l1 = 0.f, l2 = 0.f;
    for (int c = threadIdx.x; c < C; c += 32) {
        float v = tok[c];
        l0 += v * rw[c * 3 + 0];
        l1 += v * rw[c * 3 + 1];
        l2 += v * rw[c * 3 + 2];
    }
#pragma unroll
    for (int off = 16; off > 0; off >>= 1) {
        l0 += __shfl_down_sync(0xFFFFFFFFu, l0, off);
        l1 += __shfl_down_sync(0xFFFFFFFFu, l1, off);
        l2 += __shfl_down_sync(0xFFFFFFFFu, l2, off);
    }
    if (threadIdx.x == 0) {
        float mx = fmaxf(l0, fmaxf(l1, l2));
        float e0 = __expf(l0 - mx), e1 = __expf(l1 - mx), e2 = __expf(l2 - mx);
        float tot = e0 + e1 + e2;
        float p[3] = { e0 / tot, e1 / tot, e2 / tot };
        int i1 = 0;
        if (p[1] > p[i1]) i1 = 1;
        if (p[2] > p[i1]) i1 = 2;
        int i2 = -1;
        for (int i = 0; i < 3; i++) {
            if (i == i1) continue;
            if (i2 < 0 || p[i] > p[i2]) i2 = i;
        }
        float den = p[i1] + p[i2];
        float w[3] = { 0.f, 0.f, 0.f };
        w[i1] = p[i1] / den;
        w[i2] = p[i2] / den;
        g_w[t * 3 + 0] = w[0];
        g_w[t * 3 + 1] = w[1];
        g_w[t * 3 + 2] = w[2];
    }
}

// ---------------- hid = silu(g)*u*route_w -> bf16 hi/lo ----------------
__global__ void swiglu_kernel(int e) {
    long idx = (long)blockIdx.x * blockDim.x + threadIdx.x;
    if (idx >= (long)BS * HID) return;
    int t = (int)(idx / HID);
    float g = g_gbuf[idx];
    float u = g_ubuf[idx];
    float sig = 1.f / (1.f + __expf(-g));
    float v = g * sig * u * g_w[t * 3 + e];
    __nv_bfloat16 h, l;
    hilo1(v, h, l);
    g_hidh[idx] = h;
    g_hidl[idx] = l;
}

// ---------------- out(b,c,s) += acc(b,s,c) ----------------
__global__ void final_kernel(float* __restrict__ out) {
    long idx = (long)blockIdx.x * blockDim.x + threadIdx.x;
    if (idx >= (long)BATCH * C * S) return;
    int b   = (int)(idx / ((long)C * S));
    int rem = (int)(idx % ((long)C * S));
    int c = rem / S, s = rem % S;
    out[idx] += g_acc[((long)b * S + s) * C + c];
}

// ---------------- launcher ----------------
extern "C" void kernel_launch(void* const* d_in, const int* in_sizes, int n_in,
                              void* d_out, int out_size) {
    const float* x        = (const float*)d_in[0];
    const float* ln_w     = (const float*)d_in[1];
    const float* ln_b     = (const float*)d_in[2];
    const float* qkv_w    = (const float*)d_in[3];
    const float* proj_w   = (const float*)d_in[4];
    const float* router_w = (const float*)d_in[5];
    const float* gate_w   = (const float*)d_in[6];
    const float* up_w     = (const float*)d_in[7];
    const float* down_w   = (const float*)d_in[8];
    float* out = (float*)d_out;

    float *p_qkv, *p_attn, *p_o, *p_tok2, *p_gbuf, *p_ubuf, *p_acc;
    __nv_bfloat16 *p_t1h, *p_t1l, *p_oh, *p_ol, *p_t2h, *p_t2l, *p_hh, *p_hl, *p_wh, *p_wl;
    __nv_bfloat16 *p_ph, *p_pl, *p_qh, *p_ql, *p_kh, *p_kl, *p_vth, *p_vtl;
    cudaGetSymbolAddress((void**)&p_qkv,  g_qkv);
    cudaGetSymbolAddress((void**)&p_attn, g_attn);
    cudaGetSymbolAddress((void**)&p_o,    g_o);
    cudaGetSymbolAddress((void**)&p_tok2, g_tok2);
    cudaGetSymbolAddress((void**)&p_gbuf, g_gbuf);
    cudaGetSymbolAddress((void**)&p_ubuf, g_ubuf);
    cudaGetSymbolAddress((void**)&p_acc,  g_acc);
    cudaGetSymbolAddress((void**)&p_t1h, g_tok1h);
    cudaGetSymbolAddress((void**)&p_t1l, g_tok1l);
    cudaGetSymbolAddress((void**)&p_oh,  g_oh);
    cudaGetSymbolAddress((void**)&p_ol,  g_ol);
    cudaGetSymbolAddress((void**)&p_t2h, g_tok2h);
    cudaGetSymbolAddress((void**)&p_t2l, g_tok2l);
    cudaGetSymbolAddress((void**)&p_hh,  g_hidh);
    cudaGetSymbolAddress((void**)&p_hl,  g_hidl);
    cudaGetSymbolAddress((void**)&p_wh,  g_wth);
    cudaGetSymbolAddress((void**)&p_wl,  g_wtl);
    cudaGetSymbolAddress((void**)&p_ph,  g_ph);
    cudaGetSymbolAddress((void**)&p_pl,  g_pl);
    cudaGetSymbolAddress((void**)&p_qh,  g_qh);
    cudaGetSymbolAddress((void**)&p_ql,  g_ql);
    cudaGetSymbolAddress((void**)&p_kh,  g_kh);
    cudaGetSymbolAddress((void**)&p_kl,  g_kl);
    cudaGetSymbolAddress((void**)&p_vth, g_vth);
    cudaGetSymbolAddress((void**)&p_vtl, g_vtl);

    const int SMEM_GEMM = 2 * 4 * TSZ * 4;   // 81920 B
    cudaFuncSetAttribute(hmma3_gemm_kernel<false>,
                         cudaFuncAttributeMaxDynamicSharedMemorySize, SMEM_GEMM);
    cudaFuncSetAttribute(hmma3_gemm_kernel<true>,
                         cudaFuncAttributeMaxDynamicSharedMemorySize, SMEM_GEMM);

    const long n_elem = (long)BATCH * C * S;
    const int MT = (BS + 127) / 128;   // 46 row tiles

    // 0) weight conversions
    wconv_kernel<<<dim3(3 * C / 32, C / 32), 256>>>(qkv_w,  p_wh + OFF_QKV,  p_wl + OFF_QKV,  C, 3 * C);
    wconv_kernel<<<dim3(C / 32, C / 32),     256>>>(proj_w, p_wh + OFF_PROJ, p_wl + OFF_PROJ, C, C);
    for (int e = 0; e < NEXP; e++) {
        wconv_kernel<<<dim3(HID / 32, C / 32), 256>>>(
            gate_w + (long)e * C * HID, p_wh + OFF_GATE + e * WSZ_GU, p_wl + OFF_GATE + e * WSZ_GU, C, HID);
        wconv_kernel<<<dim3(HID / 32, C / 32), 256>>>(
            up_w + (long)e * C * HID,   p_wh + OFF_UP + e * WSZ_GU,   p_wl + OFF_UP + e * WSZ_GU,   C, HID);
        wconv_kernel<<<dim3(C / 32, HID / 32), 256>>>(
            down_w + (long)e * HID * C, p_wh + OFF_DOWN + e * WSZ_GU, p_wl + OFF_DOWN + e * WSZ_GU, HID, C);
    }

    // 1) LayerNorm -> tok1 hi/lo
    stats_kernel<<<BATCH, 256>>>(x);
    ln_kernel<<<(int)((n_elem + 255) / 256), 256>>>(x, ln_w, ln_b);

    // 2) qkv GEMM
    hmma3_gemm_kernel<false><<<dim3(3 * C / 128, MT, 1), 256, SMEM_GEMM>>>(
        p_t1h, p_t1l, p_wh + OFF_QKV, p_wl + OFF_QKV, p_qkv, BS, 3 * C, C,
        C, C, 3 * C, 0, 0, 0, 0, 0, 0, 1);

    // 2b) split q,k -> (b,h,s,d); v -> (b,h,d,s_pad)
    qkconv_kernel<<<(int)(((long)BS * 2 * C + 255) / 256), 256>>>();
    vconv_kernel<<<dim3((S + 31) / 32, DH / 32, BH), 256>>>();

    // 3) scores: per (b,h) 729x729 = q @ k^T     [HMMA bf16x3]
    hmma3_gemm_kernel<false><<<dim3(6, 6, BH), 256, SMEM_GEMM>>>(
        p_qh, p_ql, p_kh, p_kl, p_attn, S, S, DH,
        DH, DH, SP,
        (long)NH * S * DH, (long)S * DH,
        (long)NH * S * DH, (long)S * DH,
        (long)NH * S * SP, (long)S * SP, NH);

    // 4) fused softmax -> bf16 hi/lo P
    softmax_bf_kernel<<<BH * S, 256>>>();

    // 5) PV: per (b,h) 729x96 = P @ V            [HMMA bf16x3]
    hmma3_gemm_kernel<false><<<dim3(1, 6, BH), 256, SMEM_GEMM>>>(
        p_ph, p_pl, p_vth, p_vtl, p_o, S, DH, SP,
        SP, SP, C,
        (long)NH * S * SP, (long)S * SP,
        (long)NH * DH * SP, (long)DH * SP,
        (long)S * C, DH, NH);

    // 5b) o -> hi/lo
    aconv_kernel<<<(int)((n_elem + 255) / 256), 256>>>(p_o, p_oh, p_ol, n_elem);

    // 6) proj GEMM
    hmma3_gemm_kernel<false><<<dim3(C / 128, MT, 1), 256, SMEM_GEMM>>>(
        p_oh, p_ol, p_wh + OFF_PROJ, p_wl + OFF_PROJ, p_tok2, BS, C, C,
        C, C, C, 0, 0, 0, 0, 0, 0, 1);

    // 7) residual + tok2
    residual_kernel<<<(int)((n_elem + 255) / 256), 256>>>(x, out);

    // 8) router
    {
        dim3 blk(32, 8);
        router_kernel<<<(BS + 7) / 8, blk>>>(router_w);
    }

    // 9) MoE experts
    for (int e = 0; e < NEXP; e++) {
        hmma3_gemm_kernel<false><<<dim3(HID / 128, MT, 1), 256, SMEM_GEMM>>>(
            p_t2h, p_t2l, p_wh + OFF_GATE + e * WSZ_GU, p_wl + OFF_GATE + e * WSZ_GU,
            p_gbuf, BS, HID, C, C, C, HID, 0, 0, 0, 0, 0, 0, 1);
        hmma3_gemm_kernel<false><<<dim3(HID / 128, MT, 1), 256, SMEM_GEMM>>>(
            p_t2h, p_t2l, p_wh + OFF_UP + e * WSZ_GU, p_wl + OFF_UP + e * WSZ_GU,
            p_ubuf, BS, HID, C, C, C, HID, 0, 0, 0, 0, 0, 0, 1);

        long nh_elem = (long)BS * HID;
        swiglu_kernel<<<(int)((nh_elem + 255) / 256), 256>>>(e);

        if (e == 0)
            hmma3_gemm_kernel<false><<<dim3(C / 128, MT, 1), 256, SMEM_GEMM>>>(
                p_hh, p_hl, p_wh + OFF_DOWN + e * WSZ_GU, p_wl + OFF_DOWN + e * WSZ_GU,
                p_acc, BS, C, HID, HID, HID, C, 0, 0, 0, 0, 0, 0, 1);
        else
            hmma3_gemm_kernel<true><<<dim3(C / 128, MT, 1), 256, SMEM_GEMM>>>(
                p_hh, p_hl, p_wh + OFF_DOWN + e * WSZ_GU, p_wl + OFF_DOWN + e * WSZ_GU,
                p_acc, BS, C, HID, HID, HID, C, 0, 0, 0, 0, 0, 0, 1);
    }

    // 10) final add
    final_kernel<<<(int)((n_elem + 255) / 256), 256>>>(out);
}

// round 8
// speedup vs baseline: 2.2964x; 1.0425x over previous
#include <cuda_runtime.h>
#include <cuda_bf16.h>
#include <cstdint>

// ---------------- problem constants ----------------
#define BATCH 8
#define C 768
#define S 729               // 9^3
#define SP 736              // S padded to multiple of 32
#define NH 8
#define DH 96               // C / NH
#define HID 2048
#define NEXP 3
#define BS (BATCH * S)      // 5832 tokens
#define BH (BATCH * NH)     // 64
#define EPS 1e-5f

// weight pool offsets (elements) in transposed (N,K) bf16 hi/lo pools
#define OFF_QKV  0L
#define OFF_PROJ 1769472L
#define OFF_GU   2359296L          // interleaved gate/up, stride 2*C*HID per expert
#define WSZ_GU2  3145728L
#define OFF_DOWN 11796480L
#define WSZ_DN   1572864L
#define WPOOL    16515072L

// ---------------- static device scratch (no allocs allowed) ----------------
__device__ __nv_bfloat16 g_tok1h[(long)BS * C], g_tok1l[(long)BS * C];
__device__ float g_attn[(long)BH * S * SP];               // scores, padded cols
__device__ __nv_bfloat16 g_ph[(long)BH * S * SP], g_pl[(long)BH * S * SP];
__device__ __nv_bfloat16 g_qh[(long)BH * S * DH], g_ql[(long)BH * S * DH];
__device__ __nv_bfloat16 g_kh[(long)BH * S * DH], g_kl[(long)BH * S * DH];
__device__ __nv_bfloat16 g_vth[(long)BH * DH * SP], g_vtl[(long)BH * DH * SP];
__device__ __nv_bfloat16 g_oh[(long)BS * C], g_ol[(long)BS * C];
__device__ float g_tok2[(long)BS * C];
__device__ __nv_bfloat16 g_tok2h[(long)BS * C], g_tok2l[(long)BS * C];
__device__ __nv_bfloat16 g_hidh[(long)BS * HID], g_hidl[(long)BS * HID];
__device__ float g_acc [(long)BS * C];
__device__ float g_w   [(long)BS * NEXP];
__device__ float g_stats[BATCH * 2];
__device__ __nv_bfloat16 g_wth[WPOOL], g_wtl[WPOOL];

__device__ __forceinline__ void hilo1(float x, __nv_bfloat16& h, __nv_bfloat16& l) {
    h = __float2bfloat16(x);
    l = __float2bfloat16(x - __bfloat162float(h));
}

__device__ __forceinline__ void mma16816(float* c, const uint32_t* a, const uint32_t* b) {
    asm volatile(
        "mma.sync.aligned.m16n8k16.row.col.f32.bf16.bf16.f32 "
        "{%0,%1,%2,%3}, {%4,%5,%6,%7}, {%8,%9}, {%0,%1,%2,%3};"
        : "+f"(c[0]), "+f"(c[1]), "+f"(c[2]), "+f"(c[3])
        : "r"(a[0]), "r"(a[1]), "r"(a[2]), "r"(a[3]), "r"(b[0]), "r"(b[1]));
}

// ================== weight transpose+split (row = n*mul + add) ==================
__global__ void wconv_kernel(const float* __restrict__ W,
                             __nv_bfloat16* __restrict__ th,
                             __nv_bfloat16* __restrict__ tl,
                             int K, int N, int mul, int add) {
    __shared__ float t[32][33];
    int nt = blockIdx.x * 32, kt = blockIdx.y * 32;
    int tx = threadIdx.x & 31, ty = threadIdx.x >> 5;
    for (int r = ty; r < 32; r += 8)
        t[r][tx] = W[(long)(kt + r) * N + nt + tx];
    __syncthreads();
    for (int r = ty; r < 32; r += 8) {
        float v = t[tx][r];
        __nv_bfloat16 h, l;
        hilo1(v, h, l);
        long o = ((long)(nt + r) * mul + add) * K + kt + tx;
        th[o] = h;
        tl[o] = l;
    }
}

// ================== epilogue dispatch ==================
// EPI: 0=store, 1=accumulate, 2=qkv split, 3=swiglu, 4=proj+residual, 5=bf16 out
template<int EPI>
__device__ __forceinline__ void epi_store(
    int row, int col, float x, float y, int ldc,
    float* Cm, __nv_bfloat16* Eh, __nv_bfloat16* El,
    const float* Xaux, float* Faux, const float* Wrow, int eidx)
{
    if (EPI == 0) {
        *reinterpret_cast<float2*>(Cm + (long)row * ldc + col) = make_float2(x, y);
    } else if (EPI == 1) {
        float2* p = reinterpret_cast<float2*>(Cm + (long)row * ldc + col);
        float2 o = *p; o.x += x; o.y += y; *p = o;
    } else if (EPI == 2) {
        int b = row / S, s = row - b * S;
        int which = col / C;
        int hd = col - which * C;
        int h = hd / DH, d = hd - h * DH;
        __nv_bfloat16 xh, xl, yh, yl;
        hilo1(x, xh, xl); hilo1(y, yh, yl);
        if (which == 2) {
            long o = ((long)(b * NH + h) * DH + d) * SP + s;
            g_vth[o] = xh; g_vtl[o] = xl;
            g_vth[o + SP] = yh; g_vtl[o + SP] = yl;
        } else {
            long o = ((long)(b * NH + h) * S + s) * DH + d;
            __nv_bfloat16* H = which ? g_kh : g_qh;
            __nv_bfloat16* L = which ? g_kl : g_ql;
            H[o] = xh; H[o + 1] = yh;
            L[o] = xl; L[o + 1] = yl;
        }
    } else if (EPI == 3) {
        float w = Wrow[row * 3 + eidx];
        float sig = 1.f / (1.f + __expf(-x));
        float v = x * sig * y * w;
        __nv_bfloat16 h, l; hilo1(v, h, l);
        long o = (long)row * HID + (col >> 1);
        Eh[o] = h; El[o] = l;
    } else if (EPI == 4) {
        int b = row / S, s = row - b * S;
        long xo = ((long)b * C + col) * S + s;
        float v0 = x + Xaux[xo];
        float v1 = y + Xaux[xo + S];
        Faux[xo] = v0; Faux[xo + S] = v1;
        *reinterpret_cast<float2*>(Cm + (long)row * ldc + col) = make_float2(v0, v1);
        __nv_bfloat16 h, l;
        hilo1(v0, h, l); Eh[(long)row * ldc + col] = h;     El[(long)row * ldc + col] = l;
        hilo1(v1, h, l); Eh[(long)row * ldc + col + 1] = h; El[(long)row * ldc + col + 1] = l;
    } else {  // 5
        __nv_bfloat16 h, l;
        hilo1(x, h, l); Eh[(long)row * ldc + col] = h;     El[(long)row * ldc + col] = l;
        hilo1(y, h, l); Eh[(long)row * ldc + col + 1] = h; El[(long)row * ldc + col + 1] = l;
    }
}

// ================== generalized pipelined HMMA bf16x3 GEMM + fused epilogue ==================
#define LDT 20
#define TSZ (128 * LDT)

__device__ __forceinline__ void load_chunks(
    uint32_t sb32, int stage, int k0, int tid, int m0, int n0, int M, int N,
    int lda, int ldb,
    const __nv_bfloat16* __restrict__ Ah, const __nv_bfloat16* __restrict__ Al,
    const __nv_bfloat16* __restrict__ Bh, const __nv_bfloat16* __restrict__ Bl)
{
#pragma unroll
    for (int j = 0; j < 8; j++) {
        int c = tid + j * 256;
        int mat = c >> 9;          // 0:Ah 1:Al 2:Bh 3:Bl
        int idx = c & 511;
        int row = idx >> 2;
        int seg = idx & 3;
        const __nv_bfloat16* g;
        int vb = 16;
        if (mat < 2) {
            int r = m0 + row;
            if (r >= M) { r = M - 1; vb = 0; }
            g = ((mat == 0) ? Ah : Al) + (long)r * lda;
        } else {
            int r = n0 + row;
            if (r >= N) { r = N - 1; vb = 0; }
            g = ((mat == 2) ? Bh : Bl) + (long)r * ldb;
        }
        g += k0 + seg * 8;
        uint32_t dst = sb32 + (uint32_t)((stage * 4 * TSZ + mat * TSZ + row * LDT + seg * 4) * 4);
        asm volatile("cp.async.ca.shared.global [%0], [%1], 16, %2;"
                     :: "r"(dst), "l"(g), "r"(vb) : "memory");
    }
}

template<int EPI>
__global__ void __launch_bounds__(256)
hmma4_gemm_kernel(const __nv_bfloat16* __restrict__ Ah, const __nv_bfloat16* __restrict__ Al,
                  const __nv_bfloat16* __restrict__ Bh, const __nv_bfloat16* __restrict__ Bl,
                  float* __restrict__ Cm, __nv_bfloat16* __restrict__ Eh, __nv_bfloat16* __restrict__ El,
                  const float* __restrict__ Xaux, float* __restrict__ Faux,
                  const float* __restrict__ Wrow, int eidx,
                  int M, int N, int K, int lda, int ldb, int ldc,
                  long sA1, long sA2, long sB1, long sB2, long sC1, long sC2, int div)
{
    extern __shared__ uint32_t smp[];
    const int tid = threadIdx.x;
    const int lane = tid & 31;
    const int w = tid >> 5;
    const int wm = w & 3;
    const int wn = w >> 2;
    const int gid = lane >> 2;
    const int tig = lane & 3;
    const int m0 = blockIdx.y * 128;
    const int n0 = blockIdx.x * 128;
    uint32_t sb32 = (uint32_t)__cvta_generic_to_shared(smp);

    int z = blockIdx.z;
    int z1 = z / div, z2 = z % div;
    Ah += z1 * sA1 + z2 * sA2;  Al += z1 * sA1 + z2 * sA2;
    Bh += z1 * sB1 + z2 * sB2;  Bl += z1 * sB1 + z2 * sB2;
    Cm += z1 * sC1 + z2 * sC2;
    if (EPI == 5) { Eh += z1 * sC1 + z2 * sC2; El += z1 * sC1 + z2 * sC2; }

    float acc[2][8][4];
#pragma unroll
    for (int i = 0; i < 2; i++)
#pragma unroll
        for (int j = 0; j < 8; j++)
#pragma unroll
            for (int q = 0; q < 4; q++) acc[i][j][q] = 0.f;

    const int NKB = K >> 5;
    load_chunks(sb32, 0, 0, tid, m0, n0, M, N, lda, ldb, Ah, Al, Bh, Bl);
    asm volatile("cp.async.commit_group;" ::: "memory");

    for (int kb = 0; kb < NKB; kb++) {
        if (kb + 1 < NKB) {
            load_chunks(sb32, (kb + 1) & 1, (kb + 1) << 5, tid, m0, n0, M, N, lda, ldb, Ah, Al, Bh, Bl);
            asm volatile("cp.async.commit_group;" ::: "memory");
            asm volatile("cp.async.wait_group 1;" ::: "memory");
        } else {
            asm volatile("cp.async.wait_group 0;" ::: "memory");
        }
        __syncthreads();

        const uint32_t* sAhi = smp + (kb & 1) * 4 * TSZ;
        const uint32_t* sAlo = sAhi + TSZ;
        const uint32_t* sBhi = sAhi + 2 * TSZ;
        const uint32_t* sBlo = sAhi + 3 * TSZ;

#pragma unroll
        for (int k16 = 0; k16 < 2; k16++) {
            const int kb8 = k16 * 8;
            uint32_t ahi[2][4], alo[2][4];
#pragma unroll
            for (int mt = 0; mt < 2; mt++) {
                int r0 = (wm * 32 + mt * 16 + gid) * LDT;
                int r8 = r0 + 8 * LDT;
                ahi[mt][0] = sAhi[r0 + kb8 + tig];
                ahi[mt][1] = sAhi[r8 + kb8 + tig];
                ahi[mt][2] = sAhi[r0 + kb8 + 4 + tig];
                ahi[mt][3] = sAhi[r8 + kb8 + 4 + tig];
                alo[mt][0] = sAlo[r0 + kb8 + tig];
                alo[mt][1] = sAlo[r8 + kb8 + tig];
                alo[mt][2] = sAlo[r0 + kb8 + 4 + tig];
                alo[mt][3] = sAlo[r8 + kb8 + 4 + tig];
            }
#pragma unroll
            for (int nt = 0; nt < 8; nt++) {
                int nr = (wn * 64 + nt * 8 + gid) * LDT;
                uint32_t bhi[2], blo[2];
                bhi[0] = sBhi[nr + kb8 + tig];
                bhi[1] = sBhi[nr + kb8 + 4 + tig];
                blo[0] = sBlo[nr + kb8 + tig];
                blo[1] = sBlo[nr + kb8 + 4 + tig];
#pragma unroll
                for (int mt = 0; mt < 2; mt++) {
                    mma16816(acc[mt][nt], ahi[mt], bhi);
                    mma16816(acc[mt][nt], ahi[mt], blo);
                    mma16816(acc[mt][nt], alo[mt], bhi);
                }
            }
        }
        __syncthreads();
    }

    // ---- fused epilogue ----
#pragma unroll
    for (int mt = 0; mt < 2; mt++) {
        int row = m0 + wm * 32 + mt * 16 + gid;
#pragma unroll
        for (int nt = 0; nt < 8; nt++) {
            int col = n0 + wn * 64 + nt * 8 + tig * 2;
            if (col >= N) continue;
            if (row < M)
                epi_store<EPI>(row, col, acc[mt][nt][0], acc[mt][nt][1], ldc,
                               Cm, Eh, El, Xaux, Faux, Wrow, eidx);
            if (row + 8 < M)
                epi_store<EPI>(row + 8, col, acc[mt][nt][2], acc[mt][nt][3], ldc,
                               Cm, Eh, El, Xaux, Faux, Wrow, eidx);
        }
    }
}

// ---------------- LayerNorm statistics ----------------
__global__ void stats_kernel(const float* __restrict__ x) {
    int b = blockIdx.x;
    const float* xb = x + (long)b * C * S;
    const int N = C * S;
    float s = 0.f, s2 = 0.f;
    for (int i = threadIdx.x; i < N; i += blockDim.x) {
        float v = xb[i];
        s += v; s2 += v * v;
    }
    __shared__ float sh[256], sh2[256];
    int tid = threadIdx.x;
    sh[tid] = s; sh2[tid] = s2;
    __syncthreads();
    for (int st = 128; st > 0; st >>= 1) {
        if (tid < st) { sh[tid] += sh[tid + st]; sh2[tid] += sh2[tid + st]; }
        __syncthreads();
    }
    if (tid == 0) {
        float m = sh[0] / (float)N;
        g_stats[b * 2 + 0] = m;
        g_stats[b * 2 + 1] = sh2[0] / (float)N - m * m;
    }
}

// ---------------- LN apply + transpose + bf16 split ----------------
__global__ void ln_kernel(const float* __restrict__ x,
                          const float* __restrict__ w,
                          const float* __restrict__ bia) {
    long idx = (long)blockIdx.x * blockDim.x + threadIdx.x;
    if (idx >= (long)BATCH * C * S) return;
    int b   = (int)(idx / ((long)C * S));
    int rem = (int)(idx % ((long)C * S));
    int c = rem / S, s = rem % S;
    float m   = g_stats[b * 2 + 0];
    float var = g_stats[b * 2 + 1];
    float y = (x[idx] - m) * rsqrtf(var + EPS) * w[rem] + bia[rem];
    long t = ((long)b * S + s) * C + c;
    __nv_bfloat16 h, l;
    hilo1(y, h, l);
    g_tok1h[t] = h;
    g_tok1l[t] = l;
}

// ---------------- fused one-pass softmax -> bf16 hi/lo P (padded) ----------------
__global__ void softmax_bf_kernel() {
    long row = blockIdx.x;                    // BH * S rows
    const float* p = g_attn + row * SP;
    __nv_bfloat16* ph = g_ph + row * SP;
    __nv_bfloat16* pl = g_pl + row * SP;
    int tid = threadIdx.x;
    __shared__ float sw[8];

    int i2 = tid + 512;
    float v0 = p[tid];
    float v1 = p[tid + 256];
    float v2 = (i2 < S) ? p[i2] : -1e30f;

    float mx = fmaxf(v0, fmaxf(v1, v2));
#pragma unroll
    for (int o = 16; o > 0; o >>= 1) mx = fmaxf(mx, __shfl_xor_sync(~0u, mx, o));
    if ((tid & 31) == 0) sw[tid >> 5] = mx;
    __syncthreads();
    if (tid < 32) {
        float m = (tid < 8) ? sw[tid] : -1e30f;
#pragma unroll
        for (int o = 4; o > 0; o >>= 1) m = fmaxf(m, __shfl_xor_sync(~0u, m, o));
        if (tid == 0) sw[0] = m;
    }
    __syncthreads();
    mx = sw[0];
    __syncthreads();

    float e0 = __expf(v0 - mx);
    float e1 = __expf(v1 - mx);
    float e2 = (i2 < S) ? __expf(v2 - mx) : 0.f;
    float sum = e0 + e1 + e2;
#pragma unroll
    for (int o = 16; o > 0; o >>= 1) sum += __shfl_xor_sync(~0u, sum, o);
    if ((tid & 31) == 0) sw[tid >> 5] = sum;
    __syncthreads();
    if (tid < 32) {
        float s = (tid < 8) ? sw[tid] : 0.f;
#pragma unroll
        for (int o = 4; o > 0; o >>= 1) s += __shfl_xor_sync(~0u, s, o);
        if (tid == 0) sw[0] = s;
    }
    __syncthreads();
    float inv = 1.f / sw[0];

    __nv_bfloat16 h, l;
    hilo1(e0 * inv, h, l); ph[tid] = h;       pl[tid] = l;
    hilo1(e1 * inv, h, l); ph[tid + 256] = h; pl[tid + 256] = l;
    if (i2 < SP) {
        float v = (i2 < S) ? e2 * inv : 0.f;
        hilo1(v, h, l); ph[i2] = h; pl[i2] = l;
    }
}

// ---------------- router ----------------
__global__ void router_kernel(const float* __restrict__ rw) {
    int t = blockIdx.x * blockDim.y + threadIdx.y;
    if (t >= BS) return;
    const float* tok = g_tok2 + (long)t * C;
    float l0 = 0.f, l1 = 0.f, l2 = 0.f;
    for (int c = threadIdx.x; c < C; c += 32) {
        float v = tok[c];
        l0 += v * rw[c * 3 + 0];
        l1 += v * rw[c * 3 + 1];
        l2 += v * rw[c * 3 + 2];
    }
#pragma unroll
    for (int off = 16; off > 0; off >>= 1) {
        l0 += __shfl_down_sync(0xFFFFFFFFu, l0, off);
        l1 += __shfl_down_sync(0xFFFFFFFFu, l1, off);
        l2 += __shfl_down_sync(0xFFFFFFFFu, l2, off);
    }
    if (threadIdx.x == 0) {
        float mx = fmaxf(l0, fmaxf(l1, l2));
        float e0 = __expf(l0 - mx), e1 = __expf(l1 - mx), e2 = __expf(l2 - mx);
        float tot = e0 + e1 + e2;
        float p[3] = { e0 / tot, e1 / tot, e2 / tot };
        int i1 = 0;
        if (p[1] > p[i1]) i1 = 1;
        if (p[2] > p[i1]) i1 = 2;
        int i2 = -1;
        for (int i = 0; i < 3; i++) {
            if (i == i1) continue;
            if (i2 < 0 || p[i] > p[i2]) i2 = i;
        }
        float den = p[i1] + p[i2];
        float w[3] = { 0.f, 0.f, 0.f };
        w[i1] = p[i1] / den;
        w[i2] = p[i2] / den;
        g_w[t * 3 + 0] = w[0];
        g_w[t * 3 + 1] = w[1];
        g_w[t * 3 + 2] = w[2];
    }
}

// ---------------- out(b,c,s) += acc(b,s,c) ----------------
__global__ void final_kernel(float* __restrict__ out) {
    long idx = (long)blockIdx.x * blockDim.x + threadIdx.x;
    if (idx >= (long)BATCH * C * S) return;
    int b   = (int)(idx / ((long)C * S));
    int rem = (int)(idx % ((long)C * S));
    int c = rem / S, s = rem % S;
    out[idx] += g_acc[((long)b * S + s) * C + c];
}

// ---------------- launcher ----------------
extern "C" void kernel_launch(void* const* d_in, const int* in_sizes, int n_in,
                              void* d_out, int out_size) {
    const float* x        = (const float*)d_in[0];
    const float* ln_w     = (const float*)d_in[1];
    const float* ln_b     = (const float*)d_in[2];
    const float* qkv_w    = (const float*)d_in[3];
    const float* proj_w   = (const float*)d_in[4];
    const float* router_w = (const float*)d_in[5];
    const float* gate_w   = (const float*)d_in[6];
    const float* up_w     = (const float*)d_in[7];
    const float* down_w   = (const float*)d_in[8];
    float* out = (float*)d_out;

    float *p_attn, *p_tok2, *p_acc, *p_gw;
    __nv_bfloat16 *p_t1h, *p_t1l, *p_oh, *p_ol, *p_t2h, *p_t2l, *p_hh, *p_hl, *p_wh, *p_wl;
    __nv_bfloat16 *p_ph, *p_pl, *p_qh, *p_ql, *p_kh, *p_kl, *p_vth, *p_vtl;
    cudaGetSymbolAddress((void**)&p_attn, g_attn);
    cudaGetSymbolAddress((void**)&p_tok2, g_tok2);
    cudaGetSymbolAddress((void**)&p_acc,  g_acc);
    cudaGetSymbolAddress((void**)&p_gw,   g_w);
    cudaGetSymbolAddress((void**)&p_t1h, g_tok1h);
    cudaGetSymbolAddress((void**)&p_t1l, g_tok1l);
    cudaGetSymbolAddress((void**)&p_oh,  g_oh);
    cudaGetSymbolAddress((void**)&p_ol,  g_ol);
    cudaGetSymbolAddress((void**)&p_t2h, g_tok2h);
    cudaGetSymbolAddress((void**)&p_t2l, g_tok2l);
    cudaGetSymbolAddress((void**)&p_hh,  g_hidh);
    cudaGetSymbolAddress((void**)&p_hl,  g_hidl);
    cudaGetSymbolAddress((void**)&p_wh,  g_wth);
    cudaGetSymbolAddress((void**)&p_wl,  g_wtl);
    cudaGetSymbolAddress((void**)&p_ph,  g_ph);
    cudaGetSymbolAddress((void**)&p_pl,  g_pl);
    cudaGetSymbolAddress((void**)&p_qh,  g_qh);
    cudaGetSymbolAddress((void**)&p_ql,  g_ql);
    cudaGetSymbolAddress((void**)&p_kh,  g_kh);
    cudaGetSymbolAddress((void**)&p_kl,  g_kl);
    cudaGetSymbolAddress((void**)&p_vth, g_vth);
    cudaGetSymbolAddress((void**)&p_vtl, g_vtl);

    const int SMEM_GEMM = 2 * 4 * TSZ * 4;   // 81920 B
    cudaFuncSetAttribute(hmma4_gemm_kernel<0>, cudaFuncAttributeMaxDynamicSharedMemorySize, SMEM_GEMM);
    cudaFuncSetAttribute(hmma4_gemm_kernel<1>, cudaFuncAttributeMaxDynamicSharedMemorySize, SMEM_GEMM);
    cudaFuncSetAttribute(hmma4_gemm_kernel<2>, cudaFuncAttributeMaxDynamicSharedMemorySize, SMEM_GEMM);
    cudaFuncSetAttribute(hmma4_gemm_kernel<3>, cudaFuncAttributeMaxDynamicSharedMemorySize, SMEM_GEMM);
    cudaFuncSetAttribute(hmma4_gemm_kernel<4>, cudaFuncAttributeMaxDynamicSharedMemorySize, SMEM_GEMM);
    cudaFuncSetAttribute(hmma4_gemm_kernel<5>, cudaFuncAttributeMaxDynamicSharedMemorySize, SMEM_GEMM);

    const long n_elem = (long)BATCH * C * S;
    const int MT = (BS + 127) / 128;   // 46 row tiles

    // 1-2) LayerNorm
    stats_kernel<<<BATCH, 256>>>(x);
    ln_kernel<<<(int)((n_elem + 255) / 256), 256>>>(x, ln_w, ln_b);

    // 3-5) first weight conversions
    wconv_kernel<<<dim3(3 * C / 32, C / 32), 256>>>(qkv_w,  p_wh + OFF_QKV,  p_wl + OFF_QKV,  C, 3 * C, 1, 0);
    wconv_kernel<<<dim3(C / 32, C / 32),     256>>>(proj_w, p_wh + OFF_PROJ, p_wl + OFF_PROJ, C, C, 1, 0);
    wconv_kernel<<<dim3(HID / 32, C / 32),   256>>>(gate_w, p_wh + OFF_GU,   p_wl + OFF_GU,   C, HID, 2, 0);

    // 6) qkv GEMM with fused q/k/v split epilogue  [profiled launch]
    hmma4_gemm_kernel<2><<<dim3(3 * C / 128, MT, 1), 256, SMEM_GEMM>>>(
        p_t1h, p_t1l, p_wh + OFF_QKV, p_wl + OFF_QKV,
        nullptr, nullptr, nullptr, nullptr, nullptr, nullptr, 0,
        BS, 3 * C, C, C, C, 0, 0, 0, 0, 0, 0, 0, 1);

    // 7-14) remaining weight conversions (interleaved gate/up + down)
    wconv_kernel<<<dim3(HID / 32, C / 32), 256>>>(up_w, p_wh + OFF_GU, p_wl + OFF_GU, C, HID, 2, 1);
    for (int e = 1; e < NEXP; e++) {
        wconv_kernel<<<dim3(HID / 32, C / 32), 256>>>(
            gate_w + (long)e * C * HID, p_wh + OFF_GU + e * WSZ_GU2, p_wl + OFF_GU + e * WSZ_GU2, C, HID, 2, 0);
        wconv_kernel<<<dim3(HID / 32, C / 32), 256>>>(
            up_w + (long)e * C * HID,   p_wh + OFF_GU + e * WSZ_GU2, p_wl + OFF_GU + e * WSZ_GU2, C, HID, 2, 1);
    }
    for (int e = 0; e < NEXP; e++)
        wconv_kernel<<<dim3(C / 32, HID / 32), 256>>>(
            down_w + (long)e * HID * C, p_wh + OFF_DOWN + e * WSZ_DN, p_wl + OFF_DOWN + e * WSZ_DN, HID, C, 1, 0);

    // scores: per (b,h) 729x729 = q @ k^T
    hmma4_gemm_kernel<0><<<dim3(6, 6, BH), 256, SMEM_GEMM>>>(
        p_qh, p_ql, p_kh, p_kl,
        p_attn, nullptr, nullptr, nullptr, nullptr, nullptr, 0,
        S, S, DH, DH, DH, SP,
        (long)NH * S * DH, (long)S * DH,
        (long)NH * S * DH, (long)S * DH,
        (long)NH * S * SP, (long)S * SP, NH);

    // softmax -> bf16 hi/lo P
    softmax_bf_kernel<<<BH * S, 256>>>();

    // PV: per (b,h) 729x96 = P @ V, bf16 hi/lo out
    hmma4_gemm_kernel<5><<<dim3(1, 6, BH), 256, SMEM_GEMM>>>(
        p_ph, p_pl, p_vth, p_vtl,
        nullptr, p_oh, p_ol, nullptr, nullptr, nullptr, 0,
        S, DH, SP, SP, SP, C,
        (long)NH * S * SP, (long)S * SP,
        (long)NH * DH * SP, (long)DH * SP,
        (long)S * C, DH, NH);

    // proj GEMM + fused residual (writes out, tok2 fp32 + hi/lo)
    hmma4_gemm_kernel<4><<<dim3(C / 128, MT, 1), 256, SMEM_GEMM>>>(
        p_oh, p_ol, p_wh + OFF_PROJ, p_wl + OFF_PROJ,
        p_tok2, p_t2h, p_t2l, x, out, nullptr, 0,
        BS, C, C, C, C, C, 0, 0, 0, 0, 0, 0, 1);

    // router
    {
        dim3 blk(32, 8);
        router_kernel<<<(BS + 7) / 8, blk>>>(router_w);
    }

    // MoE experts: fused gate+up GEMM (swiglu epilogue) + down GEMM
    for (int e = 0; e < NEXP; e++) {
        hmma4_gemm_kernel<3><<<dim3(2 * HID / 128, MT, 1), 256, SMEM_GEMM>>>(
            p_t2h, p_t2l, p_wh + OFF_GU + e * WSZ_GU2, p_wl + OFF_GU + e * WSZ_GU2,
            nullptr, p_hh, p_hl, nullptr, nullptr, p_gw, e,
            BS, 2 * HID, C, C, C, 0, 0, 0, 0, 0, 0, 0, 1);

        if (e == 0)
            hmma4_gemm_kernel<0><<<dim3(C / 128, MT, 1), 256, SMEM_GEMM>>>(
                p_hh, p_hl, p_wh + OFF_DOWN + e * WSZ_DN, p_wl + OFF_DOWN + e * WSZ_DN,
                p_acc, nullptr, nullptr, nullptr, nullptr, nullptr, 0,
                BS, C, HID, HID, HID, C, 0, 0, 0, 0, 0, 0, 1);
        else
            hmma4_gemm_kernel<1><<<dim3(C / 128, MT, 1), 256, SMEM_GEMM>>>(
                p_hh, p_hl, p_wh + OFF_DOWN + e * WSZ_DN, p_wl + OFF_DOWN + e * WSZ_DN,
                p_acc, nullptr, nullptr, nullptr, nullptr, nullptr, 0,
                BS, C, HID, HID, HID, C, 0, 0, 0, 0, 0, 0, 1);
    }

    // final add
    final_kernel<<<(int)((n_elem + 255) / 256), 256>>>(out);
}

// round 9
// speedup vs baseline: 2.3051x; 1.0038x over previous
#include <cuda_runtime.h>
#include <cuda_bf16.h>
#include <cstdint>

// ---------------- problem constants ----------------
#define BATCH 8
#define C 768
#define S 729               // 9^3
#define SP 736              // S padded to multiple of 32
#define NH 8
#define DH 96               // C / NH
#define HID 2048
#define NEXP 3
#define BS (BATCH * S)      // 5832 tokens
#define BH (BATCH * NH)     // 64
#define EPS 1e-5f

// weight pool offsets (elements) in transposed (N,K) bf16 hi/lo pools
#define OFF_QKV  0L
#define OFF_PROJ 1769472L
#define OFF_GU   2359296L          // interleaved gate/up, stride 2*C*HID per expert
#define WSZ_GU2  3145728L
#define OFF_DOWN 11796480L
#define WSZ_DN   1572864L
#define WPOOL    16515072L

// ---------------- static device scratch (no allocs allowed) ----------------
__device__ __nv_bfloat16 g_tok1h[(long)BS * C], g_tok1l[(long)BS * C];
__device__ float g_attn[(long)BH * S * SP];               // scores, padded cols
__device__ __nv_bfloat16 g_ph[(long)BH * S * SP], g_pl[(long)BH * S * SP];
__device__ __nv_bfloat16 g_qh[(long)BH * S * DH], g_ql[(long)BH * S * DH];
__device__ __nv_bfloat16 g_kh[(long)BH * S * DH], g_kl[(long)BH * S * DH];
__device__ __nv_bfloat16 g_vth[(long)BH * DH * SP], g_vtl[(long)BH * DH * SP];
__device__ __nv_bfloat16 g_oh[(long)BS * C], g_ol[(long)BS * C];
__device__ float g_tok2[(long)BS * C];
__device__ __nv_bfloat16 g_tok2h[(long)BS * C], g_tok2l[(long)BS * C];
__device__ __nv_bfloat16 g_hidh[(long)BS * HID], g_hidl[(long)BS * HID];
__device__ float g_acc [(long)BS * C];
__device__ float g_w   [(long)BS * NEXP];
__device__ float g_stats[BATCH * 2];
__device__ __nv_bfloat16 g_wth[WPOOL], g_wtl[WPOOL];

__device__ __forceinline__ void hilo1(float x, __nv_bfloat16& h, __nv_bfloat16& l) {
    h = __float2bfloat16(x);
    l = __float2bfloat16(x - __bfloat162float(h));
}

__device__ __forceinline__ void mma16816(float* c, const uint32_t* a, const uint32_t* b) {
    asm volatile(
        "mma.sync.aligned.m16n8k16.row.col.f32.bf16.bf16.f32 "
        "{%0,%1,%2,%3}, {%4,%5,%6,%7}, {%8,%9}, {%0,%1,%2,%3};"
        : "+f"(c[0]), "+f"(c[1]), "+f"(c[2]), "+f"(c[3])
        : "r"(a[0]), "r"(a[1]), "r"(a[2]), "r"(a[3]), "r"(b[0]), "r"(b[1]));
}

// ================== weight transpose+split (row = n*mul + add) ==================
__global__ void wconv_kernel(const float* __restrict__ W,
                             __nv_bfloat16* __restrict__ th,
                             __nv_bfloat16* __restrict__ tl,
                             int K, int N, int mul, int add) {
    __shared__ float t[32][33];
    int nt = blockIdx.x * 32, kt = blockIdx.y * 32;
    int tx = threadIdx.x & 31, ty = threadIdx.x >> 5;
    for (int r = ty; r < 32; r += 8)
        t[r][tx] = W[(long)(kt + r) * N + nt + tx];
    __syncthreads();
    for (int r = ty; r < 32; r += 8) {
        float v = t[tx][r];
        __nv_bfloat16 h, l;
        hilo1(v, h, l);
        long o = ((long)(nt + r) * mul + add) * K + kt + tx;
        th[o] = h;
        tl[o] = l;
    }
}

// ================== epilogue dispatch ==================
// EPI: 0=store, 1=accumulate, 2=qkv split, 3=swiglu, 4=proj+residual, 5=bf16 out
template<int EPI>
__device__ __forceinline__ void epi_store(
    int row, int col, float x, float y, int ldc,
    float* Cm, __nv_bfloat16* Eh, __nv_bfloat16* El,
    const float* Xaux, float* Faux, const float* Wrow, int eidx)
{
    if (EPI == 0) {
        *reinterpret_cast<float2*>(Cm + (long)row * ldc + col) = make_float2(x, y);
    } else if (EPI == 1) {
        float2* p = reinterpret_cast<float2*>(Cm + (long)row * ldc + col);
        float2 o = *p; o.x += x; o.y += y; *p = o;
    } else if (EPI == 2) {
        int b = row / S, s = row - b * S;
        int which = col / C;
        int hd = col - which * C;
        int h = hd / DH, d = hd - h * DH;
        __nv_bfloat16 xh, xl, yh, yl;
        hilo1(x, xh, xl); hilo1(y, yh, yl);
        if (which == 2) {
            long o = ((long)(b * NH + h) * DH + d) * SP + s;
            g_vth[o] = xh; g_vtl[o] = xl;
            g_vth[o + SP] = yh; g_vtl[o + SP] = yl;
        } else {
            long o = ((long)(b * NH + h) * S + s) * DH + d;
            __nv_bfloat16* H = which ? g_kh : g_qh;
            __nv_bfloat16* L = which ? g_kl : g_ql;
            H[o] = xh; H[o + 1] = yh;
            L[o] = xl; L[o + 1] = yl;
        }
    } else if (EPI == 3) {
        float w = Wrow[row * 3 + eidx];
        float sig = 1.f / (1.f + __expf(-x));
        float v = x * sig * y * w;
        __nv_bfloat16 h, l; hilo1(v, h, l);
        long o = (long)row * HID + (col >> 1);
        Eh[o] = h; El[o] = l;
    } else if (EPI == 4) {
        int b = row / S, s = row - b * S;
        long xo = ((long)b * C + col) * S + s;
        float v0 = x + Xaux[xo];
        float v1 = y + Xaux[xo + S];
        Faux[xo] = v0; Faux[xo + S] = v1;
        *reinterpret_cast<float2*>(Cm + (long)row * ldc + col) = make_float2(v0, v1);
        __nv_bfloat16 h, l;
        hilo1(v0, h, l); Eh[(long)row * ldc + col] = h;     El[(long)row * ldc + col] = l;
        hilo1(v1, h, l); Eh[(long)row * ldc + col + 1] = h; El[(long)row * ldc + col + 1] = l;
    } else {  // 5
        __nv_bfloat16 h, l;
        hilo1(x, h, l); Eh[(long)row * ldc + col] = h;     El[(long)row * ldc + col] = l;
        hilo1(y, h, l); Eh[(long)row * ldc + col + 1] = h; El[(long)row * ldc + col + 1] = l;
    }
}

// ================== generalized 3-stage pipelined HMMA bf16x3 GEMM ==================
#define LDT 20
#define TSZ (128 * LDT)
#define STAGES 3

__device__ __forceinline__ void load_chunks(
    uint32_t sb32, int stage, int k0, int tid, int m0, int n0, int M, int N,
    int lda, int ldb,
    const __nv_bfloat16* __restrict__ Ah, const __nv_bfloat16* __restrict__ Al,
    const __nv_bfloat16* __restrict__ Bh, const __nv_bfloat16* __restrict__ Bl)
{
#pragma unroll
    for (int j = 0; j < 8; j++) {
        int c = tid + j * 256;
        int mat = c >> 9;          // 0:Ah 1:Al 2:Bh 3:Bl
        int idx = c & 511;
        int row = idx >> 2;
        int seg = idx & 3;
        const __nv_bfloat16* g;
        int vb = 16;
        if (mat < 2) {
            int r = m0 + row;
            if (r >= M) { r = M - 1; vb = 0; }
            g = ((mat == 0) ? Ah : Al) + (long)r * lda;
        } else {
            int r = n0 + row;
            if (r >= N) { r = N - 1; vb = 0; }
            g = ((mat == 2) ? Bh : Bl) + (long)r * ldb;
        }
        g += k0 + seg * 8;
        uint32_t dst = sb32 + (uint32_t)((stage * 4 * TSZ + mat * TSZ + row * LDT + seg * 4) * 4);
        asm volatile("cp.async.ca.shared.global [%0], [%1], 16, %2;"
                     :: "r"(dst), "l"(g), "r"(vb) : "memory");
    }
}

template<int EPI>
__global__ void __launch_bounds__(256)
hmma4_gemm_kernel(const __nv_bfloat16* __restrict__ Ah, const __nv_bfloat16* __restrict__ Al,
                  const __nv_bfloat16* __restrict__ Bh, const __nv_bfloat16* __restrict__ Bl,
                  float* __restrict__ Cm, __nv_bfloat16* __restrict__ Eh, __nv_bfloat16* __restrict__ El,
                  const float* __restrict__ Xaux, float* __restrict__ Faux,
                  const float* __restrict__ Wrow, int eidx,
                  int M, int N, int K, int lda, int ldb, int ldc,
                  long sA1, long sA2, long sB1, long sB2, long sC1, long sC2, int div)
{
    extern __shared__ uint32_t smp[];
    const int tid = threadIdx.x;
    const int lane = tid & 31;
    const int w = tid >> 5;
    const int wm = w & 3;
    const int wn = w >> 2;
    const int gid = lane >> 2;
    const int tig = lane & 3;
    const int m0 = blockIdx.y * 128;
    const int n0 = blockIdx.x * 128;
    uint32_t sb32 = (uint32_t)__cvta_generic_to_shared(smp);

    int z = blockIdx.z;
    int z1 = z / div, z2 = z % div;
    Ah += z1 * sA1 + z2 * sA2;  Al += z1 * sA1 + z2 * sA2;
    Bh += z1 * sB1 + z2 * sB2;  Bl += z1 * sB1 + z2 * sB2;
    Cm += z1 * sC1 + z2 * sC2;
    if (EPI == 5) { Eh += z1 * sC1 + z2 * sC2; El += z1 * sC1 + z2 * sC2; }

    float acc[2][8][4];
#pragma unroll
    for (int i = 0; i < 2; i++)
#pragma unroll
        for (int j = 0; j < 8; j++)
#pragma unroll
            for (int q = 0; q < 4; q++) acc[i][j][q] = 0.f;

    const int NKB = K >> 5;

    // prologue: stages 0 and 1 in flight
    load_chunks(sb32, 0, 0, tid, m0, n0, M, N, lda, ldb, Ah, Al, Bh, Bl);
    asm volatile("cp.async.commit_group;" ::: "memory");
    if (NKB > 1) {
        load_chunks(sb32, 1, 32, tid, m0, n0, M, N, lda, ldb, Ah, Al, Bh, Bl);
        asm volatile("cp.async.commit_group;" ::: "memory");
    }

    int stage = 0;
    for (int kb = 0; kb < NKB; kb++) {
        if (kb + 1 < NKB)
            asm volatile("cp.async.wait_group 1;" ::: "memory");
        else
            asm volatile("cp.async.wait_group 0;" ::: "memory");
        __syncthreads();

        if (kb + 2 < NKB) {
            int ls = stage + 2; if (ls >= STAGES) ls -= STAGES;
            load_chunks(sb32, ls, (kb + 2) << 5, tid, m0, n0, M, N, lda, ldb, Ah, Al, Bh, Bl);
            asm volatile("cp.async.commit_group;" ::: "memory");
        }

        const uint32_t* sAhi = smp + stage * 4 * TSZ;
        const uint32_t* sAlo = sAhi + TSZ;
        const uint32_t* sBhi = sAhi + 2 * TSZ;
        const uint32_t* sBlo = sAhi + 3 * TSZ;

#pragma unroll
        for (int k16 = 0; k16 < 2; k16++) {
            const int kb8 = k16 * 8;
            uint32_t ahi[2][4], alo[2][4];
#pragma unroll
            for (int mt = 0; mt < 2; mt++) {
                int r0 = (wm * 32 + mt * 16 + gid) * LDT;
                int r8 = r0 + 8 * LDT;
                ahi[mt][0] = sAhi[r0 + kb8 + tig];
                ahi[mt][1] = sAhi[r8 + kb8 + tig];
                ahi[mt][2] = sAhi[r0 + kb8 + 4 + tig];
                ahi[mt][3] = sAhi[r8 + kb8 + 4 + tig];
                alo[mt][0] = sAlo[r0 + kb8 + tig];
                alo[mt][1] = sAlo[r8 + kb8 + tig];
                alo[mt][2] = sAlo[r0 + kb8 + 4 + tig];
                alo[mt][3] = sAlo[r8 + kb8 + 4 + tig];
            }
#pragma unroll
            for (int nt = 0; nt < 8; nt++) {
                int nr = (wn * 64 + nt * 8 + gid) * LDT;
                uint32_t bhi[2], blo[2];
                bhi[0] = sBhi[nr + kb8 + tig];
                bhi[1] = sBhi[nr + kb8 + 4 + tig];
                blo[0] = sBlo[nr + kb8 + tig];
                blo[1] = sBlo[nr + kb8 + 4 + tig];
#pragma unroll
                for (int mt = 0; mt < 2; mt++) {
                    mma16816(acc[mt][nt], ahi[mt], bhi);
                    mma16816(acc[mt][nt], ahi[mt], blo);
                    mma16816(acc[mt][nt], alo[mt], bhi);
                }
            }
        }
        __syncthreads();
        if (++stage == STAGES) stage = 0;
    }

    // ---- fused epilogue ----
#pragma unroll
    for (int mt = 0; mt < 2; mt++) {
        int row = m0 + wm * 32 + mt * 16 + gid;
#pragma unroll
        for (int nt = 0; nt < 8; nt++) {
            int col = n0 + wn * 64 + nt * 8 + tig * 2;
            if (col >= N) continue;
            if (row < M)
                epi_store<EPI>(row, col, acc[mt][nt][0], acc[mt][nt][1], ldc,
                               Cm, Eh, El, Xaux, Faux, Wrow, eidx);
            if (row + 8 < M)
                epi_store<EPI>(row + 8, col, acc[mt][nt][2], acc[mt][nt][3], ldc,
                               Cm, Eh, El, Xaux, Faux, Wrow, eidx);
        }
    }
}

// ---------------- LayerNorm statistics ----------------
__global__ void stats_kernel(const float* __restrict__ x) {
    int b = blockIdx.x;
    const float* xb = x + (long)b * C * S;
    const int N = C * S;
    float s = 0.f, s2 = 0.f;
    for (int i = threadIdx.x; i < N; i += blockDim.x) {
        float v = xb[i];
        s += v; s2 += v * v;
    }
    __shared__ float sh[256], sh2[256];
    int tid = threadIdx.x;
    sh[tid] = s; sh2[tid] = s2;
    __syncthreads();
    for (int st = 128; st > 0; st >>= 1) {
        if (tid < st) { sh[tid] += sh[tid + st]; sh2[tid] += sh2[tid + st]; }
        __syncthreads();
    }
    if (tid == 0) {
        float m = sh[0] / (float)N;
        g_stats[b * 2 + 0] = m;
        g_stats[b * 2 + 1] = sh2[0] / (float)N - m * m;
    }
}

// ---------------- LN apply + transpose + bf16 split ----------------
__global__ void ln_kernel(const float* __restrict__ x,
                          const float* __restrict__ w,
                          const float* __restrict__ bia) {
    long idx = (long)blockIdx.x * blockDim.x + threadIdx.x;
    if (idx >= (long)BATCH * C * S) return;
    int b   = (int)(idx / ((long)C * S));
    int rem = (int)(idx % ((long)C * S));
    int c = rem / S, s = rem % S;
    float m   = g_stats[b * 2 + 0];
    float var = g_stats[b * 2 + 1];
    float y = (x[idx] - m) * rsqrtf(var + EPS) * w[rem] + bia[rem];
    long t = ((long)b * S + s) * C + c;
    __nv_bfloat16 h, l;
    hilo1(y, h, l);
    g_tok1h[t] = h;
    g_tok1l[t] = l;
}

// ---------------- fused one-pass softmax -> bf16 hi/lo P (padded) ----------------
__global__ void softmax_bf_kernel() {
    long row = blockIdx.x;                    // BH * S rows
    const float* p = g_attn + row * SP;
    __nv_bfloat16* ph = g_ph + row * SP;
    __nv_bfloat16* pl = g_pl + row * SP;
    int tid = threadIdx.x;
    __shared__ float sw[8];

    int i2 = tid + 512;
    float v0 = p[tid];
    float v1 = p[tid + 256];
    float v2 = (i2 < S) ? p[i2] : -1e30f;

    float mx = fmaxf(v0, fmaxf(v1, v2));
#pragma unroll
    for (int o = 16; o > 0; o >>= 1) mx = fmaxf(mx, __shfl_xor_sync(~0u, mx, o));
    if ((tid & 31) == 0) sw[tid >> 5] = mx;
    __syncthreads();
    if (tid < 32) {
        float m = (tid < 8) ? sw[tid] : -1e30f;
#pragma unroll
        for (int o = 4; o > 0; o >>= 1) m = fmaxf(m, __shfl_xor_sync(~0u, m, o));
        if (tid == 0) sw[0] = m;
    }
    __syncthreads();
    mx = sw[0];
    __syncthreads();

    float e0 = __expf(v0 - mx);
    float e1 = __expf(v1 - mx);
    float e2 = (i2 < S) ? __expf(v2 - mx) : 0.f;
    float sum = e0 + e1 + e2;
#pragma unroll
    for (int o = 16; o > 0; o >>= 1) sum += __shfl_xor_sync(~0u, sum, o);
    if ((tid & 31) == 0) sw[tid >> 5] = sum;
    __syncthreads();
    if (tid < 32) {
        float s = (tid < 8) ? sw[tid] : 0.f;
#pragma unroll
        for (int o = 4; o > 0; o >>= 1) s += __shfl_xor_sync(~0u, s, o);
        if (tid == 0) sw[0] = s;
    }
    __syncthreads();
    float inv = 1.f / sw[0];

    __nv_bfloat16 h, l;
    hilo1(e0 * inv, h, l); ph[tid] = h;       pl[tid] = l;
    hilo1(e1 * inv, h, l); ph[tid + 256] = h; pl[tid + 256] = l;
    if (i2 < SP) {
        float v = (i2 < S) ? e2 * inv : 0.f;
        hilo1(v, h, l); ph[i2] = h; pl[i2] = l;
    }
}

// ---------------- router ----------------
__global__ void router_kernel(const float* __restrict__ rw) {
    int t = blockIdx.x * blockDim.y + threadIdx.y;
    if (t >= BS) return;
    const float* tok = g_tok2 + (long)t * C;
    float l0 = 0.f, l1 = 0.f, l2 = 0.f;
    for (int c = threadIdx.x; c < C; c += 32) {
        float v = tok[c];
        l0 += v * rw[c * 3 + 0];
        l1 += v * rw[c * 3 + 1];
        l2 += v * rw[c * 3 + 2];
    }
#pragma unroll
    for (int off = 16; off > 0; off >>= 1) {
        l0 += __shfl_down_sync(0xFFFFFFFFu, l0, off);
        l1 += __shfl_down_sync(0xFFFFFFFFu, l1, off);
        l2 += __shfl_down_sync(0xFFFFFFFFu, l2, off);
    }
    if (threadIdx.x == 0) {
        float mx = fmaxf(l0, fmaxf(l1, l2));
        float e0 = __expf(l0 - mx), e1 = __expf(l1 - mx), e2 = __expf(l2 - mx);
        float tot = e0 + e1 + e2;
        float p[3] = { e0 / tot, e1 / tot, e2 / tot };
        int i1 = 0;
        if (p[1] > p[i1]) i1 = 1;
        if (p[2] > p[i1]) i1 = 2;
        int i2 = -1;
        for (int i = 0; i < 3; i++) {
            if (i == i1) continue;
            if (i2 < 0 || p[i] > p[i2]) i2 = i;
        }
        float den = p[i1] + p[i2];
        float w[3] = { 0.f, 0.f, 0.f };
        w[i1] = p[i1] / den;
        w[i2] = p[i2] / den;
        g_w[t * 3 + 0] = w[0];
        g_w[t * 3 + 1] = w[1];
        g_w[t * 3 + 2] = w[2];
    }
}

// ---------------- out(b,c,s) += acc(b,s,c) ----------------
__global__ void final_kernel(float* __restrict__ out) {
    long idx = (long)blockIdx.x * blockDim.x + threadIdx.x;
    if (idx >= (long)BATCH * C * S) return;
    int b   = (int)(idx / ((long)C * S));
    int rem = (int)(idx % ((long)C * S));
    int c = rem / S, s = rem % S;
    out[idx] += g_acc[((long)b * S + s) * C + c];
}

// ---------------- launcher ----------------
extern "C" void kernel_launch(void* const* d_in, const int* in_sizes, int n_in,
                              void* d_out, int out_size) {
    const float* x        = (const float*)d_in[0];
    const float* ln_w     = (const float*)d_in[1];
    const float* ln_b     = (const float*)d_in[2];
    const float* qkv_w    = (const float*)d_in[3];
    const float* proj_w   = (const float*)d_in[4];
    const float* router_w = (const float*)d_in[5];
    const float* gate_w   = (const float*)d_in[6];
    const float* up_w     = (const float*)d_in[7];
    const float* down_w   = (const float*)d_in[8];
    float* out = (float*)d_out;

    float *p_attn, *p_tok2, *p_acc, *p_gw;
    __nv_bfloat16 *p_t1h, *p_t1l, *p_oh, *p_ol, *p_t2h, *p_t2l, *p_hh, *p_hl, *p_wh, *p_wl;
    __nv_bfloat16 *p_ph, *p_pl, *p_qh, *p_ql, *p_kh, *p_kl, *p_vth, *p_vtl;
    cudaGetSymbolAddress((void**)&p_attn, g_attn);
    cudaGetSymbolAddress((void**)&p_tok2, g_tok2);
    cudaGetSymbolAddress((void**)&p_acc,  g_acc);
    cudaGetSymbolAddress((void**)&p_gw,   g_w);
    cudaGetSymbolAddress((void**)&p_t1h, g_tok1h);
    cudaGetSymbolAddress((void**)&p_t1l, g_tok1l);
    cudaGetSymbolAddress((void**)&p_oh,  g_oh);
    cudaGetSymbolAddress((void**)&p_ol,  g_ol);
    cudaGetSymbolAddress((void**)&p_t2h, g_tok2h);
    cudaGetSymbolAddress((void**)&p_t2l, g_tok2l);
    cudaGetSymbolAddress((void**)&p_hh,  g_hidh);
    cudaGetSymbolAddress((void**)&p_hl,  g_hidl);
    cudaGetSymbolAddress((void**)&p_wh,  g_wth);
    cudaGetSymbolAddress((void**)&p_wl,  g_wtl);
    cudaGetSymbolAddress((void**)&p_ph,  g_ph);
    cudaGetSymbolAddress((void**)&p_pl,  g_pl);
    cudaGetSymbolAddress((void**)&p_qh,  g_qh);
    cudaGetSymbolAddress((void**)&p_ql,  g_ql);
    cudaGetSymbolAddress((void**)&p_kh,  g_kh);
    cudaGetSymbolAddress((void**)&p_kl,  g_kl);
    cudaGetSymbolAddress((void**)&p_vth, g_vth);
    cudaGetSymbolAddress((void**)&p_vtl, g_vtl);

    const int SMEM_GEMM = STAGES * 4 * TSZ * 4;   // 122880 B
    cudaFuncSetAttribute(hmma4_gemm_kernel<0>, cudaFuncAttributeMaxDynamicSharedMemorySize, SMEM_GEMM);
    cudaFuncSetAttribute(hmma4_gemm_kernel<1>, cudaFuncAttributeMaxDynamicSharedMemorySize, SMEM_GEMM);
    cudaFuncSetAttribute(hmma4_gemm_kernel<2>, cudaFuncAttributeMaxDynamicSharedMemorySize, SMEM_GEMM);
    cudaFuncSetAttribute(hmma4_gemm_kernel<3>, cudaFuncAttributeMaxDynamicSharedMemorySize, SMEM_GEMM);
    cudaFuncSetAttribute(hmma4_gemm_kernel<4>, cudaFuncAttributeMaxDynamicSharedMemorySize, SMEM_GEMM);
    cudaFuncSetAttribute(hmma4_gemm_kernel<5>, cudaFuncAttributeMaxDynamicSharedMemorySize, SMEM_GEMM);

    const long n_elem = (long)BATCH * C * S;
    const int MT = (BS + 127) / 128;   // 46 row tiles

    // 1) qkv weight conversion first
    wconv_kernel<<<dim3(3 * C / 32, C / 32), 256>>>(qkv_w,  p_wh + OFF_QKV,  p_wl + OFF_QKV,  C, 3 * C, 1, 0);

    // 2-3) LayerNorm
    stats_kernel<<<BATCH, 256>>>(x);
    ln_kernel<<<(int)((n_elem + 255) / 256), 256>>>(x, ln_w, ln_b);

    // 4) qkv GEMM with fused q/k/v split epilogue
    hmma4_gemm_kernel<2><<<dim3(3 * C / 128, MT, 1), 256, SMEM_GEMM>>>(
        p_t1h, p_t1l, p_wh + OFF_QKV, p_wl + OFF_QKV,
        nullptr, nullptr, nullptr, nullptr, nullptr, nullptr, 0,
        BS, 3 * C, C, C, C, 0, 0, 0, 0, 0, 0, 0, 1);

    // 5) scores: per (b,h) 729x729 = q @ k^T
    hmma4_gemm_kernel<0><<<dim3(6, 6, BH), 256, SMEM_GEMM>>>(
        p_qh, p_ql, p_kh, p_kl,
        p_attn, nullptr, nullptr, nullptr, nullptr, nullptr, 0,
        S, S, DH, DH, DH, SP,
        (long)NH * S * DH, (long)S * DH,
        (long)NH * S * DH, (long)S * DH,
        (long)NH * S * SP, (long)S * SP, NH);

    // 6) softmax -> bf16 hi/lo P
    softmax_bf_kernel<<<BH * S, 256>>>();

    // 7+) remaining weight conversions
    wconv_kernel<<<dim3(C / 32, C / 32), 256>>>(proj_w, p_wh + OFF_PROJ, p_wl + OFF_PROJ, C, C, 1, 0);
    for (int e = 0; e < NEXP; e++) {
        wconv_kernel<<<dim3(HID / 32, C / 32), 256>>>(
            gate_w + (long)e * C * HID, p_wh + OFF_GU + e * WSZ_GU2, p_wl + OFF_GU + e * WSZ_GU2, C, HID, 2, 0);
        wconv_kernel<<<dim3(HID / 32, C / 32), 256>>>(
            up_w + (long)e * C * HID,   p_wh + OFF_GU + e * WSZ_GU2, p_wl + OFF_GU + e * WSZ_GU2, C, HID, 2, 1);
        wconv_kernel<<<dim3(C / 32, HID / 32), 256>>>(
            down_w + (long)e * HID * C, p_wh + OFF_DOWN + e * WSZ_DN, p_wl + OFF_DOWN + e * WSZ_DN, HID, C, 1, 0);
    }

    // PV: per (b,h) 729x96 = P @ V, bf16 hi/lo out
    hmma4_gemm_kernel<5><<<dim3(1, 6, BH), 256, SMEM_GEMM>>>(
        p_ph, p_pl, p_vth, p_vtl,
        nullptr, p_oh, p_ol, nullptr, nullptr, nullptr, 0,
        S, DH, SP, SP, SP, C,
        (long)NH * S * SP, (long)S * SP,
        (long)NH * DH * SP, (long)DH * SP,
        (long)S * C, DH, NH);

    // proj GEMM + fused residual (writes out, tok2 fp32 + hi/lo)
    hmma4_gemm_kernel<4><<<dim3(C / 128, MT, 1), 256, SMEM_GEMM>>>(
        p_oh, p_ol, p_wh + OFF_PROJ, p_wl + OFF_PROJ,
        p_tok2, p_t2h, p_t2l, x, out, nullptr, 0,
        BS, C, C, C, C, C, 0, 0, 0, 0, 0, 0, 1);

    // router
    {
        dim3 blk(32, 8);
        router_kernel<<<(BS + 7) / 8, blk>>>(router_w);
    }

    // MoE experts: fused gate+up GEMM (swiglu epilogue) + down GEMM
    for (int e = 0; e < NEXP; e++) {
        hmma4_gemm_kernel<3><<<dim3(2 * HID / 128, MT, 1), 256, SMEM_GEMM>>>(
            p_t2h, p_t2l, p_wh + OFF_GU + e * WSZ_GU2, p_wl + OFF_GU + e * WSZ_GU2,
            nullptr, p_hh, p_hl, nullptr, nullptr, p_gw, e,
            BS, 2 * HID, C, C, C, 0, 0, 0, 0, 0, 0, 0, 1);

        if (e == 0)
            hmma4_gemm_kernel<0><<<dim3(C / 128, MT, 1), 256, SMEM_GEMM>>>(
                p_hh, p_hl, p_wh + OFF_DOWN + e * WSZ_DN, p_wl + OFF_DOWN + e * WSZ_DN,
                p_acc, nullptr, nullptr, nullptr, nullptr, nullptr, 0,
                BS, C, HID, HID, HID, C, 0, 0, 0, 0, 0, 0, 1);
        else
            hmma4_gemm_kernel<1><<<dim3(C / 128, MT, 1), 256, SMEM_GEMM>>>(
                p_hh, p_hl, p_wh + OFF_DOWN + e * WSZ_DN, p_wl + OFF_DOWN + e * WSZ_DN,
                p_acc, nullptr, nullptr, nullptr, nullptr, nullptr, 0,
                BS, C, HID, HID, HID, C, 0, 0, 0, 0, 0, 0, 1);
    }

    // final add
    final_kernel<<<(int)((n_elem + 255) / 256), 256>>>(out);
}

// round 10
// speedup vs baseline: 2.5878x; 1.1226x over previous
#include <cuda_runtime.h>
#include <cuda_bf16.h>
#include <cstdint>

// ---------------- problem constants ----------------
#define BATCH 8
#define C 768
#define S 729               // 9^3
#define SP 736              // S padded to multiple of 32
#define NH 8
#define DH 96               // C / NH
#define HID 2048
#define NEXP 3
#define BS (BATCH * S)      // 5832 tokens
#define BH (BATCH * NH)     // 64
#define EPS 1e-5f

// weight pool offsets (elements) in transposed (N,K) bf16 hi/lo pools
#define OFF_QKV  0L
#define OFF_PROJ 1769472L
#define OFF_GU   2359296L          // interleaved gate/up, stride 2*C*HID per expert
#define WSZ_GU2  3145728L
#define OFF_DOWN 11796480L
#define WSZ_DN   1572864L
#define WPOOL    16515072L

// ---------------- static device scratch (no allocs allowed) ----------------
__device__ __nv_bfloat16 g_tok1h[(long)BS * C], g_tok1l[(long)BS * C];
__device__ float g_attn[(long)BH * S * SP];               // scores, padded cols
__device__ __nv_bfloat16 g_ph[(long)BH * S * SP], g_pl[(long)BH * S * SP];
__device__ __nv_bfloat16 g_qh[(long)BH * S * DH], g_ql[(long)BH * S * DH];
__device__ __nv_bfloat16 g_kh[(long)BH * S * DH], g_kl[(long)BH * S * DH];
__device__ __nv_bfloat16 g_vth[(long)BH * DH * SP], g_vtl[(long)BH * DH * SP];
__device__ __nv_bfloat16 g_oh[(long)BS * C], g_ol[(long)BS * C];
__device__ float g_tok2[(long)BS * C];
__device__ __nv_bfloat16 g_tok2h[(long)BS * C], g_tok2l[(long)BS * C];
__device__ __nv_bfloat16 g_hidh[(long)BS * HID], g_hidl[(long)BS * HID];
__device__ float g_acc [(long)BS * C];
__device__ float g_w   [(long)BS * NEXP];
__device__ float g_stats[BATCH * 2];
__device__ __nv_bfloat16 g_wth[WPOOL], g_wtl[WPOOL];

__device__ __forceinline__ void hilo1(float x, __nv_bfloat16& h, __nv_bfloat16& l) {
    h = __float2bfloat16(x);
    l = __float2bfloat16(x - __bfloat162float(h));
}

__device__ __forceinline__ void mma16816(float* c, const uint32_t* a, const uint32_t* b) {
    asm volatile(
        "mma.sync.aligned.m16n8k16.row.col.f32.bf16.bf16.f32 "
        "{%0,%1,%2,%3}, {%4,%5,%6,%7}, {%8,%9}, {%0,%1,%2,%3};"
        : "+f"(c[0]), "+f"(c[1]), "+f"(c[2]), "+f"(c[3])
        : "r"(a[0]), "r"(a[1]), "r"(a[2]), "r"(a[3]), "r"(b[0]), "r"(b[1]));
}

// ================== weight transpose+split (row = n*mul + add) ==================
__global__ void wconv_kernel(const float* __restrict__ W,
                             __nv_bfloat16* __restrict__ th,
                             __nv_bfloat16* __restrict__ tl,
                             int K, int N, int mul, int add) {
    __shared__ float t[32][33];
    int nt = blockIdx.x * 32, kt = blockIdx.y * 32;
    int tx = threadIdx.x & 31, ty = threadIdx.x >> 5;
    for (int r = ty; r < 32; r += 8)
        t[r][tx] = W[(long)(kt + r) * N + nt + tx];
    __syncthreads();
    for (int r = ty; r < 32; r += 8) {
        float v = t[tx][r];
        __nv_bfloat16 h, l;
        hilo1(v, h, l);
        long o = ((long)(nt + r) * mul + add) * K + kt + tx;
        th[o] = h;
        tl[o] = l;
    }
}

// ================== epilogue dispatch ==================
// EPI: 0=store, 1=accumulate, 2=qkv split, 3=swiglu, 4=proj+residual, 5=bf16 out
template<int EPI>
__device__ __forceinline__ void epi_store(
    int row, int col, float x, float y, int ldc,
    float* Cm, __nv_bfloat16* Eh, __nv_bfloat16* El,
    const float* Xaux, float* Faux, const float* Wrow, int eidx)
{
    if (EPI == 0) {
        *reinterpret_cast<float2*>(Cm + (long)row * ldc + col) = make_float2(x, y);
    } else if (EPI == 1) {
        float2* p = reinterpret_cast<float2*>(Cm + (long)row * ldc + col);
        float2 o = *p; o.x += x; o.y += y; *p = o;
    } else if (EPI == 2) {
        int b = row / S, s = row - b * S;
        int which = col / C;
        int hd = col - which * C;
        int h = hd / DH, d = hd - h * DH;
        __nv_bfloat16 xh, xl, yh, yl;
        hilo1(x, xh, xl); hilo1(y, yh, yl);
        if (which == 2) {
            long o = ((long)(b * NH + h) * DH + d) * SP + s;
            g_vth[o] = xh; g_vtl[o] = xl;
            g_vth[o + SP] = yh; g_vtl[o + SP] = yl;
        } else {
            long o = ((long)(b * NH + h) * S + s) * DH + d;
            __nv_bfloat16* H = which ? g_kh : g_qh;
            __nv_bfloat16* L = which ? g_kl : g_ql;
            H[o] = xh; H[o + 1] = yh;
            L[o] = xl; L[o + 1] = yl;
        }
    } else if (EPI == 3) {
        float w = Wrow[row * 3 + eidx];
        float sig = 1.f / (1.f + __expf(-x));
        float v = x * sig * y * w;
        __nv_bfloat16 h, l; hilo1(v, h, l);
        long o = (long)row * HID + (col >> 1);
        Eh[o] = h; El[o] = l;
    } else if (EPI == 4) {
        int b = row / S, s = row - b * S;
        long xo = ((long)b * C + col) * S + s;
        float v0 = x + Xaux[xo];
        float v1 = y + Xaux[xo + S];
        Faux[xo] = v0; Faux[xo + S] = v1;
        *reinterpret_cast<float2*>(Cm + (long)row * ldc + col) = make_float2(v0, v1);
        __nv_bfloat16 h, l;
        hilo1(v0, h, l); Eh[(long)row * ldc + col] = h;     El[(long)row * ldc + col] = l;
        hilo1(v1, h, l); Eh[(long)row * ldc + col + 1] = h; El[(long)row * ldc + col + 1] = l;
    } else {  // 5
        __nv_bfloat16 h, l;
        hilo1(x, h, l); Eh[(long)row * ldc + col] = h;     El[(long)row * ldc + col] = l;
        hilo1(y, h, l); Eh[(long)row * ldc + col + 1] = h; El[(long)row * ldc + col + 1] = l;
    }
}

// ================== 2-stage pipelined HMMA bf16x3 GEMM, 2 CTAs/SM ==================
#define LDT 20
#define TSZ (128 * LDT)
#define STAGES 2

__device__ __forceinline__ void load_chunks(
    uint32_t sb32, int stage, int k0, int tid, int m0, int n0, int M, int N,
    int lda, int ldb,
    const __nv_bfloat16* __restrict__ Ah, const __nv_bfloat16* __restrict__ Al,
    const __nv_bfloat16* __restrict__ Bh, const __nv_bfloat16* __restrict__ Bl)
{
#pragma unroll
    for (int j = 0; j < 8; j++) {
        int c = tid + j * 256;
        int mat = c >> 9;          // 0:Ah 1:Al 2:Bh 3:Bl
        int idx = c & 511;
        int row = idx >> 2;
        int seg = idx & 3;
        const __nv_bfloat16* g;
        int vb = 16;
        if (mat < 2) {
            int r = m0 + row;
            if (r >= M) { r = M - 1; vb = 0; }
            g = ((mat == 0) ? Ah : Al) + (long)r * lda;
        } else {
            int r = n0 + row;
            if (r >= N) { r = N - 1; vb = 0; }
            g = ((mat == 2) ? Bh : Bl) + (long)r * ldb;
        }
        g += k0 + seg * 8;
        uint32_t dst = sb32 + (uint32_t)((stage * 4 * TSZ + mat * TSZ + row * LDT + seg * 4) * 4);
        asm volatile("cp.async.ca.shared.global [%0], [%1], 16, %2;"
                     :: "r"(dst), "l"(g), "r"(vb) : "memory");
    }
}

template<int EPI>
__global__ void __launch_bounds__(256, 2)
hmma4_gemm_kernel(const __nv_bfloat16* __restrict__ Ah, const __nv_bfloat16* __restrict__ Al,
                  const __nv_bfloat16* __restrict__ Bh, const __nv_bfloat16* __restrict__ Bl,
                  float* __restrict__ Cm, __nv_bfloat16* __restrict__ Eh, __nv_bfloat16* __restrict__ El,
                  const float* __restrict__ Xaux, float* __restrict__ Faux,
                  const float* __restrict__ Wrow, int eidx,
                  int M, int N, int K, int lda, int ldb, int ldc,
                  long sA1, long sA2, long sB1, long sB2, long sC1, long sC2, int div)
{
    extern __shared__ uint32_t smp[];
    const int tid = threadIdx.x;
    const int lane = tid & 31;
    const int w = tid >> 5;
    const int wm = w & 3;
    const int wn = w >> 2;
    const int gid = lane >> 2;
    const int tig = lane & 3;
    const int m0 = blockIdx.y * 128;
    const int n0 = blockIdx.x * 128;
    uint32_t sb32 = (uint32_t)__cvta_generic_to_shared(smp);

    int z = blockIdx.z;
    int z1 = z / div, z2 = z % div;
    Ah += z1 * sA1 + z2 * sA2;  Al += z1 * sA1 + z2 * sA2;
    Bh += z1 * sB1 + z2 * sB2;  Bl += z1 * sB1 + z2 * sB2;
    Cm += z1 * sC1 + z2 * sC2;
    if (EPI == 5) { Eh += z1 * sC1 + z2 * sC2; El += z1 * sC1 + z2 * sC2; }

    float acc[2][8][4];
#pragma unroll
    for (int i = 0; i < 2; i++)
#pragma unroll
        for (int j = 0; j < 8; j++)
#pragma unroll
            for (int q = 0; q < 4; q++) acc[i][j][q] = 0.f;

    const int NKB = K >> 5;

    load_chunks(sb32, 0, 0, tid, m0, n0, M, N, lda, ldb, Ah, Al, Bh, Bl);
    asm volatile("cp.async.commit_group;" ::: "memory");

    for (int kb = 0; kb < NKB; kb++) {
        if (kb + 1 < NKB) {
            load_chunks(sb32, (kb + 1) & 1, (kb + 1) << 5, tid, m0, n0, M, N, lda, ldb, Ah, Al, Bh, Bl);
            asm volatile("cp.async.commit_group;" ::: "memory");
            asm volatile("cp.async.wait_group 1;" ::: "memory");
        } else {
            asm volatile("cp.async.wait_group 0;" ::: "memory");
        }
        __syncthreads();

        const uint32_t* sAhi = smp + (kb & 1) * 4 * TSZ;
        const uint32_t* sAlo = sAhi + TSZ;
        const uint32_t* sBhi = sAhi + 2 * TSZ;
        const uint32_t* sBlo = sAhi + 3 * TSZ;

#pragma unroll
        for (int k16 = 0; k16 < 2; k16++) {
            const int kb8 = k16 * 8;
            uint32_t ahi[2][4], alo[2][4];
#pragma unroll
            for (int mt = 0; mt < 2; mt++) {
                int r0 = (wm * 32 + mt * 16 + gid) * LDT;
                int r8 = r0 + 8 * LDT;
                ahi[mt][0] = sAhi[r0 + kb8 + tig];
                ahi[mt][1] = sAhi[r8 + kb8 + tig];
                ahi[mt][2] = sAhi[r0 + kb8 + 4 + tig];
                ahi[mt][3] = sAhi[r8 + kb8 + 4 + tig];
                alo[mt][0] = sAlo[r0 + kb8 + tig];
                alo[mt][1] = sAlo[r8 + kb8 + tig];
                alo[mt][2] = sAlo[r0 + kb8 + 4 + tig];
                alo[mt][3] = sAlo[r8 + kb8 + 4 + tig];
            }
#pragma unroll
            for (int nt = 0; nt < 8; nt++) {
                int nr = (wn * 64 + nt * 8 + gid) * LDT;
                uint32_t bhi[2], blo[2];
                bhi[0] = sBhi[nr + kb8 + tig];
                bhi[1] = sBhi[nr + kb8 + 4 + tig];
                blo[0] = sBlo[nr + kb8 + tig];
                blo[1] = sBlo[nr + kb8 + 4 + tig];
#pragma unroll
                for (int mt = 0; mt < 2; mt++) {
                    mma16816(acc[mt][nt], ahi[mt], bhi);
                    mma16816(acc[mt][nt], ahi[mt], blo);
                    mma16816(acc[mt][nt], alo[mt], bhi);
                }
            }
        }
        __syncthreads();
    }

    // ---- fused epilogue ----
#pragma unroll
    for (int mt = 0; mt < 2; mt++) {
        int row = m0 + wm * 32 + mt * 16 + gid;
#pragma unroll
        for (int nt = 0; nt < 8; nt++) {
            int col = n0 + wn * 64 + nt * 8 + tig * 2;
            if (col >= N) continue;
            if (row < M)
                epi_store<EPI>(row, col, acc[mt][nt][0], acc[mt][nt][1], ldc,
                               Cm, Eh, El, Xaux, Faux, Wrow, eidx);
            if (row + 8 < M)
                epi_store<EPI>(row + 8, col, acc[mt][nt][2], acc[mt][nt][3], ldc,
                               Cm, Eh, El, Xaux, Faux, Wrow, eidx);
        }
    }
}

// ---------------- LayerNorm statistics ----------------
__global__ void stats_kernel(const float* __restrict__ x) {
    int b = blockIdx.x;
    const float* xb = x + (long)b * C * S;
    const int N = C * S;
    float s = 0.f, s2 = 0.f;
    for (int i = threadIdx.x; i < N; i += blockDim.x) {
        float v = xb[i];
        s += v; s2 += v * v;
    }
    __shared__ float sh[256], sh2[256];
    int tid = threadIdx.x;
    sh[tid] = s; sh2[tid] = s2;
    __syncthreads();
    for (int st = 128; st > 0; st >>= 1) {
        if (tid < st) { sh[tid] += sh[tid + st]; sh2[tid] += sh2[tid + st]; }
        __syncthreads();
    }
    if (tid == 0) {
        float m = sh[0] / (float)N;
        g_stats[b * 2 + 0] = m;
        g_stats[b * 2 + 1] = sh2[0] / (float)N - m * m;
    }
}

// ---------------- LN apply + transpose + bf16 split ----------------
__global__ void ln_kernel(const float* __restrict__ x,
                          const float* __restrict__ w,
                          const float* __restrict__ bia) {
    long idx = (long)blockIdx.x * blockDim.x + threadIdx.x;
    if (idx >= (long)BATCH * C * S) return;
    int b   = (int)(idx / ((long)C * S));
    int rem = (int)(idx % ((long)C * S));
    int c = rem / S, s = rem % S;
    float m   = g_stats[b * 2 + 0];
    float var = g_stats[b * 2 + 1];
    float y = (x[idx] - m) * rsqrtf(var + EPS) * w[rem] + bia[rem];
    long t = ((long)b * S + s) * C + c;
    __nv_bfloat16 h, l;
    hilo1(y, h, l);
    g_tok1h[t] = h;
    g_tok1l[t] = l;
}

// ---------------- fused one-pass softmax -> bf16 hi/lo P (padded) ----------------
__global__ void softmax_bf_kernel() {
    long row = blockIdx.x;                    // BH * S rows
    const float* p = g_attn + row * SP;
    __nv_bfloat16* ph = g_ph + row * SP;
    __nv_bfloat16* pl = g_pl + row * SP;
    int tid = threadIdx.x;
    __shared__ float sw[8];

    int i2 = tid + 512;
    float v0 = p[tid];
    float v1 = p[tid + 256];
    float v2 = (i2 < S) ? p[i2] : -1e30f;

    float mx = fmaxf(v0, fmaxf(v1, v2));
#pragma unroll
    for (int o = 16; o > 0; o >>= 1) mx = fmaxf(mx, __shfl_xor_sync(~0u, mx, o));
    if ((tid & 31) == 0) sw[tid >> 5] = mx;
    __syncthreads();
    if (tid < 32) {
        float m = (tid < 8) ? sw[tid] : -1e30f;
#pragma unroll
        for (int o = 4; o > 0; o >>= 1) m = fmaxf(m, __shfl_xor_sync(~0u, m, o));
        if (tid == 0) sw[0] = m;
    }
    __syncthreads();
    mx = sw[0];
    __syncthreads();

    float e0 = __expf(v0 - mx);
    float e1 = __expf(v1 - mx);
    float e2 = (i2 < S) ? __expf(v2 - mx) : 0.f;
    float sum = e0 + e1 + e2;
#pragma unroll
    for (int o = 16; o > 0; o >>= 1) sum += __shfl_xor_sync(~0u, sum, o);
    if ((tid & 31) == 0) sw[tid >> 5] = sum;
    __syncthreads();
    if (tid < 32) {
        float s = (tid < 8) ? sw[tid] : 0.f;
#pragma unroll
        for (int o = 4; o > 0; o >>= 1) s += __shfl_xor_sync(~0u, s, o);
        if (tid == 0) sw[0] = s;
    }
    __syncthreads();
    float inv = 1.f / sw[0];

    __nv_bfloat16 h, l;
    hilo1(e0 * inv, h, l); ph[tid] = h;       pl[tid] = l;
    hilo1(e1 * inv, h, l); ph[tid + 256] = h; pl[tid + 256] = l;
    if (i2 < SP) {
        float v = (i2 < S) ? e2 * inv : 0.f;
        hilo1(v, h, l); ph[i2] = h; pl[i2] = l;
    }
}

// ---------------- router ----------------
__global__ void router_kernel(const float* __restrict__ rw) {
    int t = blockIdx.x * blockDim.y + threadIdx.y;
    if (t >= BS) return;
    const float* tok = g_tok2 + (long)t * C;
    float l0 = 0.f, l1 = 0.f, l2 = 0.f;
    for (int c = threadIdx.x; c < C; c += 32) {
        float v = tok[c];
        l0 += v * rw[c * 3 + 0];
        l1 += v * rw[c * 3 + 1];
        l2 += v * rw[c * 3 + 2];
    }
#pragma unroll
    for (int off = 16; off > 0; off >>= 1) {
        l0 += __shfl_down_sync(0xFFFFFFFFu, l0, off);
        l1 += __shfl_down_sync(0xFFFFFFFFu, l1, off);
        l2 += __shfl_down_sync(0xFFFFFFFFu, l2, off);
    }
    if (threadIdx.x == 0) {
        float mx = fmaxf(l0, fmaxf(l1, l2));
        float e0 = __expf(l0 - mx), e1 = __expf(l1 - mx), e2 = __expf(l2 - mx);
        float tot = e0 + e1 + e2;
        float p[3] = { e0 / tot, e1 / tot, e2 / tot };
        int i1 = 0;
        if (p[1] > p[i1]) i1 = 1;
        if (p[2] > p[i1]) i1 = 2;
        int i2 = -1;
        for (int i = 0; i < 3; i++) {
            if (i == i1) continue;
            if (i2 < 0 || p[i] > p[i2]) i2 = i;
        }
        float den = p[i1] + p[i2];
        float w[3] = { 0.f, 0.f, 0.f };
        w[i1] = p[i1] / den;
        w[i2] = p[i2] / den;
        g_w[t * 3 + 0] = w[0];
        g_w[t * 3 + 1] = w[1];
        g_w[t * 3 + 2] = w[2];
    }
}

// ---------------- out(b,c,s) += acc(b,s,c) ----------------
__global__ void final_kernel(float* __restrict__ out) {
    long idx = (long)blockIdx.x * blockDim.x + threadIdx.x;
    if (idx >= (long)BATCH * C * S) return;
    int b   = (int)(idx / ((long)C * S));
    int rem = (int)(idx % ((long)C * S));
    int c = rem / S, s = rem % S;
    out[idx] += g_acc[((long)b * S + s) * C + c];
}

// ---------------- launcher ----------------
extern "C" void kernel_launch(void* const* d_in, const int* in_sizes, int n_in,
                              void* d_out, int out_size) {
    const float* x        = (const float*)d_in[0];
    const float* ln_w     = (const float*)d_in[1];
    const float* ln_b     = (const float*)d_in[2];
    const float* qkv_w    = (const float*)d_in[3];
    const float* proj_w   = (const float*)d_in[4];
    const float* router_w = (const float*)d_in[5];
    const float* gate_w   = (const float*)d_in[6];
    const float* up_w     = (const float*)d_in[7];
    const float* down_w   = (const float*)d_in[8];
    float* out = (float*)d_out;

    float *p_attn, *p_tok2, *p_acc, *p_gw;
    __nv_bfloat16 *p_t1h, *p_t1l, *p_oh, *p_ol, *p_t2h, *p_t2l, *p_hh, *p_hl, *p_wh, *p_wl;
    __nv_bfloat16 *p_ph, *p_pl, *p_qh, *p_ql, *p_kh, *p_kl, *p_vth, *p_vtl;
    cudaGetSymbolAddress((void**)&p_attn, g_attn);
    cudaGetSymbolAddress((void**)&p_tok2, g_tok2);
    cudaGetSymbolAddress((void**)&p_acc,  g_acc);
    cudaGetSymbolAddress((void**)&p_gw,   g_w);
    cudaGetSymbolAddress((void**)&p_t1h, g_tok1h);
    cudaGetSymbolAddress((void**)&p_t1l, g_tok1l);
    cudaGetSymbolAddress((void**)&p_oh,  g_oh);
    cudaGetSymbolAddress((void**)&p_ol,  g_ol);
    cudaGetSymbolAddress((void**)&p_t2h, g_tok2h);
    cudaGetSymbolAddress((void**)&p_t2l, g_tok2l);
    cudaGetSymbolAddress((void**)&p_hh,  g_hidh);
    cudaGetSymbolAddress((void**)&p_hl,  g_hidl);
    cudaGetSymbolAddress((void**)&p_wh,  g_wth);
    cudaGetSymbolAddress((void**)&p_wl,  g_wtl);
    cudaGetSymbolAddress((void**)&p_ph,  g_ph);
    cudaGetSymbolAddress((void**)&p_pl,  g_pl);
    cudaGetSymbolAddress((void**)&p_qh,  g_qh);
    cudaGetSymbolAddress((void**)&p_ql,  g_ql);
    cudaGetSymbolAddress((void**)&p_kh,  g_kh);
    cudaGetSymbolAddress((void**)&p_kl,  g_kl);
    cudaGetSymbolAddress((void**)&p_vth, g_vth);
    cudaGetSymbolAddress((void**)&p_vtl, g_vtl);

    const int SMEM_GEMM = STAGES * 4 * TSZ * 4;   // 81920 B
    cudaFuncSetAttribute(hmma4_gemm_kernel<0>, cudaFuncAttributeMaxDynamicSharedMemorySize, SMEM_GEMM);
    cudaFuncSetAttribute(hmma4_gemm_kernel<1>, cudaFuncAttributeMaxDynamicSharedMemorySize, SMEM_GEMM);
    cudaFuncSetAttribute(hmma4_gemm_kernel<2>, cudaFuncAttributeMaxDynamicSharedMemorySize, SMEM_GEMM);
    cudaFuncSetAttribute(hmma4_gemm_kernel<3>, cudaFuncAttributeMaxDynamicSharedMemorySize, SMEM_GEMM);
    cudaFuncSetAttribute(hmma4_gemm_kernel<4>, cudaFuncAttributeMaxDynamicSharedMemorySize, SMEM_GEMM);
    cudaFuncSetAttribute(hmma4_gemm_kernel<5>, cudaFuncAttributeMaxDynamicSharedMemorySize, SMEM_GEMM);

    const long n_elem = (long)BATCH * C * S;
    const int MT = (BS + 127) / 128;   // 46 row tiles

    // 1) qkv weight conversion first
    wconv_kernel<<<dim3(3 * C / 32, C / 32), 256>>>(qkv_w,  p_wh + OFF_QKV,  p_wl + OFF_QKV,  C, 3 * C, 1, 0);

    // 2-3) LayerNorm
    stats_kernel<<<BATCH, 256>>>(x);
    ln_kernel<<<(int)((n_elem + 255) / 256), 256>>>(x, ln_w, ln_b);

    // 4) qkv GEMM with fused q/k/v split epilogue
    hmma4_gemm_kernel<2><<<dim3(3 * C / 128, MT, 1), 256, SMEM_GEMM>>>(
        p_t1h, p_t1l, p_wh + OFF_QKV, p_wl + OFF_QKV,
        nullptr, nullptr, nullptr, nullptr, nullptr, nullptr, 0,
        BS, 3 * C, C, C, C, 0, 0, 0, 0, 0, 0, 0, 1);

    // 5) scores: per (b,h) 729x729 = q @ k^T
    hmma4_gemm_kernel<0><<<dim3(6, 6, BH), 256, SMEM_GEMM>>>(
        p_qh, p_ql, p_kh, p_kl,
        p_attn, nullptr, nullptr, nullptr, nullptr, nullptr, 0,
        S, S, DH, DH, DH, SP,
        (long)NH * S * DH, (long)S * DH,
        (long)NH * S * DH, (long)S * DH,
        (long)NH * S * SP, (long)S * SP, NH);

    // 6) softmax -> bf16 hi/lo P
    softmax_bf_kernel<<<BH * S, 256>>>();

    // 7+) remaining weight conversions
    wconv_kernel<<<dim3(C / 32, C / 32), 256>>>(proj_w, p_wh + OFF_PROJ, p_wl + OFF_PROJ, C, C, 1, 0);
    for (int e = 0; e < NEXP; e++) {
        wconv_kernel<<<dim3(HID / 32, C / 32), 256>>>(
            gate_w + (long)e * C * HID, p_wh + OFF_GU + e * WSZ_GU2, p_wl + OFF_GU + e * WSZ_GU2, C, HID, 2, 0);
        wconv_kernel<<<dim3(HID / 32, C / 32), 256>>>(
            up_w + (long)e * C * HID,   p_wh + OFF_GU + e * WSZ_GU2, p_wl + OFF_GU + e * WSZ_GU2, C, HID, 2, 1);
        wconv_kernel<<<dim3(C / 32, HID / 32), 256>>>(
            down_w + (long)e * HID * C, p_wh + OFF_DOWN + e * WSZ_DN, p_wl + OFF_DOWN + e * WSZ_DN, HID, C, 1, 0);
    }

    // PV: per (b,h) 729x96 = P @ V, bf16 hi/lo out
    hmma4_gemm_kernel<5><<<dim3(1, 6, BH), 256, SMEM_GEMM>>>(
        p_ph, p_pl, p_vth, p_vtl,
        nullptr, p_oh, p_ol, nullptr, nullptr, nullptr, 0,
        S, DH, SP, SP, SP, C,
        (long)NH * S * SP, (long)S * SP,
        (long)NH * DH * SP, (long)DH * SP,
        (long)S * C, DH, NH);

    // proj GEMM + fused residual (writes out, tok2 fp32 + hi/lo)
    hmma4_gemm_kernel<4><<<dim3(C / 128, MT, 1), 256, SMEM_GEMM>>>(
        p_oh, p_ol, p_wh + OFF_PROJ, p_wl + OFF_PROJ,
        p_tok2, p_t2h, p_t2l, x, out, nullptr, 0,
        BS, C, C, C, C, C, 0, 0, 0, 0, 0, 0, 1);

    // router
    {
        dim3 blk(32, 8);
        router_kernel<<<(BS + 7) / 8, blk>>>(router_w);
    }

    // MoE experts: fused gate+up GEMM (swiglu epilogue) + down GEMM
    for (int e = 0; e < NEXP; e++) {
        hmma4_gemm_kernel<3><<<dim3(2 * HID / 128, MT, 1), 256, SMEM_GEMM>>>(
            p_t2h, p_t2l, p_wh + OFF_GU + e * WSZ_GU2, p_wl + OFF_GU + e * WSZ_GU2,
            nullptr, p_hh, p_hl, nullptr, nullptr, p_gw, e,
            BS, 2 * HID, C, C, C, 0, 0, 0, 0, 0, 0, 0, 1);

        if (e == 0)
            hmma4_gemm_kernel<0><<<dim3(C / 128, MT, 1), 256, SMEM_GEMM>>>(
                p_hh, p_hl, p_wh + OFF_DOWN + e * WSZ_DN, p_wl + OFF_DOWN + e * WSZ_DN,
                p_acc, nullptr, nullptr, nullptr, nullptr, nullptr, 0,
                BS, C, HID, HID, HID, C, 0, 0, 0, 0, 0, 0, 1);
        else
            hmma4_gemm_kernel<1><<<dim3(C / 128, MT, 1), 256, SMEM_GEMM>>>(
                p_hh, p_hl, p_wh + OFF_DOWN + e * WSZ_DN, p_wl + OFF_DOWN + e * WSZ_DN,
                p_acc, nullptr, nullptr, nullptr, nullptr, nullptr, 0,
                BS, C, HID, HID, HID, C, 0, 0, 0, 0, 0, 0, 1);
    }

    // final add
    final_kernel<<<(int)((n_elem + 255) / 256), 256>>>(out);
}

// round 11
// speedup vs baseline: 2.6383x; 1.0195x over previous
#include <cuda_runtime.h>
#include <cuda_bf16.h>
#include <cstdint>

// ---------------- problem constants ----------------
#define BATCH 8
#define C 768
#define S 729               // 9^3
#define SP 736              // S padded to multiple of 32
#define NH 8
#define DH 96               // C / NH
#define HID 2048
#define NEXP 3
#define BS (BATCH * S)      // 5832 tokens
#define BH (BATCH * NH)     // 64
#define EPS 1e-5f

// weight pool offsets (elements) in transposed (N,K) bf16 hi/lo pools
#define OFF_QKV  0L
#define OFF_PROJ 1769472L
#define OFF_GU   2359296L          // interleaved gate/up, stride 2*C*HID per expert
#define WSZ_GU2  3145728L
#define OFF_DOWN 11796480L
#define WSZ_DN   1572864L
#define WPOOL    16515072L

// ---------------- static device scratch (no allocs allowed) ----------------
__device__ __nv_bfloat16 g_tok1h[(long)BS * C], g_tok1l[(long)BS * C];
__device__ float g_attn[(long)BH * S * SP];               // scores, padded cols
__device__ __nv_bfloat16 g_ph[(long)BH * S * SP], g_pl[(long)BH * S * SP];
__device__ __nv_bfloat16 g_qh[(long)BH * S * DH], g_ql[(long)BH * S * DH];
__device__ __nv_bfloat16 g_kh[(long)BH * S * DH], g_kl[(long)BH * S * DH];
__device__ __nv_bfloat16 g_vth[(long)BH * DH * SP], g_vtl[(long)BH * DH * SP];
__device__ __nv_bfloat16 g_oh[(long)BS * C], g_ol[(long)BS * C];
__device__ float g_tok2[(long)BS * C];
__device__ __nv_bfloat16 g_tok2h[(long)BS * C], g_tok2l[(long)BS * C];
__device__ __nv_bfloat16 g_hidh[(long)BS * HID], g_hidl[(long)BS * HID];
__device__ float g_acc [(long)BS * C];
__device__ float g_w   [(long)BS * NEXP];
__device__ float g_stats[BATCH * 2];
__device__ __nv_bfloat16 g_wth[WPOOL], g_wtl[WPOOL];

__device__ __forceinline__ void hilo1(float x, __nv_bfloat16& h, __nv_bfloat16& l) {
    h = __float2bfloat16(x);
    l = __float2bfloat16(x - __bfloat162float(h));
}

__device__ __forceinline__ void mma16816(float* c, const uint32_t* a, const uint32_t* b) {
    asm volatile(
        "mma.sync.aligned.m16n8k16.row.col.f32.bf16.bf16.f32 "
        "{%0,%1,%2,%3}, {%4,%5,%6,%7}, {%8,%9}, {%0,%1,%2,%3};"
        : "+f"(c[0]), "+f"(c[1]), "+f"(c[2]), "+f"(c[3])
        : "r"(a[0]), "r"(a[1]), "r"(a[2]), "r"(a[3]), "r"(b[0]), "r"(b[1]));
}

__device__ __forceinline__ void ldsm4(uint32_t* r, uint32_t addr) {
    asm volatile("ldmatrix.sync.aligned.m8n8.x4.shared.b16 {%0,%1,%2,%3}, [%4];"
                 : "=r"(r[0]), "=r"(r[1]), "=r"(r[2]), "=r"(r[3]) : "r"(addr));
}
__device__ __forceinline__ void ldsm2(uint32_t* r, uint32_t addr) {
    asm volatile("ldmatrix.sync.aligned.m8n8.x2.shared.b16 {%0,%1}, [%2];"
                 : "=r"(r[0]), "=r"(r[1]) : "r"(addr));
}

// ================== weight transpose+split (row = n*mul + add) ==================
__global__ void wconv_kernel(const float* __restrict__ W,
                             __nv_bfloat16* __restrict__ th,
                             __nv_bfloat16* __restrict__ tl,
                             int K, int N, int mul, int add) {
    __shared__ float t[32][33];
    int nt = blockIdx.x * 32, kt = blockIdx.y * 32;
    int tx = threadIdx.x & 31, ty = threadIdx.x >> 5;
    for (int r = ty; r < 32; r += 8)
        t[r][tx] = W[(long)(kt + r) * N + nt + tx];
    __syncthreads();
    for (int r = ty; r < 32; r += 8) {
        float v = t[tx][r];
        __nv_bfloat16 h, l;
        hilo1(v, h, l);
        long o = ((long)(nt + r) * mul + add) * K + kt + tx;
        th[o] = h;
        tl[o] = l;
    }
}

// ================== epilogue dispatch ==================
// EPI: 0=store, 1=accumulate, 2=qkv split, 3=swiglu, 4=proj+residual, 5=bf16 out
template<int EPI>
__device__ __forceinline__ void epi_store(
    int row, int col, float x, float y, int ldc,
    float* Cm, __nv_bfloat16* Eh, __nv_bfloat16* El,
    const float* Xaux, float* Faux, const float* Wrow, int eidx)
{
    if (EPI == 0) {
        *reinterpret_cast<float2*>(Cm + (long)row * ldc + col) = make_float2(x, y);
    } else if (EPI == 1) {
        float2* p = reinterpret_cast<float2*>(Cm + (long)row * ldc + col);
        float2 o = *p; o.x += x; o.y += y; *p = o;
    } else if (EPI == 2) {
        int b = row / S, s = row - b * S;
        int which = col / C;
        int hd = col - which * C;
        int h = hd / DH, d = hd - h * DH;
        __nv_bfloat16 xh, xl, yh, yl;
        hilo1(x, xh, xl); hilo1(y, yh, yl);
        if (which == 2) {
            long o = ((long)(b * NH + h) * DH + d) * SP + s;
            g_vth[o] = xh; g_vtl[o] = xl;
            g_vth[o + SP] = yh; g_vtl[o + SP] = yl;
        } else {
            long o = ((long)(b * NH + h) * S + s) * DH + d;
            __nv_bfloat16* H = which ? g_kh : g_qh;
            __nv_bfloat16* L = which ? g_kl : g_ql;
            H[o] = xh; H[o + 1] = yh;
            L[o] = xl; L[o + 1] = yl;
        }
    } else if (EPI == 3) {
        float w = Wrow[row * 3 + eidx];
        float sig = 1.f / (1.f + __expf(-x));
        float v = x * sig * y * w;
        __nv_bfloat16 h, l; hilo1(v, h, l);
        long o = (long)row * HID + (col >> 1);
        Eh[o] = h; El[o] = l;
    } else if (EPI == 4) {
        int b = row / S, s = row - b * S;
        long xo = ((long)b * C + col) * S + s;
        float v0 = x + Xaux[xo];
        float v1 = y + Xaux[xo + S];
        Faux[xo] = v0; Faux[xo + S] = v1;
        *reinterpret_cast<float2*>(Cm + (long)row * ldc + col) = make_float2(v0, v1);
        __nv_bfloat16 h, l;
        hilo1(v0, h, l); Eh[(long)row * ldc + col] = h;     El[(long)row * ldc + col] = l;
        hilo1(v1, h, l); Eh[(long)row * ldc + col + 1] = h; El[(long)row * ldc + col + 1] = l;
    } else {  // 5
        __nv_bfloat16 h, l;
        hilo1(x, h, l); Eh[(long)row * ldc + col] = h;     El[(long)row * ldc + col] = l;
        hilo1(y, h, l); Eh[(long)row * ldc + col + 1] = h; El[(long)row * ldc + col + 1] = l;
    }
}

// ================== 2-stage pipelined HMMA bf16x3 GEMM, ldmatrix fragments ==================
#define LDT 20
#define TSZ (128 * LDT)
#define STAGES 2

__device__ __forceinline__ void load_chunks(
    uint32_t sb32, int stage, int k0, int tid, int m0, int n0, int M, int N,
    int lda, int ldb,
    const __nv_bfloat16* __restrict__ Ah, const __nv_bfloat16* __restrict__ Al,
    const __nv_bfloat16* __restrict__ Bh, const __nv_bfloat16* __restrict__ Bl)
{
#pragma unroll
    for (int j = 0; j < 8; j++) {
        int c = tid + j * 256;
        int mat = c >> 9;          // 0:Ah 1:Al 2:Bh 3:Bl
        int idx = c & 511;
        int row = idx >> 2;
        int seg = idx & 3;
        const __nv_bfloat16* g;
        int vb = 16;
        if (mat < 2) {
            int r = m0 + row;
            if (r >= M) { r = M - 1; vb = 0; }
            g = ((mat == 0) ? Ah : Al) + (long)r * lda;
        } else {
            int r = n0 + row;
            if (r >= N) { r = N - 1; vb = 0; }
            g = ((mat == 2) ? Bh : Bl) + (long)r * ldb;
        }
        g += k0 + seg * 8;
        uint32_t dst = sb32 + (uint32_t)((stage * 4 * TSZ + mat * TSZ + row * LDT + seg * 4) * 4);
        asm volatile("cp.async.ca.shared.global [%0], [%1], 16, %2;"
                     :: "r"(dst), "l"(g), "r"(vb) : "memory");
    }
}

template<int EPI>
__global__ void __launch_bounds__(256, 2)
hmma4_gemm_kernel(const __nv_bfloat16* __restrict__ Ah, const __nv_bfloat16* __restrict__ Al,
                  const __nv_bfloat16* __restrict__ Bh, const __nv_bfloat16* __restrict__ Bl,
                  float* __restrict__ Cm, __nv_bfloat16* __restrict__ Eh, __nv_bfloat16* __restrict__ El,
                  const float* __restrict__ Xaux, float* __restrict__ Faux,
                  const float* __restrict__ Wrow, int eidx,
                  int M, int N, int K, int lda, int ldb, int ldc,
                  long sA1, long sA2, long sB1, long sB2, long sC1, long sC2, int div)
{
    extern __shared__ uint32_t smp[];
    const int tid = threadIdx.x;
    const int lane = tid & 31;
    const int w = tid >> 5;
    const int wm = w & 3;
    const int wn = w >> 2;
    const int gid = lane >> 2;
    const int tig = lane & 3;
    const int m0 = blockIdx.y * 128;
    const int n0 = blockIdx.x * 128;
    uint32_t sb32 = (uint32_t)__cvta_generic_to_shared(smp);

    int z = blockIdx.z;
    int z1 = z / div, z2 = z % div;
    Ah += z1 * sA1 + z2 * sA2;  Al += z1 * sA1 + z2 * sA2;
    Bh += z1 * sB1 + z2 * sB2;  Bl += z1 * sB1 + z2 * sB2;
    Cm += z1 * sC1 + z2 * sC2;
    if (EPI == 5) { Eh += z1 * sC1 + z2 * sC2; El += z1 * sC1 + z2 * sC2; }

    // ldmatrix per-lane row offsets (u32 units within a tile)
    const int la7 = lane & 7;
    const uint32_t a_off = (uint32_t)((wm * 32 + la7 + ((lane >> 3) & 1) * 8) * LDT + (lane >> 4) * 4);
    const uint32_t b_off = (uint32_t)((wn * 64 + la7) * LDT + ((lane >> 3) & 1) * 4);

    float acc[2][8][4];
#pragma unroll
    for (int i = 0; i < 2; i++)
#pragma unroll
        for (int j = 0; j < 8; j++)
#pragma unroll
            for (int q = 0; q < 4; q++) acc[i][j][q] = 0.f;

    const int NKB = K >> 5;

    load_chunks(sb32, 0, 0, tid, m0, n0, M, N, lda, ldb, Ah, Al, Bh, Bl);
    asm volatile("cp.async.commit_group;" ::: "memory");

    for (int kb = 0; kb < NKB; kb++) {
        if (kb + 1 < NKB) {
            load_chunks(sb32, (kb + 1) & 1, (kb + 1) << 5, tid, m0, n0, M, N, lda, ldb, Ah, Al, Bh, Bl);
            asm volatile("cp.async.commit_group;" ::: "memory");
            asm volatile("cp.async.wait_group 1;" ::: "memory");
        } else {
            asm volatile("cp.async.wait_group 0;" ::: "memory");
        }
        __syncthreads();

        const uint32_t stg = sb32 + (uint32_t)((kb & 1) * 4 * TSZ * 4);

#pragma unroll
        for (int k16 = 0; k16 < 2; k16++) {
            const uint32_t kb8 = (uint32_t)(k16 * 8);
            uint32_t ahi[2][4], alo[2][4];
            {
                uint32_t aaddr = stg + (a_off + kb8) * 4;
                ldsm4(ahi[0], aaddr);
                ldsm4(ahi[1], aaddr + 16 * LDT * 4);
                ldsm4(alo[0], aaddr + TSZ * 4);
                ldsm4(alo[1], aaddr + TSZ * 4 + 16 * LDT * 4);
            }
#pragma unroll
            for (int nt = 0; nt < 8; nt++) {
                uint32_t baddr = stg + 2 * TSZ * 4 + (b_off + (uint32_t)(nt * 8 * LDT) + kb8) * 4;
                uint32_t bhi[2], blo[2];
                ldsm2(bhi, baddr);
                ldsm2(blo, baddr + TSZ * 4);
#pragma unroll
                for (int mt = 0; mt < 2; mt++) {
                    mma16816(acc[mt][nt], ahi[mt], bhi);
                    mma16816(acc[mt][nt], ahi[mt], blo);
                    mma16816(acc[mt][nt], alo[mt], bhi);
                }
            }
        }
        __syncthreads();
    }

    // ---- fused epilogue ----
#pragma unroll
    for (int mt = 0; mt < 2; mt++) {
        int row = m0 + wm * 32 + mt * 16 + gid;
#pragma unroll
        for (int nt = 0; nt < 8; nt++) {
            int col = n0 + wn * 64 + nt * 8 + tig * 2;
            if (col >= N) continue;
            if (row < M)
                epi_store<EPI>(row, col, acc[mt][nt][0], acc[mt][nt][1], ldc,
                               Cm, Eh, El, Xaux, Faux, Wrow, eidx);
            if (row + 8 < M)
                epi_store<EPI>(row + 8, col, acc[mt][nt][2], acc[mt][nt][3], ldc,
                               Cm, Eh, El, Xaux, Faux, Wrow, eidx);
        }
    }
}

// ---------------- LayerNorm statistics ----------------
__global__ void stats_kernel(const float* __restrict__ x) {
    int b = blockIdx.x;
    const float* xb = x + (long)b * C * S;
    const int N = C * S;
    float s = 0.f, s2 = 0.f;
    for (int i = threadIdx.x; i < N; i += blockDim.x) {
        float v = xb[i];
        s += v; s2 += v * v;
    }
    __shared__ float sh[256], sh2[256];
    int tid = threadIdx.x;
    sh[tid] = s; sh2[tid] = s2;
    __syncthreads();
    for (int st = 128; st > 0; st >>= 1) {
        if (tid < st) { sh[tid] += sh[tid + st]; sh2[tid] += sh2[tid + st]; }
        __syncthreads();
    }
    if (tid == 0) {
        float m = sh[0] / (float)N;
        g_stats[b * 2 + 0] = m;
        g_stats[b * 2 + 1] = sh2[0] / (float)N - m * m;
    }
}

// ---------------- LN apply + transpose + bf16 split ----------------
__global__ void ln_kernel(const float* __restrict__ x,
                          const float* __restrict__ w,
                          const float* __restrict__ bia) {
    long idx = (long)blockIdx.x * blockDim.x + threadIdx.x;
    if (idx >= (long)BATCH * C * S) return;
    int b   = (int)(idx / ((long)C * S));
    int rem = (int)(idx % ((long)C * S));
    int c = rem / S, s = rem % S;
    float m   = g_stats[b * 2 + 0];
    float var = g_stats[b * 2 + 1];
    float y = (x[idx] - m) * rsqrtf(var + EPS) * w[rem] + bia[rem];
    long t = ((long)b * S + s) * C + c;
    __nv_bfloat16 h, l;
    hilo1(y, h, l);
    g_tok1h[t] = h;
    g_tok1l[t] = l;
}

// ---------------- fused one-pass softmax -> bf16 hi/lo P (padded) ----------------
__global__ void softmax_bf_kernel() {
    long row = blockIdx.x;                    // BH * S rows
    const float* p = g_attn + row * SP;
    __nv_bfloat16* ph = g_ph + row * SP;
    __nv_bfloat16* pl = g_pl + row * SP;
    int tid = threadIdx.x;
    __shared__ float sw[8];

    int i2 = tid + 512;
    float v0 = p[tid];
    float v1 = p[tid + 256];
    float v2 = (i2 < S) ? p[i2] : -1e30f;

    float mx = fmaxf(v0, fmaxf(v1, v2));
#pragma unroll
    for (int o = 16; o > 0; o >>= 1) mx = fmaxf(mx, __shfl_xor_sync(~0u, mx, o));
    if ((tid & 31) == 0) sw[tid >> 5] = mx;
    __syncthreads();
    if (tid < 32) {
        float m = (tid < 8) ? sw[tid] : -1e30f;
#pragma unroll
        for (int o = 4; o > 0; o >>= 1) m = fmaxf(m, __shfl_xor_sync(~0u, m, o));
        if (tid == 0) sw[0] = m;
    }
    __syncthreads();
    mx = sw[0];
    __syncthreads();

    float e0 = __expf(v0 - mx);
    float e1 = __expf(v1 - mx);
    float e2 = (i2 < S) ? __expf(v2 - mx) : 0.f;
    float sum = e0 + e1 + e2;
#pragma unroll
    for (int o = 16; o > 0; o >>= 1) sum += __shfl_xor_sync(~0u, sum, o);
    if ((tid & 31) == 0) sw[tid >> 5] = sum;
    __syncthreads();
    if (tid < 32) {
        float s = (tid < 8) ? sw[tid] : 0.f;
#pragma unroll
        for (int o = 4; o > 0; o >>= 1) s += __shfl_xor_sync(~0u, s, o);
        if (tid == 0) sw[0] = s;
    }
    __syncthreads();
    float inv = 1.f / sw[0];

    __nv_bfloat16 h, l;
    hilo1(e0 * inv, h, l); ph[tid] = h;       pl[tid] = l;
    hilo1(e1 * inv, h, l); ph[tid + 256] = h; pl[tid + 256] = l;
    if (i2 < SP) {
        float v = (i2 < S) ? e2 * inv : 0.f;
        hilo1(v, h, l); ph[i2] = h; pl[i2] = l;
    }
}

// ---------------- router ----------------
__global__ void router_kernel(const float* __restrict__ rw) {
    int t = blockIdx.x * blockDim.y + threadIdx.y;
    if (t >= BS) return;
    const float* tok = g_tok2 + (long)t * C;
    float l0 = 0.f, l1 = 0.f, l2 = 0.f;
    for (int c = threadIdx.x; c < C; c += 32) {
        float v = tok[c];
        l0 += v * rw[c * 3 + 0];
        l1 += v * rw[c * 3 + 1];
        l2 += v * rw[c * 3 + 2];
    }
#pragma unroll
    for (int off = 16; off > 0; off >>= 1) {
        l0 += __shfl_down_sync(0xFFFFFFFFu, l0, off);
        l1 += __shfl_down_sync(0xFFFFFFFFu, l1, off);
        l2 += __shfl_down_sync(0xFFFFFFFFu, l2, off);
    }
    if (threadIdx.x == 0) {
        float mx = fmaxf(l0, fmaxf(l1, l2));
        float e0 = __expf(l0 - mx), e1 = __expf(l1 - mx), e2 = __expf(l2 - mx);
        float tot = e0 + e1 + e2;
        float p[3] = { e0 / tot, e1 / tot, e2 / tot };
        int i1 = 0;
        if (p[1] > p[i1]) i1 = 1;
        if (p[2] > p[i1]) i1 = 2;
        int i2 = -1;
        for (int i = 0; i < 3; i++) {
            if (i == i1) continue;
            if (i2 < 0 || p[i] > p[i2]) i2 = i;
        }
        float den = p[i1] + p[i2];
        float w[3] = { 0.f, 0.f, 0.f };
        w[i1] = p[i1] / den;
        w[i2] = p[i2] / den;
        g_w[t * 3 + 0] = w[0];
        g_w[t * 3 + 1] = w[1];
        g_w[t * 3 + 2] = w[2];
    }
}

// ---------------- out(b,c,s) += acc(b,s,c) ----------------
__global__ void final_kernel(float* __restrict__ out) {
    long idx = (long)blockIdx.x * blockDim.x + threadIdx.x;
    if (idx >= (long)BATCH * C * S) return;
    int b   = (int)(idx / ((long)C * S));
    int rem = (int)(idx % ((long)C * S));
    int c = rem / S, s = rem % S;
    out[idx] += g_acc[((long)b * S + s) * C + c];
}

// ---------------- launcher ----------------
extern "C" void kernel_launch(void* const* d_in, const int* in_sizes, int n_in,
                              void* d_out, int out_size) {
    const float* x        = (const float*)d_in[0];
    const float* ln_w     = (const float*)d_in[1];
    const float* ln_b     = (const float*)d_in[2];
    const float* qkv_w    = (const float*)d_in[3];
    const float* proj_w   = (const float*)d_in[4];
    const float* router_w = (const float*)d_in[5];
    const float* gate_w   = (const float*)d_in[6];
    const float* up_w     = (const float*)d_in[7];
    const float* down_w   = (const float*)d_in[8];
    float* out = (float*)d_out;

    float *p_attn, *p_tok2, *p_acc, *p_gw;
    __nv_bfloat16 *p_t1h, *p_t1l, *p_oh, *p_ol, *p_t2h, *p_t2l, *p_hh, *p_hl, *p_wh, *p_wl;
    __nv_bfloat16 *p_ph, *p_pl, *p_qh, *p_ql, *p_kh, *p_kl, *p_vth, *p_vtl;
    cudaGetSymbolAddress((void**)&p_attn, g_attn);
    cudaGetSymbolAddress((void**)&p_tok2, g_tok2);
    cudaGetSymbolAddress((void**)&p_acc,  g_acc);
    cudaGetSymbolAddress((void**)&p_gw,   g_w);
    cudaGetSymbolAddress((void**)&p_t1h, g_tok1h);
    cudaGetSymbolAddress((void**)&p_t1l, g_tok1l);
    cudaGetSymbolAddress((void**)&p_oh,  g_oh);
    cudaGetSymbolAddress((void**)&p_ol,  g_ol);
    cudaGetSymbolAddress((void**)&p_t2h, g_tok2h);
    cudaGetSymbolAddress((void**)&p_t2l, g_tok2l);
    cudaGetSymbolAddress((void**)&p_hh,  g_hidh);
    cudaGetSymbolAddress((void**)&p_hl,  g_hidl);
    cudaGetSymbolAddress((void**)&p_wh,  g_wth);
    cudaGetSymbolAddress((void**)&p_wl,  g_wtl);
    cudaGetSymbolAddress((void**)&p_ph,  g_ph);
    cudaGetSymbolAddress((void**)&p_pl,  g_pl);
    cudaGetSymbolAddress((void**)&p_qh,  g_qh);
    cudaGetSymbolAddress((void**)&p_ql,  g_ql);
    cudaGetSymbolAddress((void**)&p_kh,  g_kh);
    cudaGetSymbolAddress((void**)&p_kl,  g_kl);
    cudaGetSymbolAddress((void**)&p_vth, g_vth);
    cudaGetSymbolAddress((void**)&p_vtl, g_vtl);

    const int SMEM_GEMM = STAGES * 4 * TSZ * 4;   // 81920 B
    cudaFuncSetAttribute(hmma4_gemm_kernel<0>, cudaFuncAttributeMaxDynamicSharedMemorySize, SMEM_GEMM);
    cudaFuncSetAttribute(hmma4_gemm_kernel<1>, cudaFuncAttributeMaxDynamicSharedMemorySize, SMEM_GEMM);
    cudaFuncSetAttribute(hmma4_gemm_kernel<2>, cudaFuncAttributeMaxDynamicSharedMemorySize, SMEM_GEMM);
    cudaFuncSetAttribute(hmma4_gemm_kernel<3>, cudaFuncAttributeMaxDynamicSharedMemorySize, SMEM_GEMM);
    cudaFuncSetAttribute(hmma4_gemm_kernel<4>, cudaFuncAttributeMaxDynamicSharedMemorySize, SMEM_GEMM);
    cudaFuncSetAttribute(hmma4_gemm_kernel<5>, cudaFuncAttributeMaxDynamicSharedMemorySize, SMEM_GEMM);

    const long n_elem = (long)BATCH * C * S;
    const int MT = (BS + 127) / 128;   // 46 row tiles

    // 1) qkv weight conversion first
    wconv_kernel<<<dim3(3 * C / 32, C / 32), 256>>>(qkv_w,  p_wh + OFF_QKV,  p_wl + OFF_QKV,  C, 3 * C, 1, 0);

    // 2-3) LayerNorm
    stats_kernel<<<BATCH, 256>>>(x);
    ln_kernel<<<(int)((n_elem + 255) / 256), 256>>>(x, ln_w, ln_b);

    // 4) qkv GEMM with fused q/k/v split epilogue
    hmma4_gemm_kernel<2><<<dim3(3 * C / 128, MT, 1), 256, SMEM_GEMM>>>(
        p_t1h, p_t1l, p_wh + OFF_QKV, p_wl + OFF_QKV,
        nullptr, nullptr, nullptr, nullptr, nullptr, nullptr, 0,
        BS, 3 * C, C, C, C, 0, 0, 0, 0, 0, 0, 0, 1);

    // 5) scores: per (b,h) 729x729 = q @ k^T
    hmma4_gemm_kernel<0><<<dim3(6, 6, BH), 256, SMEM_GEMM>>>(
        p_qh, p_ql, p_kh, p_kl,
        p_attn, nullptr, nullptr, nullptr, nullptr, nullptr, 0,
        S, S, DH, DH, DH, SP,
        (long)NH * S * DH, (long)S * DH,
        (long)NH * S * DH, (long)S * DH,
        (long)NH * S * SP, (long)S * SP, NH);

    // 6) softmax -> bf16 hi/lo P
    softmax_bf_kernel<<<BH * S, 256>>>();

    // 7+) remaining weight conversions
    wconv_kernel<<<dim3(C / 32, C / 32), 256>>>(proj_w, p_wh + OFF_PROJ, p_wl + OFF_PROJ, C, C, 1, 0);
    for (int e = 0; e < NEXP; e++) {
        wconv_kernel<<<dim3(HID / 32, C / 32), 256>>>(
            gate_w + (long)e * C * HID, p_wh + OFF_GU + e * WSZ_GU2, p_wl + OFF_GU + e * WSZ_GU2, C, HID, 2, 0);
        wconv_kernel<<<dim3(HID / 32, C / 32), 256>>>(
            up_w + (long)e * C * HID,   p_wh + OFF_GU + e * WSZ_GU2, p_wl + OFF_GU + e * WSZ_GU2, C, HID, 2, 1);
        wconv_kernel<<<dim3(C / 32, HID / 32), 256>>>(
            down_w + (long)e * HID * C, p_wh + OFF_DOWN + e * WSZ_DN, p_wl + OFF_DOWN + e * WSZ_DN, HID, C, 1, 0);
    }

    // PV: per (b,h) 729x96 = P @ V, bf16 hi/lo out
    hmma4_gemm_kernel<5><<<dim3(1, 6, BH), 256, SMEM_GEMM>>>(
        p_ph, p_pl, p_vth, p_vtl,
        nullptr, p_oh, p_ol, nullptr, nullptr, nullptr, 0,
        S, DH, SP, SP, SP, C,
        (long)NH * S * SP, (long)S * SP,
        (long)NH * DH * SP, (long)DH * SP,
        (long)S * C, DH, NH);

    // proj GEMM + fused residual (writes out, tok2 fp32 + hi/lo)
    hmma4_gemm_kernel<4><<<dim3(C / 128, MT, 1), 256, SMEM_GEMM>>>(
        p_oh, p_ol, p_wh + OFF_PROJ, p_wl + OFF_PROJ,
        p_tok2, p_t2h, p_t2l, x, out, nullptr, 0,
        BS, C, C, C, C, C, 0, 0, 0, 0, 0, 0, 1);

    // router
    {
        dim3 blk(32, 8);
        router_kernel<<<(BS + 7) / 8, blk>>>(router_w);
    }

    // MoE experts: fused gate+up GEMM (swiglu epilogue) + down GEMM
    for (int e = 0; e < NEXP; e++) {
        hmma4_gemm_kernel<3><<<dim3(2 * HID / 128, MT, 1), 256, SMEM_GEMM>>>(
            p_t2h, p_t2l, p_wh + OFF_GU + e * WSZ_GU2, p_wl + OFF_GU + e * WSZ_GU2,
            nullptr, p_hh, p_hl, nullptr, nullptr, p_gw, e,
            BS, 2 * HID, C, C, C, 0, 0, 0, 0, 0, 0, 0, 1);

        if (e == 0)
            hmma4_gemm_kernel<0><<<dim3(C / 128, MT, 1), 256, SMEM_GEMM>>>(
                p_hh, p_hl, p_wh + OFF_DOWN + e * WSZ_DN, p_wl + OFF_DOWN + e * WSZ_DN,
                p_acc, nullptr, nullptr, nullptr, nullptr, nullptr, 0,
                BS, C, HID, HID, HID, C, 0, 0, 0, 0, 0, 0, 1);
        else
            hmma4_gemm_kernel<1><<<dim3(C / 128, MT, 1), 256, SMEM_GEMM>>>(
                p_hh, p_hl, p_wh + OFF_DOWN + e * WSZ_DN, p_wl + OFF_DOWN + e * WSZ_DN,
                p_acc, nullptr, nullptr, nullptr, nullptr, nullptr, 0,
                BS, C, HID, HID, HID, C, 0, 0, 0, 0, 0, 0, 1);
    }

    // final add
    final_kernel<<<(int)((n_elem + 255) / 256), 256>>>(out);
}

// round 12
// speedup vs baseline: 2.8775x; 1.0907x over previous
#include <cuda_runtime.h>
#include <cuda_bf16.h>
#include <cstdint>

// ---------------- problem constants ----------------
#define BATCH 8
#define C 768
#define S 729               // 9^3
#define SP 736              // S padded to multiple of 32
#define NH 8
#define DH 96               // C / NH
#define HID 2048
#define NEXP 3
#define BS (BATCH * S)      // 5832 tokens
#define BH (BATCH * NH)     // 64
#define EPS 1e-5f

// weight pool offsets (elements) in transposed (N,K) bf16 hi/lo pools
#define OFF_QKV  0L
#define OFF_PROJ 1769472L
#define OFF_GU   2359296L          // interleaved gate/up, stride 2*C*HID per expert
#define WSZ_GU2  3145728L
#define OFF_DOWN 11796480L
#define WSZ_DN   1572864L
#define WPOOL    16515072L

// ---------------- static device scratch (no allocs allowed) ----------------
__device__ __nv_bfloat16 g_tok1h[(long)BS * C], g_tok1l[(long)BS * C];
__device__ float g_attn[(long)BH * S * SP];               // scores, padded cols
__device__ __nv_bfloat16 g_ph[(long)BH * S * SP], g_pl[(long)BH * S * SP];
__device__ __nv_bfloat16 g_qh[(long)BH * S * DH], g_ql[(long)BH * S * DH];
__device__ __nv_bfloat16 g_kh[(long)BH * S * DH], g_kl[(long)BH * S * DH];
__device__ __nv_bfloat16 g_vth[(long)BH * DH * SP], g_vtl[(long)BH * DH * SP];
__device__ __nv_bfloat16 g_oh[(long)BS * C], g_ol[(long)BS * C];
__device__ float g_tok2[(long)BS * C];
__device__ __nv_bfloat16 g_tok2h[(long)BS * C], g_tok2l[(long)BS * C];
__device__ __nv_bfloat16 g_hidh[(long)BS * HID], g_hidl[(long)BS * HID];
__device__ float g_moe2[(long)BS * 2 * C];                // per-token slot outputs
__device__ float g_w   [(long)BS * NEXP];
__device__ float g_stats[BATCH * 2];
__device__ __nv_bfloat16 g_wth[WPOOL], g_wtl[WPOOL];
// MoE routing lists
__device__ int g_cnt[NEXP];
__device__ int g_tlist[NEXP * BS];                        // encoded t*2 + slot
__device__ __nv_bfloat16 g_agh[(long)BS * C], g_agl[(long)BS * C];  // gathered A

__device__ __forceinline__ void hilo1(float x, __nv_bfloat16& h, __nv_bfloat16& l) {
    h = __float2bfloat16(x);
    l = __float2bfloat16(x - __bfloat162float(h));
}

__device__ __forceinline__ void mma16816(float* c, const uint32_t* a, const uint32_t* b) {
    asm volatile(
        "mma.sync.aligned.m16n8k16.row.col.f32.bf16.bf16.f32 "
        "{%0,%1,%2,%3}, {%4,%5,%6,%7}, {%8,%9}, {%0,%1,%2,%3};"
        : "+f"(c[0]), "+f"(c[1]), "+f"(c[2]), "+f"(c[3])
        : "r"(a[0]), "r"(a[1]), "r"(a[2]), "r"(a[3]), "r"(b[0]), "r"(b[1]));
}

__device__ __forceinline__ void ldsm4(uint32_t* r, uint32_t addr) {
    asm volatile("ldmatrix.sync.aligned.m8n8.x4.shared.b16 {%0,%1,%2,%3}, [%4];"
                 : "=r"(r[0]), "=r"(r[1]), "=r"(r[2]), "=r"(r[3]) : "r"(addr));
}
__device__ __forceinline__ void ldsm2(uint32_t* r, uint32_t addr) {
    asm volatile("ldmatrix.sync.aligned.m8n8.x2.shared.b16 {%0,%1}, [%2];"
                 : "=r"(r[0]), "=r"(r[1]) : "r"(addr));
}

// ================== weight transpose+split (row = n*mul + add) ==================
__global__ void wconv_kernel(const float* __restrict__ W,
                             __nv_bfloat16* __restrict__ th,
                             __nv_bfloat16* __restrict__ tl,
                             int K, int N, int mul, int add) {
    __shared__ float t[32][33];
    int nt = blockIdx.x * 32, kt = blockIdx.y * 32;
    int tx = threadIdx.x & 31, ty = threadIdx.x >> 5;
    for (int r = ty; r < 32; r += 8)
        t[r][tx] = W[(long)(kt + r) * N + nt + tx];
    __syncthreads();
    for (int r = ty; r < 32; r += 8) {
        float v = t[tx][r];
        __nv_bfloat16 h, l;
        hilo1(v, h, l);
        long o = ((long)(nt + r) * mul + add) * K + kt + tx;
        th[o] = h;
        tl[o] = l;
    }
}

// ================== epilogue dispatch ==================
// EPI: 0=store, 2=qkv split, 3=swiglu(list), 4=proj+residual, 5=bf16 out, 6=moe scatter
template<int EPI>
__device__ __forceinline__ void epi_store(
    int row, int col, float x, float y, int ldc,
    float* Cm, __nv_bfloat16* Eh, __nv_bfloat16* El,
    const float* Xaux, float* Faux, const float* Wrow, int eidx, const int* Tl)
{
    if (EPI == 0) {
        *reinterpret_cast<float2*>(Cm + (long)row * ldc + col) = make_float2(x, y);
    } else if (EPI == 2) {
        int b = row / S, s = row - b * S;
        int which = col / C;
        int hd = col - which * C;
        int h = hd / DH, d = hd - h * DH;
        __nv_bfloat16 xh, xl, yh, yl;
        hilo1(x, xh, xl); hilo1(y, yh, yl);
        if (which == 2) {
            long o = ((long)(b * NH + h) * DH + d) * SP + s;
            g_vth[o] = xh; g_vtl[o] = xl;
            g_vth[o + SP] = yh; g_vtl[o + SP] = yl;
        } else {
            long o = ((long)(b * NH + h) * S + s) * DH + d;
            __nv_bfloat16* H = which ? g_kh : g_qh;
            __nv_bfloat16* L = which ? g_kl : g_ql;
            H[o] = xh; H[o + 1] = yh;
            L[o] = xl; L[o + 1] = yl;
        }
    } else if (EPI == 3) {
        int te = Tl[row] >> 1;
        float w = Wrow[te * 3 + eidx];
        float sig = 1.f / (1.f + __expf(-x));
        float v = x * sig * y * w;
        __nv_bfloat16 h, l; hilo1(v, h, l);
        long o = (long)row * HID + (col >> 1);
        Eh[o] = h; El[o] = l;
    } else if (EPI == 4) {
        int b = row / S, s = row - b * S;
        long xo = ((long)b * C + col) * S + s;
        float v0 = x + Xaux[xo];
        float v1 = y + Xaux[xo + S];
        Faux[xo] = v0; Faux[xo + S] = v1;
        *reinterpret_cast<float2*>(Cm + (long)row * ldc + col) = make_float2(v0, v1);
        __nv_bfloat16 h, l;
        hilo1(v0, h, l); Eh[(long)row * ldc + col] = h;     El[(long)row * ldc + col] = l;
        hilo1(v1, h, l); Eh[(long)row * ldc + col + 1] = h; El[(long)row * ldc + col + 1] = l;
    } else if (EPI == 5) {
        __nv_bfloat16 h, l;
        hilo1(x, h, l); Eh[(long)row * ldc + col] = h;     El[(long)row * ldc + col] = l;
        hilo1(y, h, l); Eh[(long)row * ldc + col + 1] = h; El[(long)row * ldc + col + 1] = l;
    } else {  // 6: MoE scatter to slot buffer
        int enc = Tl[row];
        int t = enc >> 1, slot = enc & 1;
        *reinterpret_cast<float2*>(Cm + ((long)t * 2 + slot) * C + col) = make_float2(x, y);
    }
}

// ================== 2-stage pipelined HMMA bf16x3 GEMM, ldmatrix fragments ==================
#define LDT 20
#define TSZ (128 * LDT)
#define STAGES 2

__device__ __forceinline__ void load_chunks(
    uint32_t sb32, int stage, int k0, int tid, int m0, int n0, int M, int N,
    int lda, int ldb,
    const __nv_bfloat16* __restrict__ Ah, const __nv_bfloat16* __restrict__ Al,
    const __nv_bfloat16* __restrict__ Bh, const __nv_bfloat16* __restrict__ Bl)
{
#pragma unroll
    for (int j = 0; j < 8; j++) {
        int c = tid + j * 256;
        int mat = c >> 9;          // 0:Ah 1:Al 2:Bh 3:Bl
        int idx = c & 511;
        int row = idx >> 2;
        int seg = idx & 3;
        const __nv_bfloat16* g;
        int vb = 16;
        if (mat < 2) {
            int r = m0 + row;
            if (r >= M) { r = M - 1; vb = 0; }
            g = ((mat == 0) ? Ah : Al) + (long)r * lda;
        } else {
            int r = n0 + row;
            if (r >= N) { r = N - 1; vb = 0; }
            g = ((mat == 2) ? Bh : Bl) + (long)r * ldb;
        }
        g += k0 + seg * 8;
        uint32_t dst = sb32 + (uint32_t)((stage * 4 * TSZ + mat * TSZ + row * LDT + seg * 4) * 4);
        asm volatile("cp.async.ca.shared.global [%0], [%1], 16, %2;"
                     :: "r"(dst), "l"(g), "r"(vb) : "memory");
    }
}

template<int EPI>
__global__ void __launch_bounds__(256, 2)
hmma4_gemm_kernel(const __nv_bfloat16* __restrict__ Ah, const __nv_bfloat16* __restrict__ Al,
                  const __nv_bfloat16* __restrict__ Bh, const __nv_bfloat16* __restrict__ Bl,
                  float* __restrict__ Cm, __nv_bfloat16* __restrict__ Eh, __nv_bfloat16* __restrict__ El,
                  const float* __restrict__ Xaux, float* __restrict__ Faux,
                  const float* __restrict__ Wrow, int eidx,
                  const int* __restrict__ Mdyn, const int* __restrict__ Tl,
                  int M, int N, int K, int lda, int ldb, int ldc,
                  long sA1, long sA2, long sB1, long sB2, long sC1, long sC2, int div)
{
    extern __shared__ uint32_t smp[];
    if (Mdyn) M = *Mdyn;
    const int m0 = blockIdx.y * 128;
    if (m0 >= M) return;
    const int tid = threadIdx.x;
    const int lane = tid & 31;
    const int w = tid >> 5;
    const int wm = w & 3;
    const int wn = w >> 2;
    const int gid = lane >> 2;
    const int tig = lane & 3;
    const int n0 = blockIdx.x * 128;
    uint32_t sb32 = (uint32_t)__cvta_generic_to_shared(smp);

    int z = blockIdx.z;
    int z1 = z / div, z2 = z % div;
    Ah += z1 * sA1 + z2 * sA2;  Al += z1 * sA1 + z2 * sA2;
    Bh += z1 * sB1 + z2 * sB2;  Bl += z1 * sB1 + z2 * sB2;
    Cm += z1 * sC1 + z2 * sC2;
    if (EPI == 5) { Eh += z1 * sC1 + z2 * sC2; El += z1 * sC1 + z2 * sC2; }

    // ldmatrix per-lane row offsets (u32 units within a tile)
    const int la7 = lane & 7;
    const uint32_t a_off = (uint32_t)((wm * 32 + la7 + ((lane >> 3) & 1) * 8) * LDT + (lane >> 4) * 4);
    const uint32_t b_off = (uint32_t)((wn * 64 + la7) * LDT + ((lane >> 3) & 1) * 4);

    float acc[2][8][4];
#pragma unroll
    for (int i = 0; i < 2; i++)
#pragma unroll
        for (int j = 0; j < 8; j++)
#pragma unroll
            for (int q = 0; q < 4; q++) acc[i][j][q] = 0.f;

    const int NKB = K >> 5;

    load_chunks(sb32, 0, 0, tid, m0, n0, M, N, lda, ldb, Ah, Al, Bh, Bl);
    asm volatile("cp.async.commit_group;" ::: "memory");

    for (int kb = 0; kb < NKB; kb++) {
        if (kb + 1 < NKB) {
            load_chunks(sb32, (kb + 1) & 1, (kb + 1) << 5, tid, m0, n0, M, N, lda, ldb, Ah, Al, Bh, Bl);
            asm volatile("cp.async.commit_group;" ::: "memory");
            asm volatile("cp.async.wait_group 1;" ::: "memory");
        } else {
            asm volatile("cp.async.wait_group 0;" ::: "memory");
        }
        __syncthreads();

        const uint32_t stg = sb32 + (uint32_t)((kb & 1) * 4 * TSZ * 4);

#pragma unroll
        for (int k16 = 0; k16 < 2; k16++) {
            const uint32_t kb8 = (uint32_t)(k16 * 8);
            uint32_t ahi[2][4], alo[2][4];
            {
                uint32_t aaddr = stg + (a_off + kb8) * 4;
                ldsm4(ahi[0], aaddr);
                ldsm4(ahi[1], aaddr + 16 * LDT * 4);
                ldsm4(alo[0], aaddr + TSZ * 4);
                ldsm4(alo[1], aaddr + TSZ * 4 + 16 * LDT * 4);
            }
#pragma unroll
            for (int nt = 0; nt < 8; nt++) {
                uint32_t baddr = stg + 2 * TSZ * 4 + (b_off + (uint32_t)(nt * 8 * LDT) + kb8) * 4;
                uint32_t bhi[2], blo[2];
                ldsm2(bhi, baddr);
                ldsm2(blo, baddr + TSZ * 4);
#pragma unroll
                for (int mt = 0; mt < 2; mt++) {
                    mma16816(acc[mt][nt], ahi[mt], bhi);
                    mma16816(acc[mt][nt], ahi[mt], blo);
                    mma16816(acc[mt][nt], alo[mt], bhi);
                }
            }
        }
        __syncthreads();
    }

    // ---- fused epilogue ----
#pragma unroll
    for (int mt = 0; mt < 2; mt++) {
        int row = m0 + wm * 32 + mt * 16 + gid;
#pragma unroll
        for (int nt = 0; nt < 8; nt++) {
            int col = n0 + wn * 64 + nt * 8 + tig * 2;
            if (col >= N) continue;
            if (row < M)
                epi_store<EPI>(row, col, acc[mt][nt][0], acc[mt][nt][1], ldc,
                               Cm, Eh, El, Xaux, Faux, Wrow, eidx, Tl);
            if (row + 8 < M)
                epi_store<EPI>(row + 8, col, acc[mt][nt][2], acc[mt][nt][3], ldc,
                               Cm, Eh, El, Xaux, Faux, Wrow, eidx, Tl);
        }
    }
}

// ---------------- LayerNorm statistics (also zero MoE counters) ----------------
__global__ void stats_kernel(const float* __restrict__ x) {
    int b = blockIdx.x;
    if (b == 0 && threadIdx.x < NEXP) g_cnt[threadIdx.x] = 0;
    const float* xb = x + (long)b * C * S;
    const int N = C * S;
    float s = 0.f, s2 = 0.f;
    for (int i = threadIdx.x; i < N; i += blockDim.x) {
        float v = xb[i];
        s += v; s2 += v * v;
    }
    __shared__ float sh[256], sh2[256];
    int tid = threadIdx.x;
    sh[tid] = s; sh2[tid] = s2;
    __syncthreads();
    for (int st = 128; st > 0; st >>= 1) {
        if (tid < st) { sh[tid] += sh[tid + st]; sh2[tid] += sh2[tid + st]; }
        __syncthreads();
    }
    if (tid == 0) {
        float m = sh[0] / (float)N;
        g_stats[b * 2 + 0] = m;
        g_stats[b * 2 + 1] = sh2[0] / (float)N - m * m;
    }
}

// ---------------- LN apply + transpose + bf16 split ----------------
__global__ void ln_kernel(const float* __restrict__ x,
                          const float* __restrict__ w,
                          const float* __restrict__ bia) {
    long idx = (long)blockIdx.x * blockDim.x + threadIdx.x;
    if (idx >= (long)BATCH * C * S) return;
    int b   = (int)(idx / ((long)C * S));
    int rem = (int)(idx % ((long)C * S));
    int c = rem / S, s = rem % S;
    float m   = g_stats[b * 2 + 0];
    float var = g_stats[b * 2 + 1];
    float y = (x[idx] - m) * rsqrtf(var + EPS) * w[rem] + bia[rem];
    long t = ((long)b * S + s) * C + c;
    __nv_bfloat16 h, l;
    hilo1(y, h, l);
    g_tok1h[t] = h;
    g_tok1l[t] = l;
}

// ---------------- fused one-pass softmax -> bf16 hi/lo P (padded) ----------------
__global__ void softmax_bf_kernel() {
    long row = blockIdx.x;                    // BH * S rows
    const float* p = g_attn + row * SP;
    __nv_bfloat16* ph = g_ph + row * SP;
    __nv_bfloat16* pl = g_pl + row * SP;
    int tid = threadIdx.x;
    __shared__ float sw[8];

    int i2 = tid + 512;
    float v0 = p[tid];
    float v1 = p[tid + 256];
    float v2 = (i2 < S) ? p[i2] : -1e30f;

    float mx = fmaxf(v0, fmaxf(v1, v2));
#pragma unroll
    for (int o = 16; o > 0; o >>= 1) mx = fmaxf(mx, __shfl_xor_sync(~0u, mx, o));
    if ((tid & 31) == 0) sw[tid >> 5] = mx;
    __syncthreads();
    if (tid < 32) {
        float m = (tid < 8) ? sw[tid] : -1e30f;
#pragma unroll
        for (int o = 4; o > 0; o >>= 1) m = fmaxf(m, __shfl_xor_sync(~0u, m, o));
        if (tid == 0) sw[0] = m;
    }
    __syncthreads();
    mx = sw[0];
    __syncthreads();

    float e0 = __expf(v0 - mx);
    float e1 = __expf(v1 - mx);
    float e2 = (i2 < S) ? __expf(v2 - mx) : 0.f;
    float sum = e0 + e1 + e2;
#pragma unroll
    for (int o = 16; o > 0; o >>= 1) sum += __shfl_xor_sync(~0u, sum, o);
    if ((tid & 31) == 0) sw[tid >> 5] = sum;
    __syncthreads();
    if (tid < 32) {
        float s = (tid < 8) ? sw[tid] : 0.f;
#pragma unroll
        for (int o = 4; o > 0; o >>= 1) s += __shfl_xor_sync(~0u, s, o);
        if (tid == 0) sw[0] = s;
    }
    __syncthreads();
    float inv = 1.f / sw[0];

    __nv_bfloat16 h, l;
    hilo1(e0 * inv, h, l); ph[tid] = h;       pl[tid] = l;
    hilo1(e1 * inv, h, l); ph[tid + 256] = h; pl[tid + 256] = l;
    if (i2 < SP) {
        float v = (i2 < S) ? e2 * inv : 0.f;
        hilo1(v, h, l); ph[i2] = h; pl[i2] = l;
    }
}

// ---------------- router: weights + per-expert token lists ----------------
__global__ void router_kernel(const float* __restrict__ rw) {
    int t = blockIdx.x * blockDim.y + threadIdx.y;
    if (t >= BS) return;
    const float* tok = g_tok2 + (long)t * C;
    float l0 = 0.f, l1 = 0.f, l2 = 0.f;
    for (int c = threadIdx.x; c < C; c += 32) {
        float v = tok[c];
        l0 += v * rw[c * 3 + 0];
        l1 += v * rw[c * 3 + 1];
        l2 += v * rw[c * 3 + 2];
    }
#pragma unroll
    for (int off = 16; off > 0; off >>= 1) {
        l0 += __shfl_down_sync(0xFFFFFFFFu, l0, off);
        l1 += __shfl_down_sync(0xFFFFFFFFu, l1, off);
        l2 += __shfl_down_sync(0xFFFFFFFFu, l2, off);
    }
    if (threadIdx.x == 0) {
        float mx = fmaxf(l0, fmaxf(l1, l2));
        float e0 = __expf(l0 - mx), e1 = __expf(l1 - mx), e2 = __expf(l2 - mx);
        float tot = e0 + e1 + e2;
        float p[3] = { e0 / tot, e1 / tot, e2 / tot };
        int i1 = 0;
        if (p[1] > p[i1]) i1 = 1;
        if (p[2] > p[i1]) i1 = 2;
        int i2 = -1;
        for (int i = 0; i < 3; i++) {
            if (i == i1) continue;
            if (i2 < 0 || p[i] > p[i2]) i2 = i;
        }
        float den = p[i1] + p[i2];
        float w[3] = { 0.f, 0.f, 0.f };
        w[i1] = p[i1] / den;
        w[i2] = p[i2] / den;
        g_w[t * 3 + 0] = w[0];
        g_w[t * 3 + 1] = w[1];
        g_w[t * 3 + 2] = w[2];
        int p1 = atomicAdd(&g_cnt[i1], 1);
        g_tlist[i1 * BS + p1] = t * 2;
        int p2 = atomicAdd(&g_cnt[i2], 1);
        g_tlist[i2 * BS + p2] = t * 2 + 1;
    }
}

// ---------------- gather tok2 hi/lo rows for expert e ----------------
__global__ void gather_kernel(int e) {
    int p = blockIdx.x * 8 + (threadIdx.x >> 5);
    if (p >= g_cnt[e]) return;
    int t = g_tlist[e * BS + p] >> 1;
    int lane = threadIdx.x & 31;
    const uint32_t* sh = reinterpret_cast<const uint32_t*>(g_tok2h + (long)t * C);
    const uint32_t* sl = reinterpret_cast<const uint32_t*>(g_tok2l + (long)t * C);
    uint32_t* dh = reinterpret_cast<uint32_t*>(g_agh + (long)p * C);
    uint32_t* dl = reinterpret_cast<uint32_t*>(g_agl + (long)p * C);
#pragma unroll
    for (int i = 0; i < 12; i++) {
        dh[lane + i * 32] = sh[lane + i * 32];
        dl[lane + i * 32] = sl[lane + i * 32];
    }
}

// ---------------- out(b,c,s) += slot0 + slot1 ----------------
__global__ void final_kernel(float* __restrict__ out) {
    long idx = (long)blockIdx.x * blockDim.x + threadIdx.x;
    if (idx >= (long)BATCH * C * S) return;
    int b   = (int)(idx / ((long)C * S));
    int rem = (int)(idx % ((long)C * S));
    int c = rem / S, s = rem % S;
    long t = (long)b * S + s;
    out[idx] += g_moe2[t * 2 * C + c] + g_moe2[t * 2 * C + C + c];
}

// ---------------- launcher ----------------
extern "C" void kernel_launch(void* const* d_in, const int* in_sizes, int n_in,
                              void* d_out, int out_size) {
    const float* x        = (const float*)d_in[0];
    const float* ln_w     = (const float*)d_in[1];
    const float* ln_b     = (const float*)d_in[2];
    const float* qkv_w    = (const float*)d_in[3];
    const float* proj_w   = (const float*)d_in[4];
    const float* router_w = (const float*)d_in[5];
    const float* gate_w   = (const float*)d_in[6];
    const float* up_w     = (const float*)d_in[7];
    const float* down_w   = (const float*)d_in[8];
    float* out = (float*)d_out;

    float *p_attn, *p_tok2, *p_moe2, *p_gw;
    __nv_bfloat16 *p_t1h, *p_t1l, *p_oh, *p_ol, *p_t2h, *p_t2l, *p_hh, *p_hl, *p_wh, *p_wl;
    __nv_bfloat16 *p_ph, *p_pl, *p_qh, *p_ql, *p_kh, *p_kl, *p_vth, *p_vtl, *p_agh, *p_agl;
    int *p_cnt, *p_tlist;
    cudaGetSymbolAddress((void**)&p_attn, g_attn);
    cudaGetSymbolAddress((void**)&p_tok2, g_tok2);
    cudaGetSymbolAddress((void**)&p_moe2, g_moe2);
    cudaGetSymbolAddress((void**)&p_gw,   g_w);
    cudaGetSymbolAddress((void**)&p_t1h, g_tok1h);
    cudaGetSymbolAddress((void**)&p_t1l, g_tok1l);
    cudaGetSymbolAddress((void**)&p_oh,  g_oh);
    cudaGetSymbolAddress((void**)&p_ol,  g_ol);
    cudaGetSymbolAddress((void**)&p_t2h, g_tok2h);
    cudaGetSymbolAddress((void**)&p_t2l, g_tok2l);
    cudaGetSymbolAddress((void**)&p_hh,  g_hidh);
    cudaGetSymbolAddress((void**)&p_hl,  g_hidl);
    cudaGetSymbolAddress((void**)&p_wh,  g_wth);
    cudaGetSymbolAddress((void**)&p_wl,  g_wtl);
    cudaGetSymbolAddress((void**)&p_ph,  g_ph);
    cudaGetSymbolAddress((void**)&p_pl,  g_pl);
    cudaGetSymbolAddress((void**)&p_qh,  g_qh);
    cudaGetSymbolAddress((void**)&p_ql,  g_ql);
    cudaGetSymbolAddress((void**)&p_kh,  g_kh);
    cudaGetSymbolAddress((void**)&p_kl,  g_kl);
    cudaGetSymbolAddress((void**)&p_vth, g_vth);
    cudaGetSymbolAddress((void**)&p_vtl, g_vtl);
    cudaGetSymbolAddress((void**)&p_agh, g_agh);
    cudaGetSymbolAddress((void**)&p_agl, g_agl);
    cudaGetSymbolAddress((void**)&p_cnt, g_cnt);
    cudaGetSymbolAddress((void**)&p_tlist, g_tlist);

    const int SMEM_GEMM = STAGES * 4 * TSZ * 4;   // 81920 B
    cudaFuncSetAttribute(hmma4_gemm_kernel<0>, cudaFuncAttributeMaxDynamicSharedMemorySize, SMEM_GEMM);
    cudaFuncSetAttribute(hmma4_gemm_kernel<2>, cudaFuncAttributeMaxDynamicSharedMemorySize, SMEM_GEMM);
    cudaFuncSetAttribute(hmma4_gemm_kernel<3>, cudaFuncAttributeMaxDynamicSharedMemorySize, SMEM_GEMM);
    cudaFuncSetAttribute(hmma4_gemm_kernel<4>, cudaFuncAttributeMaxDynamicSharedMemorySize, SMEM_GEMM);
    cudaFuncSetAttribute(hmma4_gemm_kernel<5>, cudaFuncAttributeMaxDynamicSharedMemorySize, SMEM_GEMM);
    cudaFuncSetAttribute(hmma4_gemm_kernel<6>, cudaFuncAttributeMaxDynamicSharedMemorySize, SMEM_GEMM);

    const long n_elem = (long)BATCH * C * S;
    const int MT = (BS + 127) / 128;   // 46 row tiles

    // 1) qkv weight conversion first
    wconv_kernel<<<dim3(3 * C / 32, C / 32), 256>>>(qkv_w,  p_wh + OFF_QKV,  p_wl + OFF_QKV,  C, 3 * C, 1, 0);

    // 2-3) LayerNorm (+ counter reset)
    stats_kernel<<<BATCH, 256>>>(x);
    ln_kernel<<<(int)((n_elem + 255) / 256), 256>>>(x, ln_w, ln_b);

    // 4) qkv GEMM with fused q/k/v split epilogue
    hmma4_gemm_kernel<2><<<dim3(3 * C / 128, MT, 1), 256, SMEM_GEMM>>>(
        p_t1h, p_t1l, p_wh + OFF_QKV, p_wl + OFF_QKV,
        nullptr, nullptr, nullptr, nullptr, nullptr, nullptr, 0, nullptr, nullptr,
        BS, 3 * C, C, C, C, 0, 0, 0, 0, 0, 0, 0, 1);

    // 5) scores: per (b,h) 729x729 = q @ k^T
    hmma4_gemm_kernel<0><<<dim3(6, 6, BH), 256, SMEM_GEMM>>>(
        p_qh, p_ql, p_kh, p_kl,
        p_attn, nullptr, nullptr, nullptr, nullptr, nullptr, 0, nullptr, nullptr,
        S, S, DH, DH, DH, SP,
        (long)NH * S * DH, (long)S * DH,
        (long)NH * S * DH, (long)S * DH,
        (long)NH * S * SP, (long)S * SP, NH);

    // 6) softmax -> bf16 hi/lo P
    softmax_bf_kernel<<<BH * S, 256>>>();

    // 7+) remaining weight conversions
    wconv_kernel<<<dim3(C / 32, C / 32), 256>>>(proj_w, p_wh + OFF_PROJ, p_wl + OFF_PROJ, C, C, 1, 0);
    for (int e = 0; e < NEXP; e++) {
        wconv_kernel<<<dim3(HID / 32, C / 32), 256>>>(
            gate_w + (long)e * C * HID, p_wh + OFF_GU + e * WSZ_GU2, p_wl + OFF_GU + e * WSZ_GU2, C, HID, 2, 0);
        wconv_kernel<<<dim3(HID / 32, C / 32), 256>>>(
            up_w + (long)e * C * HID,   p_wh + OFF_GU + e * WSZ_GU2, p_wl + OFF_GU + e * WSZ_GU2, C, HID, 2, 1);
        wconv_kernel<<<dim3(C / 32, HID / 32), 256>>>(
            down_w + (long)e * HID * C, p_wh + OFF_DOWN + e * WSZ_DN, p_wl + OFF_DOWN + e * WSZ_DN, HID, C, 1, 0);
    }

    // PV: per (b,h) 729x96 = P @ V, bf16 hi/lo out
    hmma4_gemm_kernel<5><<<dim3(1, 6, BH), 256, SMEM_GEMM>>>(
        p_ph, p_pl, p_vth, p_vtl,
        nullptr, p_oh, p_ol, nullptr, nullptr, nullptr, 0, nullptr, nullptr,
        S, DH, SP, SP, SP, C,
        (long)NH * S * SP, (long)S * SP,
        (long)NH * DH * SP, (long)DH * SP,
        (long)S * C, DH, NH);

    // proj GEMM + fused residual (writes out, tok2 fp32 + hi/lo)
    hmma4_gemm_kernel<4><<<dim3(C / 128, MT, 1), 256, SMEM_GEMM>>>(
        p_oh, p_ol, p_wh + OFF_PROJ, p_wl + OFF_PROJ,
        p_tok2, p_t2h, p_t2l, x, out, nullptr, 0, nullptr, nullptr,
        BS, C, C, C, C, C, 0, 0, 0, 0, 0, 0, 1);

    // router (weights + token lists)
    {
        dim3 blk(32, 8);
        router_kernel<<<(BS + 7) / 8, blk>>>(router_w);
    }

    // MoE experts: gather -> fused gate+up GEMM -> down GEMM (scatter)
    for (int e = 0; e < NEXP; e++) {
        gather_kernel<<<(BS + 7) / 8, 256>>>(e);

        hmma4_gemm_kernel<3><<<dim3(2 * HID / 128, MT, 1), 256, SMEM_GEMM>>>(
            p_agh, p_agl, p_wh + OFF_GU + e * WSZ_GU2, p_wl + OFF_GU + e * WSZ_GU2,
            nullptr, p_hh, p_hl, nullptr, nullptr, p_gw, e, p_cnt + e, p_tlist + e * BS,
            BS, 2 * HID, C, C, C, 0, 0, 0, 0, 0, 0, 0, 1);

        hmma4_gemm_kernel<6><<<dim3(C / 128, MT, 1), 256, SMEM_GEMM>>>(
            p_hh, p_hl, p_wh + OFF_DOWN + e * WSZ_DN, p_wl + OFF_DOWN + e * WSZ_DN,
            p_moe2, nullptr, nullptr, nullptr, nullptr, nullptr, 0, p_cnt + e, p_tlist + e * BS,
            BS, C, HID, HID, HID, C, 0, 0, 0, 0, 0, 0, 1);
    }

    // final add
    final_kernel<<<(int)((n_elem + 255) / 256), 256>>>(out);
}

// round 13
// speedup vs baseline: 3.6075x; 1.2537x over previous
#include <cuda_runtime.h>
#include <cuda_fp16.h>
#include <cstdint>

// ---------------- problem constants ----------------
#define BATCH 8
#define C 768
#define S 729               // 9^3
#define SP 736              // S padded to multiple of 32
#define NH 8
#define DH 96               // C / NH
#define HID 2048
#define NEXP 3
#define BS (BATCH * S)      // 5832 tokens
#define BH (BATCH * NH)     // 64
#define EPS 1e-5f

// weight pool offsets (elements) in transposed (N,K) fp16 pool (hi only)
#define OFF_QKV  0L
#define OFF_PROJ 1769472L
#define OFF_GU   2359296L          // interleaved gate/up, stride 2*C*HID per expert
#define WSZ_GU2  3145728L
#define OFF_DOWN 11796480L
#define WSZ_DN   1572864L
#define WPOOL    16515072L

// ---------------- static device scratch (no allocs allowed) ----------------
__device__ __half g_tok1h[(long)BS * C], g_tok1l[(long)BS * C];
__device__ float g_attn[(long)BH * S * SP];               // scores, padded cols
__device__ __half g_ph[(long)BH * S * SP], g_pl[(long)BH * S * SP];
__device__ __half g_qh[(long)BH * S * DH], g_ql[(long)BH * S * DH];
__device__ __half g_kh[(long)BH * S * DH];                // B-side: hi only
__device__ __half g_vth[(long)BH * DH * SP];              // B-side: hi only
__device__ __half g_oh[(long)BS * C], g_ol[(long)BS * C];
__device__ float g_tok2[(long)BS * C];
__device__ __half g_tok2h[(long)BS * C], g_tok2l[(long)BS * C];
__device__ __half g_hidh[(long)BS * HID], g_hidl[(long)BS * HID];
__device__ float g_moe2[(long)BS * 2 * C];                // per-token slot outputs
__device__ float g_w   [(long)BS * NEXP];
__device__ float g_stats[BATCH * 2];
__device__ __half g_wt[WPOOL];                            // weights fp16 (hi only)
// MoE routing lists
__device__ int g_cnt[NEXP];
__device__ int g_tlist[NEXP * BS];                        // encoded t*2 + slot
__device__ __half g_agh[(long)BS * C], g_agl[(long)BS * C];  // gathered A

__device__ __forceinline__ void hilo1(float x, __half& h, __half& l) {
    h = __float2half_rn(x);
    l = __float2half_rn(x - __half2float(h));
}

__device__ __forceinline__ void mma16816(float* c, const uint32_t* a, const uint32_t* b) {
    asm volatile(
        "mma.sync.aligned.m16n8k16.row.col.f32.f16.f16.f32 "
        "{%0,%1,%2,%3}, {%4,%5,%6,%7}, {%8,%9}, {%0,%1,%2,%3};"
        : "+f"(c[0]), "+f"(c[1]), "+f"(c[2]), "+f"(c[3])
        : "r"(a[0]), "r"(a[1]), "r"(a[2]), "r"(a[3]), "r"(b[0]), "r"(b[1]));
}

__device__ __forceinline__ void ldsm4(uint32_t* r, uint32_t addr) {
    asm volatile("ldmatrix.sync.aligned.m8n8.x4.shared.b16 {%0,%1,%2,%3}, [%4];"
                 : "=r"(r[0]), "=r"(r[1]), "=r"(r[2]), "=r"(r[3]) : "r"(addr));
}
__device__ __forceinline__ void ldsm2(uint32_t* r, uint32_t addr) {
    asm volatile("ldmatrix.sync.aligned.m8n8.x2.shared.b16 {%0,%1}, [%2];"
                 : "=r"(r[0]), "=r"(r[1]) : "r"(addr));
}

// ================== weight transpose+convert: W(K,N) fp32 -> Wt(N,K) fp16 ==================
__global__ void wconv_kernel(const float* __restrict__ W,
                             __half* __restrict__ th,
                             int K, int N, int mul, int add) {
    __shared__ float t[32][33];
    int nt = blockIdx.x * 32, kt = blockIdx.y * 32;
    int tx = threadIdx.x & 31, ty = threadIdx.x >> 5;
    for (int r = ty; r < 32; r += 8)
        t[r][tx] = W[(long)(kt + r) * N + nt + tx];
    __syncthreads();
    for (int r = ty; r < 32; r += 8) {
        long o = ((long)(nt + r) * mul + add) * K + kt + tx;
        th[o] = __float2half_rn(t[tx][r]);
    }
}

// ================== epilogue dispatch ==================
// EPI: 0=store, 2=qkv split, 3=swiglu(list), 4=proj+residual, 5=fp16 out, 6=moe scatter
template<int EPI>
__device__ __forceinline__ void epi_store(
    int row, int col, float x, float y, int ldc,
    float* Cm, __half* Eh, __half* El,
    const float* Xaux, float* Faux, const float* Wrow, int eidx, const int* Tl)
{
    if (EPI == 0) {
        *reinterpret_cast<float2*>(Cm + (long)row * ldc + col) = make_float2(x, y);
    } else if (EPI == 2) {
        int b = row / S, s = row - b * S;
        int which = col / C;
        int hd = col - which * C;
        int h = hd / DH, d = hd - h * DH;
        if (which == 2) {
            long o = ((long)(b * NH + h) * DH + d) * SP + s;
            g_vth[o] = __float2half_rn(x);
            g_vth[o + SP] = __float2half_rn(y);
        } else if (which == 1) {
            long o = ((long)(b * NH + h) * S + s) * DH + d;
            g_kh[o] = __float2half_rn(x);
            g_kh[o + 1] = __float2half_rn(y);
        } else {
            long o = ((long)(b * NH + h) * S + s) * DH + d;
            __half xh, xl, yh, yl;
            hilo1(x, xh, xl); hilo1(y, yh, yl);
            g_qh[o] = xh; g_qh[o + 1] = yh;
            g_ql[o] = xl; g_ql[o + 1] = yl;
        }
    } else if (EPI == 3) {
        int te = Tl[row] >> 1;
        float w = Wrow[te * 3 + eidx];
        float sig = 1.f / (1.f + __expf(-x));
        float v = x * sig * y * w;
        __half h, l; hilo1(v, h, l);
        long o = (long)row * HID + (col >> 1);
        Eh[o] = h; El[o] = l;
    } else if (EPI == 4) {
        int b = row / S, s = row - b * S;
        long xo = ((long)b * C + col) * S + s;
        float v0 = x + Xaux[xo];
        float v1 = y + Xaux[xo + S];
        Faux[xo] = v0; Faux[xo + S] = v1;
        *reinterpret_cast<float2*>(Cm + (long)row * ldc + col) = make_float2(v0, v1);
        __half h, l;
        hilo1(v0, h, l); Eh[(long)row * ldc + col] = h;     El[(long)row * ldc + col] = l;
        hilo1(v1, h, l); Eh[(long)row * ldc + col + 1] = h; El[(long)row * ldc + col + 1] = l;
    } else if (EPI == 5) {
        __half h, l;
        hilo1(x, h, l); Eh[(long)row * ldc + col] = h;     El[(long)row * ldc + col] = l;
        hilo1(y, h, l); Eh[(long)row * ldc + col + 1] = h; El[(long)row * ldc + col + 1] = l;
    } else {  // 6: MoE scatter to slot buffer
        int enc = Tl[row];
        int t = enc >> 1, slot = enc & 1;
        *reinterpret_cast<float2*>(Cm + ((long)t * 2 + slot) * C + col) = make_float2(x, y);
    }
}

// ================== 2-stage pipelined HMMA fp16x2 GEMM, ldmatrix fragments ==================
// D = (Ahi + Alo) @ Bhi^T.  3 SMEM tiles per stage (Ah, Al, Bh).
#define LDT 20
#define TSZ (128 * LDT)
#define STAGES 2

__device__ __forceinline__ void load_chunks(
    uint32_t sb32, int stage, int k0, int tid, int m0, int n0, int M, int N,
    int lda, int ldb,
    const __half* __restrict__ Ah, const __half* __restrict__ Al,
    const __half* __restrict__ Bh)
{
#pragma unroll
    for (int j = 0; j < 6; j++) {
        int c = tid + j * 256;
        int mat = c >> 9;          // 0:Ah 1:Al 2:Bh
        int idx = c & 511;
        int row = idx >> 2;
        int seg = idx & 3;
        const __half* g;
        int vb = 16;
        if (mat < 2) {
            int r = m0 + row;
            if (r >= M) { r = M - 1; vb = 0; }
            g = ((mat == 0) ? Ah : Al) + (long)r * lda;
        } else {
            int r = n0 + row;
            if (r >= N) { r = N - 1; vb = 0; }
            g = Bh + (long)r * ldb;
        }
        g += k0 + seg * 8;
        uint32_t dst = sb32 + (uint32_t)((stage * 3 * TSZ + mat * TSZ + row * LDT + seg * 4) * 4);
        asm volatile("cp.async.ca.shared.global [%0], [%1], 16, %2;"
                     :: "r"(dst), "l"(g), "r"(vb) : "memory");
    }
}

template<int EPI>
__global__ void __launch_bounds__(256, 2)
hmma4_gemm_kernel(const __half* __restrict__ Ah, const __half* __restrict__ Al,
                  const __half* __restrict__ Bh,
                  float* __restrict__ Cm, __half* __restrict__ Eh, __half* __restrict__ El,
                  const float* __restrict__ Xaux, float* __restrict__ Faux,
                  const float* __restrict__ Wrow, int eidx,
                  const int* __restrict__ Mdyn, const int* __restrict__ Tl,
                  int M, int N, int K, int lda, int ldb, int ldc,
                  long sA1, long sA2, long sB1, long sB2, long sC1, long sC2, int div)
{
    extern __shared__ uint32_t smp[];
    if (Mdyn) M = *Mdyn;
    const int m0 = blockIdx.y * 128;
    if (m0 >= M) return;
    const int tid = threadIdx.x;
    const int lane = tid & 31;
    const int w = tid >> 5;
    const int wm = w & 3;
    const int wn = w >> 2;
    const int gid = lane >> 2;
    const int tig = lane & 3;
    const int n0 = blockIdx.x * 128;
    uint32_t sb32 = (uint32_t)__cvta_generic_to_shared(smp);

    int z = blockIdx.z;
    int z1 = z / div, z2 = z % div;
    Ah += z1 * sA1 + z2 * sA2;  Al += z1 * sA1 + z2 * sA2;
    Bh += z1 * sB1 + z2 * sB2;
    Cm += z1 * sC1 + z2 * sC2;
    if (EPI == 5) { Eh += z1 * sC1 + z2 * sC2; El += z1 * sC1 + z2 * sC2; }

    // ldmatrix per-lane row offsets (u32 units within a tile)
    const int la7 = lane & 7;
    const uint32_t a_off = (uint32_t)((wm * 32 + la7 + ((lane >> 3) & 1) * 8) * LDT + (lane >> 4) * 4);
    const uint32_t b_off = (uint32_t)((wn * 64 + la7) * LDT + ((lane >> 3) & 1) * 4);

    float acc[2][8][4];
#pragma unroll
    for (int i = 0; i < 2; i++)
#pragma unroll
        for (int j = 0; j < 8; j++)
#pragma unroll
            for (int q = 0; q < 4; q++) acc[i][j][q] = 0.f;

    const int NKB = K >> 5;

    load_chunks(sb32, 0, 0, tid, m0, n0, M, N, lda, ldb, Ah, Al, Bh);
    asm volatile("cp.async.commit_group;" ::: "memory");

    for (int kb = 0; kb < NKB; kb++) {
        if (kb + 1 < NKB) {
            load_chunks(sb32, (kb + 1) & 1, (kb + 1) << 5, tid, m0, n0, M, N, lda, ldb, Ah, Al, Bh);
            asm volatile("cp.async.commit_group;" ::: "memory");
            asm volatile("cp.async.wait_group 1;" ::: "memory");
        } else {
            asm volatile("cp.async.wait_group 0;" ::: "memory");
        }
        __syncthreads();

        const uint32_t stg = sb32 + (uint32_t)((kb & 1) * 3 * TSZ * 4);

#pragma unroll
        for (int k16 = 0; k16 < 2; k16++) {
            const uint32_t kb8 = (uint32_t)(k16 * 8);
            uint32_t ahi[2][4], alo[2][4];
            {
                uint32_t aaddr = stg + (a_off + kb8) * 4;
                ldsm4(ahi[0], aaddr);
                ldsm4(ahi[1], aaddr + 16 * LDT * 4);
                ldsm4(alo[0], aaddr + TSZ * 4);
                ldsm4(alo[1], aaddr + TSZ * 4 + 16 * LDT * 4);
            }
#pragma unroll
            for (int nt = 0; nt < 8; nt++) {
                uint32_t baddr = stg + 2 * TSZ * 4 + (b_off + (uint32_t)(nt * 8 * LDT) + kb8) * 4;
                uint32_t bh[2];
                ldsm2(bh, baddr);
#pragma unroll
                for (int mt = 0; mt < 2; mt++) {
                    mma16816(acc[mt][nt], ahi[mt], bh);
                    mma16816(acc[mt][nt], alo[mt], bh);
                }
            }
        }
        __syncthreads();
    }

    // ---- fused epilogue ----
#pragma unroll
    for (int mt = 0; mt < 2; mt++) {
        int row = m0 + wm * 32 + mt * 16 + gid;
#pragma unroll
        for (int nt = 0; nt < 8; nt++) {
            int col = n0 + wn * 64 + nt * 8 + tig * 2;
            if (col >= N) continue;
            if (row < M)
                epi_store<EPI>(row, col, acc[mt][nt][0], acc[mt][nt][1], ldc,
                               Cm, Eh, El, Xaux, Faux, Wrow, eidx, Tl);
            if (row + 8 < M)
                epi_store<EPI>(row + 8, col, acc[mt][nt][2], acc[mt][nt][3], ldc,
                               Cm, Eh, El, Xaux, Faux, Wrow, eidx, Tl);
        }
    }
}

// ---------------- LayerNorm statistics (also zero MoE counters) ----------------
__global__ void stats_kernel(const float* __restrict__ x) {
    int b = blockIdx.x;
    if (b == 0 && threadIdx.x < NEXP) g_cnt[threadIdx.x] = 0;
    const float* xb = x + (long)b * C * S;
    const int N = C * S;
    float s = 0.f, s2 = 0.f;
    for (int i = threadIdx.x; i < N; i += blockDim.x) {
        float v = xb[i];
        s += v; s2 += v * v;
    }
    __shared__ float sh[256], sh2[256];
    int tid = threadIdx.x;
    sh[tid] = s; sh2[tid] = s2;
    __syncthreads();
    for (int st = 128; st > 0; st >>= 1) {
        if (tid < st) { sh[tid] += sh[tid + st]; sh2[tid] += sh2[tid + st]; }
        __syncthreads();
    }
    if (tid == 0) {
        float m = sh[0] / (float)N;
        g_stats[b * 2 + 0] = m;
        g_stats[b * 2 + 1] = sh2[0] / (float)N - m * m;
    }
}

// ---------------- LN apply + transpose + fp16 split ----------------
__global__ void ln_kernel(const float* __restrict__ x,
                          const float* __restrict__ w,
                          const float* __restrict__ bia) {
    long idx = (long)blockIdx.x * blockDim.x + threadIdx.x;
    if (idx >= (long)BATCH * C * S) return;
    int b   = (int)(idx / ((long)C * S));
    int rem = (int)(idx % ((long)C * S));
    int c = rem / S, s = rem % S;
    float m   = g_stats[b * 2 + 0];
    float var = g_stats[b * 2 + 1];
    float y = (x[idx] - m) * rsqrtf(var + EPS) * w[rem] + bia[rem];
    long t = ((long)b * S + s) * C + c;
    __half h, l;
    hilo1(y, h, l);
    g_tok1h[t] = h;
    g_tok1l[t] = l;
}

// ---------------- fused one-pass softmax -> fp16 hi/lo P (padded) ----------------
__global__ void softmax_bf_kernel() {
    long row = blockIdx.x;                    // BH * S rows
    const float* p = g_attn + row * SP;
    __half* ph = g_ph + row * SP;
    __half* pl = g_pl + row * SP;
    int tid = threadIdx.x;
    __shared__ float sw[8];

    int i2 = tid + 512;
    float v0 = p[tid];
    float v1 = p[tid + 256];
    float v2 = (i2 < S) ? p[i2] : -1e30f;

    float mx = fmaxf(v0, fmaxf(v1, v2));
#pragma unroll
    for (int o = 16; o > 0; o >>= 1) mx = fmaxf(mx, __shfl_xor_sync(~0u, mx, o));
    if ((tid & 31) == 0) sw[tid >> 5] = mx;
    __syncthreads();
    if (tid < 32) {
        float m = (tid < 8) ? sw[tid] : -1e30f;
#pragma unroll
        for (int o = 4; o > 0; o >>= 1) m = fmaxf(m, __shfl_xor_sync(~0u, m, o));
        if (tid == 0) sw[0] = m;
    }
    __syncthreads();
    mx = sw[0];
    __syncthreads();

    float e0 = __expf(v0 - mx);
    float e1 = __expf(v1 - mx);
    float e2 = (i2 < S) ? __expf(v2 - mx) : 0.f;
    float sum = e0 + e1 + e2;
#pragma unroll
    for (int o = 16; o > 0; o >>= 1) sum += __shfl_xor_sync(~0u, sum, o);
    if ((tid & 31) == 0) sw[tid >> 5] = sum;
    __syncthreads();
    if (tid < 32) {
        float s = (tid < 8) ? sw[tid] : 0.f;
#pragma unroll
        for (int o = 4; o > 0; o >>= 1) s += __shfl_xor_sync(~0u, s, o);
        if (tid == 0) sw[0] = s;
    }
    __syncthreads();
    float inv = 1.f / sw[0];

    __half h, l;
    hilo1(e0 * inv, h, l); ph[tid] = h;       pl[tid] = l;
    hilo1(e1 * inv, h, l); ph[tid + 256] = h; pl[tid + 256] = l;
    if (i2 < SP) {
        float v = (i2 < S) ? e2 * inv : 0.f;
        hilo1(v, h, l); ph[i2] = h; pl[i2] = l;
    }
}

// ---------------- router: weights + per-expert token lists ----------------
__global__ void router_kernel(const float* __restrict__ rw) {
    int t = blockIdx.x * blockDim.y + threadIdx.y;
    if (t >= BS) return;
    const float* tok = g_tok2 + (long)t * C;
    float l0 = 0.f, l1 = 0.f, l2 = 0.f;
    for (int c = threadIdx.x; c < C; c += 32) {
        float v = tok[c];
        l0 += v * rw[c * 3 + 0];
        l1 += v * rw[c * 3 + 1];
        l2 += v * rw[c * 3 + 2];
    }
#pragma unroll
    for (int off = 16; off > 0; off >>= 1) {
        l0 += __shfl_down_sync(0xFFFFFFFFu, l0, off);
        l1 += __shfl_down_sync(0xFFFFFFFFu, l1, off);
        l2 += __shfl_down_sync(0xFFFFFFFFu, l2, off);
    }
    if (threadIdx.x == 0) {
        float mx = fmaxf(l0, fmaxf(l1, l2));
        float e0 = __expf(l0 - mx), e1 = __expf(l1 - mx), e2 = __expf(l2 - mx);
        float tot = e0 + e1 + e2;
        float p[3] = { e0 / tot, e1 / tot, e2 / tot };
        int i1 = 0;
        if (p[1] > p[i1]) i1 = 1;
        if (p[2] > p[i1]) i1 = 2;
        int i2 = -1;
        for (int i = 0; i < 3; i++) {
            if (i == i1) continue;
            if (i2 < 0 || p[i] > p[i2]) i2 = i;
        }
        float den = p[i1] + p[i2];
        float w[3] = { 0.f, 0.f, 0.f };
        w[i1] = p[i1] / den;
        w[i2] = p[i2] / den;
        g_w[t * 3 + 0] = w[0];
        g_w[t * 3 + 1] = w[1];
        g_w[t * 3 + 2] = w[2];
        int p1 = atomicAdd(&g_cnt[i1], 1);
        g_tlist[i1 * BS + p1] = t * 2;
        int p2 = atomicAdd(&g_cnt[i2], 1);
        g_tlist[i2 * BS + p2] = t * 2 + 1;
    }
}

// ---------------- gather tok2 hi/lo rows for expert e ----------------
__global__ void gather_kernel(int e) {
    int p = blockIdx.x * 8 + (threadIdx.x >> 5);
    if (p >= g_cnt[e]) return;
    int t = g_tlist[e * BS + p] >> 1;
    int lane = threadIdx.x & 31;
    const uint32_t* sh = reinterpret_cast<const uint32_t*>(g_tok2h + (long)t * C);
    const uint32_t* sl = reinterpret_cast<const uint32_t*>(g_tok2l + (long)t * C);
    uint32_t* dh = reinterpret_cast<uint32_t*>(g_agh + (long)p * C);
    uint32_t* dl = reinterpret_cast<uint32_t*>(g_agl + (long)p * C);
#pragma unroll
    for (int i = 0; i < 12; i++) {
        dh[lane + i * 32] = sh[lane + i * 32];
        dl[lane + i * 32] = sl[lane + i * 32];
    }
}

// ---------------- out(b,c,s) += slot0 + slot1 ----------------
__global__ void final_kernel(float* __restrict__ out) {
    long idx = (long)blockIdx.x * blockDim.x + threadIdx.x;
    if (idx >= (long)BATCH * C * S) return;
    int b   = (int)(idx / ((long)C * S));
    int rem = (int)(idx % ((long)C * S));
    int c = rem / S, s = rem % S;
    long t = (long)b * S + s;
    out[idx] += g_moe2[t * 2 * C + c] + g_moe2[t * 2 * C + C + c];
}

// ---------------- launcher ----------------
extern "C" void kernel_launch(void* const* d_in, const int* in_sizes, int n_in,
                              void* d_out, int out_size) {
    const float* x        = (const float*)d_in[0];
    const float* ln_w     = (const float*)d_in[1];
    const float* ln_b     = (const float*)d_in[2];
    const float* qkv_w    = (const float*)d_in[3];
    const float* proj_w   = (const float*)d_in[4];
    const float* router_w = (const float*)d_in[5];
    const float* gate_w   = (const float*)d_in[6];
    const float* up_w     = (const float*)d_in[7];
    const float* down_w   = (const float*)d_in[8];
    float* out = (float*)d_out;

    float *p_attn, *p_tok2, *p_moe2, *p_gw;
    __half *p_t1h, *p_t1l, *p_oh, *p_ol, *p_t2h, *p_t2l, *p_hh, *p_hl, *p_wt;
    __half *p_ph, *p_pl, *p_qh, *p_ql, *p_kh, *p_vth, *p_agh, *p_agl;
    int *p_cnt, *p_tlist;
    cudaGetSymbolAddress((void**)&p_attn, g_attn);
    cudaGetSymbolAddress((void**)&p_tok2, g_tok2);
    cudaGetSymbolAddress((void**)&p_moe2, g_moe2);
    cudaGetSymbolAddress((void**)&p_gw,   g_w);
    cudaGetSymbolAddress((void**)&p_t1h, g_tok1h);
    cudaGetSymbolAddress((void**)&p_t1l, g_tok1l);
    cudaGetSymbolAddress((void**)&p_oh,  g_oh);
    cudaGetSymbolAddress((void**)&p_ol,  g_ol);
    cudaGetSymbolAddress((void**)&p_t2h, g_tok2h);
    cudaGetSymbolAddress((void**)&p_t2l, g_tok2l);
    cudaGetSymbolAddress((void**)&p_hh,  g_hidh);
    cudaGetSymbolAddress((void**)&p_hl,  g_hidl);
    cudaGetSymbolAddress((void**)&p_wt,  g_wt);
    cudaGetSymbolAddress((void**)&p_ph,  g_ph);
    cudaGetSymbolAddress((void**)&p_pl,  g_pl);
    cudaGetSymbolAddress((void**)&p_qh,  g_qh);
    cudaGetSymbolAddress((void**)&p_ql,  g_ql);
    cudaGetSymbolAddress((void**)&p_kh,  g_kh);
    cudaGetSymbolAddress((void**)&p_vth, g_vth);
    cudaGetSymbolAddress((void**)&p_agh, g_agh);
    cudaGetSymbolAddress((void**)&p_agl, g_agl);
    cudaGetSymbolAddress((void**)&p_cnt, g_cnt);
    cudaGetSymbolAddress((void**)&p_tlist, g_tlist);

    const int SMEM_GEMM = STAGES * 3 * TSZ * 4;   // 61440 B
    cudaFuncSetAttribute(hmma4_gemm_kernel<0>, cudaFuncAttributeMaxDynamicSharedMemorySize, SMEM_GEMM);
    cudaFuncSetAttribute(hmma4_gemm_kernel<2>, cudaFuncAttributeMaxDynamicSharedMemorySize, SMEM_GEMM);
    cudaFuncSetAttribute(hmma4_gemm_kernel<3>, cudaFuncAttributeMaxDynamicSharedMemorySize, SMEM_GEMM);
    cudaFuncSetAttribute(hmma4_gemm_kernel<4>, cudaFuncAttributeMaxDynamicSharedMemorySize, SMEM_GEMM);
    cudaFuncSetAttribute(hmma4_gemm_kernel<5>, cudaFuncAttributeMaxDynamicSharedMemorySize, SMEM_GEMM);
    cudaFuncSetAttribute(hmma4_gemm_kernel<6>, cudaFuncAttributeMaxDynamicSharedMemorySize, SMEM_GEMM);

    const long n_elem = (long)BATCH * C * S;
    const int MT = (BS + 127) / 128;   // 46 row tiles

    // 1) qkv weight conversion first
    wconv_kernel<<<dim3(3 * C / 32, C / 32), 256>>>(qkv_w, p_wt + OFF_QKV, C, 3 * C, 1, 0);

    // 2-3) LayerNorm (+ counter reset)
    stats_kernel<<<BATCH, 256>>>(x);
    ln_kernel<<<(int)((n_elem + 255) / 256), 256>>>(x, ln_w, ln_b);

    // 4) qkv GEMM with fused q/k/v split epilogue
    hmma4_gemm_kernel<2><<<dim3(3 * C / 128, MT, 1), 256, SMEM_GEMM>>>(
        p_t1h, p_t1l, p_wt + OFF_QKV,
        nullptr, nullptr, nullptr, nullptr, nullptr, nullptr, 0, nullptr, nullptr,
        BS, 3 * C, C, C, C, 0, 0, 0, 0, 0, 0, 0, 1);

    // 5) scores: per (b,h) 729x729 = q @ k^T
    hmma4_gemm_kernel<0><<<dim3(6, 6, BH), 256, SMEM_GEMM>>>(
        p_qh, p_ql, p_kh,
        p_attn, nullptr, nullptr, nullptr, nullptr, nullptr, 0, nullptr, nullptr,
        S, S, DH, DH, DH, SP,
        (long)NH * S * DH, (long)S * DH,
        (long)NH * S * DH, (long)S * DH,
        (long)NH * S * SP, (long)S * SP, NH);

    // 6) softmax -> fp16 hi/lo P
    softmax_bf_kernel<<<BH * S, 256>>>();

    // 7+) remaining weight conversions
    wconv_kernel<<<dim3(C / 32, C / 32), 256>>>(proj_w, p_wt + OFF_PROJ, C, C, 1, 0);
    for (int e = 0; e < NEXP; e++) {
        wconv_kernel<<<dim3(HID / 32, C / 32), 256>>>(
            gate_w + (long)e * C * HID, p_wt + OFF_GU + e * WSZ_GU2, C, HID, 2, 0);
        wconv_kernel<<<dim3(HID / 32, C / 32), 256>>>(
            up_w + (long)e * C * HID,   p_wt + OFF_GU + e * WSZ_GU2, C, HID, 2, 1);
        wconv_kernel<<<dim3(C / 32, HID / 32), 256>>>(
            down_w + (long)e * HID * C, p_wt + OFF_DOWN + e * WSZ_DN, HID, C, 1, 0);
    }

    // PV: per (b,h) 729x96 = P @ V, fp16 hi/lo out
    hmma4_gemm_kernel<5><<<dim3(1, 6, BH), 256, SMEM_GEMM>>>(
        p_ph, p_pl, p_vth,
        nullptr, p_oh, p_ol, nullptr, nullptr, nullptr, 0, nullptr, nullptr,
        S, DH, SP, SP, SP, C,
        (long)NH * S * SP, (long)S * SP,
        (long)NH * DH * SP, (long)DH * SP,
        (long)S * C, DH, NH);

    // proj GEMM + fused residual (writes out, tok2 fp32 + hi/lo)
    hmma4_gemm_kernel<4><<<dim3(C / 128, MT, 1), 256, SMEM_GEMM>>>(
        p_oh, p_ol, p_wt + OFF_PROJ,
        p_tok2, p_t2h, p_t2l, x, out, nullptr, 0, nullptr, nullptr,
        BS, C, C, C, C, C, 0, 0, 0, 0, 0, 0, 1);

    // router (weights + token lists)
    {
        dim3 blk(32, 8);
        router_kernel<<<(BS + 7) / 8, blk>>>(router_w);
    }

    // MoE experts: gather -> fused gate+up GEMM -> down GEMM (scatter)
    for (int e = 0; e < NEXP; e++) {
        gather_kernel<<<(BS + 7) / 8, 256>>>(e);

        hmma4_gemm_kernel<3><<<dim3(2 * HID / 128, MT, 1), 256, SMEM_GEMM>>>(
            p_agh, p_agl, p_wt + OFF_GU + e * WSZ_GU2,
            nullptr, p_hh, p_hl, nullptr, nullptr, p_gw, e, p_cnt + e, p_tlist + e * BS,
            BS, 2 * HID, C, C, C, 0, 0, 0, 0, 0, 0, 0, 1);

        hmma4_gemm_kernel<6><<<dim3(C / 128, MT, 1), 256, SMEM_GEMM>>>(
            p_hh, p_hl, p_wt + OFF_DOWN + e * WSZ_DN,
            p_moe2, nullptr, nullptr, nullptr, nullptr, nullptr, 0, p_cnt + e, p_tlist + e * BS,
            BS, C, HID, HID, HID, C, 0, 0, 0, 0, 0, 0, 1);
    }

    // final add
    final_kernel<<<(int)((n_elem + 255) / 256), 256>>>(out);
}

// round 14
// speedup vs baseline: 4.8761x; 1.3517x over previous
#include <cuda_runtime.h>
#include <cuda_fp16.h>
#include <cstdint>

// ---------------- problem constants ----------------
#define BATCH 8
#define C 768
#define S 729               // 9^3
#define SP 736              // S padded to multiple of 32
#define NH 8
#define DH 96               // C / NH
#define HID 2048
#define NEXP 3
#define BS (BATCH * S)      // 5832 tokens
#define BH (BATCH * NH)     // 64
#define EPS 1e-5f

// weight pool offsets (elements) in transposed (N,K) fp16 pool
#define OFF_QKV  0L
#define OFF_PROJ 1769472L
#define OFF_GU   2359296L          // interleaved gate/up, stride 2*C*HID per expert
#define WSZ_GU2  3145728L
#define OFF_DOWN 11796480L
#define WSZ_DN   1572864L
#define WPOOL    16515072L

// ---------------- static device scratch (no allocs allowed) ----------------
__device__ __half g_tok1h[(long)BS * C];
__device__ float g_attn[(long)BH * S * SP];               // scores, padded cols
__device__ __half g_ph[(long)BH * S * SP];
__device__ __half g_qh[(long)BH * S * DH];
__device__ __half g_kh[(long)BH * S * DH];
__device__ __half g_vth[(long)BH * DH * SP];
__device__ __half g_oh[(long)BS * C];
__device__ float g_tok2[(long)BS * C];
__device__ __half g_tok2h[(long)BS * C];
__device__ __half g_hidh[(long)BS * HID];
__device__ float g_moe2[(long)BS * 2 * C];                // per-token slot outputs
__device__ float g_w   [(long)BS * NEXP];
__device__ float g_stats[BATCH * 2];
__device__ __half g_wt[WPOOL];                            // weights fp16
// MoE routing lists
__device__ int g_cnt[NEXP];
__device__ int g_tlist[NEXP * BS];                        // encoded t*2 + slot
__device__ __half g_agh[(long)BS * C];                    // gathered A

__device__ __forceinline__ void mma16816(float* c, const uint32_t* a, const uint32_t* b) {
    asm volatile(
        "mma.sync.aligned.m16n8k16.row.col.f32.f16.f16.f32 "
        "{%0,%1,%2,%3}, {%4,%5,%6,%7}, {%8,%9}, {%0,%1,%2,%3};"
        : "+f"(c[0]), "+f"(c[1]), "+f"(c[2]), "+f"(c[3])
        : "r"(a[0]), "r"(a[1]), "r"(a[2]), "r"(a[3]), "r"(b[0]), "r"(b[1]));
}

__device__ __forceinline__ void ldsm4(uint32_t* r, uint32_t addr) {
    asm volatile("ldmatrix.sync.aligned.m8n8.x4.shared.b16 {%0,%1,%2,%3}, [%4];"
                 : "=r"(r[0]), "=r"(r[1]), "=r"(r[2]), "=r"(r[3]) : "r"(addr));
}
__device__ __forceinline__ void ldsm2(uint32_t* r, uint32_t addr) {
    asm volatile("ldmatrix.sync.aligned.m8n8.x2.shared.b16 {%0,%1}, [%2];"
                 : "=r"(r[0]), "=r"(r[1]) : "r"(addr));
}

// ================== weight transpose+convert: W(K,N) fp32 -> Wt(N,K) fp16 ==================
__global__ void wconv_kernel(const float* __restrict__ W,
                             __half* __restrict__ th,
                             int K, int N, int mul, int add) {
    __shared__ float t[32][33];
    int nt = blockIdx.x * 32, kt = blockIdx.y * 32;
    int tx = threadIdx.x & 31, ty = threadIdx.x >> 5;
    for (int r = ty; r < 32; r += 8)
        t[r][tx] = W[(long)(kt + r) * N + nt + tx];
    __syncthreads();
    for (int r = ty; r < 32; r += 8) {
        long o = ((long)(nt + r) * mul + add) * K + kt + tx;
        th[o] = __float2half_rn(t[tx][r]);
    }
}

// ================== epilogue dispatch ==================
// EPI: 0=store, 2=qkv split, 3=swiglu(list), 4=proj+residual, 5=fp16 out, 6=moe scatter
template<int EPI>
__device__ __forceinline__ void epi_store(
    int row, int col, float x, float y, int ldc,
    float* Cm, __half* Eh,
    const float* Xaux, float* Faux, const float* Wrow, int eidx, const int* Tl)
{
    if (EPI == 0) {
        *reinterpret_cast<float2*>(Cm + (long)row * ldc + col) = make_float2(x, y);
    } else if (EPI == 2) {
        int b = row / S, s = row - b * S;
        int which = col / C;
        int hd = col - which * C;
        int h = hd / DH, d = hd - h * DH;
        if (which == 2) {
            long o = ((long)(b * NH + h) * DH + d) * SP + s;
            g_vth[o] = __float2half_rn(x);
            g_vth[o + SP] = __float2half_rn(y);
        } else {
            long o = ((long)(b * NH + h) * S + s) * DH + d;
            __half* H = which ? g_kh : g_qh;
            H[o] = __float2half_rn(x);
            H[o + 1] = __float2half_rn(y);
        }
    } else if (EPI == 3) {
        int te = Tl[row] >> 1;
        float w = Wrow[te * 3 + eidx];
        float sig = 1.f / (1.f + __expf(-x));
        float v = x * sig * y * w;
        long o = (long)row * HID + (col >> 1);
        Eh[o] = __float2half_rn(v);
    } else if (EPI == 4) {
        int b = row / S, s = row - b * S;
        long xo = ((long)b * C + col) * S + s;
        float v0 = x + Xaux[xo];
        float v1 = y + Xaux[xo + S];
        Faux[xo] = v0; Faux[xo + S] = v1;
        *reinterpret_cast<float2*>(Cm + (long)row * ldc + col) = make_float2(v0, v1);
        Eh[(long)row * ldc + col] = __float2half_rn(v0);
        Eh[(long)row * ldc + col + 1] = __float2half_rn(v1);
    } else if (EPI == 5) {
        Eh[(long)row * ldc + col] = __float2half_rn(x);
        Eh[(long)row * ldc + col + 1] = __float2half_rn(y);
    } else {  // 6: MoE scatter to slot buffer
        int enc = Tl[row];
        int t = enc >> 1, slot = enc & 1;
        *reinterpret_cast<float2*>(Cm + ((long)t * 2 + slot) * C + col) = make_float2(x, y);
    }
}

// ================== 2-stage pipelined HMMA fp16 GEMM, ldmatrix fragments ==================
// D = A @ B^T, both fp16.  2 SMEM tiles per stage (A, B).
#define LDT 20
#define TSZ (128 * LDT)
#define STAGES 2

__device__ __forceinline__ void load_chunks(
    uint32_t sb32, int stage, int k0, int tid, int m0, int n0, int M, int N,
    int lda, int ldb,
    const __half* __restrict__ Ah, const __half* __restrict__ Bh)
{
#pragma unroll
    for (int j = 0; j < 4; j++) {
        int c = tid + j * 256;
        int mat = c >> 9;          // 0:A 1:B
        int idx = c & 511;
        int row = idx >> 2;
        int seg = idx & 3;
        const __half* g;
        int vb = 16;
        if (mat == 0) {
            int r = m0 + row;
            if (r >= M) { r = M - 1; vb = 0; }
            g = Ah + (long)r * lda;
        } else {
            int r = n0 + row;
            if (r >= N) { r = N - 1; vb = 0; }
            g = Bh + (long)r * ldb;
        }
        g += k0 + seg * 8;
        uint32_t dst = sb32 + (uint32_t)((stage * 2 * TSZ + mat * TSZ + row * LDT + seg * 4) * 4);
        asm volatile("cp.async.ca.shared.global [%0], [%1], 16, %2;"
                     :: "r"(dst), "l"(g), "r"(vb) : "memory");
    }
}

template<int EPI>
__global__ void __launch_bounds__(256, 2)
hmma4_gemm_kernel(const __half* __restrict__ Ah, const __half* __restrict__ Bh,
                  float* __restrict__ Cm, __half* __restrict__ Eh,
                  const float* __restrict__ Xaux, float* __restrict__ Faux,
                  const float* __restrict__ Wrow, int eidx,
                  const int* __restrict__ Mdyn, const int* __restrict__ Tl,
                  int M, int N, int K, int lda, int ldb, int ldc,
                  long sA1, long sA2, long sB1, long sB2, long sC1, long sC2, int div)
{
    extern __shared__ uint32_t smp[];
    if (Mdyn) M = *Mdyn;
    const int m0 = blockIdx.y * 128;
    if (m0 >= M) return;
    const int tid = threadIdx.x;
    const int lane = tid & 31;
    const int w = tid >> 5;
    const int wm = w & 3;
    const int wn = w >> 2;
    const int gid = lane >> 2;
    const int tig = lane & 3;
    const int n0 = blockIdx.x * 128;
    uint32_t sb32 = (uint32_t)__cvta_generic_to_shared(smp);

    int z = blockIdx.z;
    int z1 = z / div, z2 = z % div;
    Ah += z1 * sA1 + z2 * sA2;
    Bh += z1 * sB1 + z2 * sB2;
    Cm += z1 * sC1 + z2 * sC2;
    if (EPI == 5) { Eh += z1 * sC1 + z2 * sC2; }

    // ldmatrix per-lane row offsets (u32 units within a tile)
    const int la7 = lane & 7;
    const uint32_t a_off = (uint32_t)((wm * 32 + la7 + ((lane >> 3) & 1) * 8) * LDT + (lane >> 4) * 4);
    const uint32_t b_off = (uint32_t)((wn * 64 + la7) * LDT + ((lane >> 3) & 1) * 4);

    float acc[2][8][4];
#pragma unroll
    for (int i = 0; i < 2; i++)
#pragma unroll
        for (int j = 0; j < 8; j++)
#pragma unroll
            for (int q = 0; q < 4; q++) acc[i][j][q] = 0.f;

    const int NKB = K >> 5;

    load_chunks(sb32, 0, 0, tid, m0, n0, M, N, lda, ldb, Ah, Bh);
    asm volatile("cp.async.commit_group;" ::: "memory");

    for (int kb = 0; kb < NKB; kb++) {
        if (kb + 1 < NKB) {
            load_chunks(sb32, (kb + 1) & 1, (kb + 1) << 5, tid, m0, n0, M, N, lda, ldb, Ah, Bh);
            asm volatile("cp.async.commit_group;" ::: "memory");
            asm volatile("cp.async.wait_group 1;" ::: "memory");
        } else {
            asm volatile("cp.async.wait_group 0;" ::: "memory");
        }
        __syncthreads();

        const uint32_t stg = sb32 + (uint32_t)((kb & 1) * 2 * TSZ * 4);

#pragma unroll
        for (int k16 = 0; k16 < 2; k16++) {
            const uint32_t kb8 = (uint32_t)(k16 * 8);
            uint32_t ahi[2][4];
            {
                uint32_t aaddr = stg + (a_off + kb8) * 4;
                ldsm4(ahi[0], aaddr);
                ldsm4(ahi[1], aaddr + 16 * LDT * 4);
            }
#pragma unroll
            for (int nt = 0; nt < 8; nt++) {
                uint32_t baddr = stg + TSZ * 4 + (b_off + (uint32_t)(nt * 8 * LDT) + kb8) * 4;
                uint32_t bh[2];
                ldsm2(bh, baddr);
#pragma unroll
                for (int mt = 0; mt < 2; mt++)
                    mma16816(acc[mt][nt], ahi[mt], bh);
            }
        }
        __syncthreads();
    }

    // ---- fused epilogue ----
#pragma unroll
    for (int mt = 0; mt < 2; mt++) {
        int row = m0 + wm * 32 + mt * 16 + gid;
#pragma unroll
        for (int nt = 0; nt < 8; nt++) {
            int col = n0 + wn * 64 + nt * 8 + tig * 2;
            if (col >= N) continue;
            if (row < M)
                epi_store<EPI>(row, col, acc[mt][nt][0], acc[mt][nt][1], ldc,
                               Cm, Eh, Xaux, Faux, Wrow, eidx, Tl);
            if (row + 8 < M)
                epi_store<EPI>(row + 8, col, acc[mt][nt][2], acc[mt][nt][3], ldc,
                               Cm, Eh, Xaux, Faux, Wrow, eidx, Tl);
        }
    }
}

// ---------------- LayerNorm statistics (also zero MoE counters) ----------------
__global__ void stats_kernel(const float* __restrict__ x) {
    int b = blockIdx.x;
    if (b == 0 && threadIdx.x < NEXP) g_cnt[threadIdx.x] = 0;
    const float* xb = x + (long)b * C * S;
    const int N = C * S;
    float s = 0.f, s2 = 0.f;
    for (int i = threadIdx.x; i < N; i += blockDim.x) {
        float v = xb[i];
        s += v; s2 += v * v;
    }
    __shared__ float sh[256], sh2[256];
    int tid = threadIdx.x;
    sh[tid] = s; sh2[tid] = s2;
    __syncthreads();
    for (int st = 128; st > 0; st >>= 1) {
        if (tid < st) { sh[tid] += sh[tid + st]; sh2[tid] += sh2[tid + st]; }
        __syncthreads();
    }
    if (tid == 0) {
        float m = sh[0] / (float)N;
        g_stats[b * 2 + 0] = m;
        g_stats[b * 2 + 1] = sh2[0] / (float)N - m * m;
    }
}

// ---------------- LN apply + transpose + fp16 ----------------
__global__ void ln_kernel(const float* __restrict__ x,
                          const float* __restrict__ w,
                          const float* __restrict__ bia) {
    long idx = (long)blockIdx.x * blockDim.x + threadIdx.x;
    if (idx >= (long)BATCH * C * S) return;
    int b   = (int)(idx / ((long)C * S));
    int rem = (int)(idx % ((long)C * S));
    int c = rem / S, s = rem % S;
    float m   = g_stats[b * 2 + 0];
    float var = g_stats[b * 2 + 1];
    float y = (x[idx] - m) * rsqrtf(var + EPS) * w[rem] + bia[rem];
    g_tok1h[((long)b * S + s) * C + c] = __float2half_rn(y);
}

// ---------------- fused one-pass softmax -> fp16 P (padded) ----------------
__global__ void softmax_bf_kernel() {
    long row = blockIdx.x;                    // BH * S rows
    const float* p = g_attn + row * SP;
    __half* ph = g_ph + row * SP;
    int tid = threadIdx.x;
    __shared__ float sw[8];

    int i2 = tid + 512;
    float v0 = p[tid];
    float v1 = p[tid + 256];
    float v2 = (i2 < S) ? p[i2] : -1e30f;

    float mx = fmaxf(v0, fmaxf(v1, v2));
#pragma unroll
    for (int o = 16; o > 0; o >>= 1) mx = fmaxf(mx, __shfl_xor_sync(~0u, mx, o));
    if ((tid & 31) == 0) sw[tid >> 5] = mx;
    __syncthreads();
    if (tid < 32) {
        float m = (tid < 8) ? sw[tid] : -1e30f;
#pragma unroll
        for (int o = 4; o > 0; o >>= 1) m = fmaxf(m, __shfl_xor_sync(~0u, m, o));
        if (tid == 0) sw[0] = m;
    }
    __syncthreads();
    mx = sw[0];
    __syncthreads();

    float e0 = __expf(v0 - mx);
    float e1 = __expf(v1 - mx);
    float e2 = (i2 < S) ? __expf(v2 - mx) : 0.f;
    float sum = e0 + e1 + e2;
#pragma unroll
    for (int o = 16; o > 0; o >>= 1) sum += __shfl_xor_sync(~0u, sum, o);
    if ((tid & 31) == 0) sw[tid >> 5] = sum;
    __syncthreads();
    if (tid < 32) {
        float s = (tid < 8) ? sw[tid] : 0.f;
#pragma unroll
        for (int o = 4; o > 0; o >>= 1) s += __shfl_xor_sync(~0u, s, o);
        if (tid == 0) sw[0] = s;
    }
    __syncthreads();
    float inv = 1.f / sw[0];

    ph[tid]       = __float2half_rn(e0 * inv);
    ph[tid + 256] = __float2half_rn(e1 * inv);
    if (i2 < SP)
        ph[i2] = __float2half_rn((i2 < S) ? e2 * inv : 0.f);
}

// ---------------- router: weights + per-expert token lists ----------------
__global__ void router_kernel(const float* __restrict__ rw) {
    int t = blockIdx.x * blockDim.y + threadIdx.y;
    if (t >= BS) return;
    const float* tok = g_tok2 + (long)t * C;
    float l0 = 0.f, l1 = 0.f, l2 = 0.f;
    for (int c = threadIdx.x; c < C; c += 32) {
        float v = tok[c];
        l0 += v * rw[c * 3 + 0];
        l1 += v * rw[c * 3 + 1];
        l2 += v * rw[c * 3 + 2];
    }
#pragma unroll
    for (int off = 16; off > 0; off >>= 1) {
        l0 += __shfl_down_sync(0xFFFFFFFFu, l0, off);
        l1 += __shfl_down_sync(0xFFFFFFFFu, l1, off);
        l2 += __shfl_down_sync(0xFFFFFFFFu, l2, off);
    }
    if (threadIdx.x == 0) {
        float mx = fmaxf(l0, fmaxf(l1, l2));
        float e0 = __expf(l0 - mx), e1 = __expf(l1 - mx), e2 = __expf(l2 - mx);
        float tot = e0 + e1 + e2;
        float p[3] = { e0 / tot, e1 / tot, e2 / tot };
        int i1 = 0;
        if (p[1] > p[i1]) i1 = 1;
        if (p[2] > p[i1]) i1 = 2;
        int i2 = -1;
        for (int i = 0; i < 3; i++) {
            if (i == i1) continue;
            if (i2 < 0 || p[i] > p[i2]) i2 = i;
        }
        float den = p[i1] + p[i2];
        float w[3] = { 0.f, 0.f, 0.f };
        w[i1] = p[i1] / den;
        w[i2] = p[i2] / den;
        g_w[t * 3 + 0] = w[0];
        g_w[t * 3 + 1] = w[1];
        g_w[t * 3 + 2] = w[2];
        int p1 = atomicAdd(&g_cnt[i1], 1);
        g_tlist[i1 * BS + p1] = t * 2;
        int p2 = atomicAdd(&g_cnt[i2], 1);
        g_tlist[i2 * BS + p2] = t * 2 + 1;
    }
}

// ---------------- gather tok2 fp16 rows for expert e ----------------
__global__ void gather_kernel(int e) {
    int p = blockIdx.x * 8 + (threadIdx.x >> 5);
    if (p >= g_cnt[e]) return;
    int t = g_tlist[e * BS + p] >> 1;
    int lane = threadIdx.x & 31;
    const uint32_t* sh = reinterpret_cast<const uint32_t*>(g_tok2h + (long)t * C);
    uint32_t* dh = reinterpret_cast<uint32_t*>(g_agh + (long)p * C);
#pragma unroll
    for (int i = 0; i < 12; i++)
        dh[lane + i * 32] = sh[lane + i * 32];
}

// ---------------- out(b,c,s) += slot0 + slot1 ----------------
__global__ void final_kernel(float* __restrict__ out) {
    long idx = (long)blockIdx.x * blockDim.x + threadIdx.x;
    if (idx >= (long)BATCH * C * S) return;
    int b   = (int)(idx / ((long)C * S));
    int rem = (int)(idx % ((long)C * S));
    int c = rem / S, s = rem % S;
    long t = (long)b * S + s;
    out[idx] += g_moe2[t * 2 * C + c] + g_moe2[t * 2 * C + C + c];
}

// ---------------- launcher ----------------
extern "C" void kernel_launch(void* const* d_in, const int* in_sizes, int n_in,
                              void* d_out, int out_size) {
    const float* x        = (const float*)d_in[0];
    const float* ln_w     = (const float*)d_in[1];
    const float* ln_b     = (const float*)d_in[2];
    const float* qkv_w    = (const float*)d_in[3];
    const float* proj_w   = (const float*)d_in[4];
    const float* router_w = (const float*)d_in[5];
    const float* gate_w   = (const float*)d_in[6];
    const float* up_w     = (const float*)d_in[7];
    const float* down_w   = (const float*)d_in[8];
    float* out = (float*)d_out;

    float *p_attn, *p_tok2, *p_moe2, *p_gw;
    __half *p_t1h, *p_oh, *p_t2h, *p_hh, *p_wt;
    __half *p_ph, *p_qh, *p_kh, *p_vth, *p_agh;
    int *p_cnt, *p_tlist;
    cudaGetSymbolAddress((void**)&p_attn, g_attn);
    cudaGetSymbolAddress((void**)&p_tok2, g_tok2);
    cudaGetSymbolAddress((void**)&p_moe2, g_moe2);
    cudaGetSymbolAddress((void**)&p_gw,   g_w);
    cudaGetSymbolAddress((void**)&p_t1h, g_tok1h);
    cudaGetSymbolAddress((void**)&p_oh,  g_oh);
    cudaGetSymbolAddress((void**)&p_t2h, g_tok2h);
    cudaGetSymbolAddress((void**)&p_hh,  g_hidh);
    cudaGetSymbolAddress((void**)&p_wt,  g_wt);
    cudaGetSymbolAddress((void**)&p_ph,  g_ph);
    cudaGetSymbolAddress((void**)&p_qh,  g_qh);
    cudaGetSymbolAddress((void**)&p_kh,  g_kh);
    cudaGetSymbolAddress((void**)&p_vth, g_vth);
    cudaGetSymbolAddress((void**)&p_agh, g_agh);
    cudaGetSymbolAddress((void**)&p_cnt, g_cnt);
    cudaGetSymbolAddress((void**)&p_tlist, g_tlist);

    const int SMEM_GEMM = STAGES * 2 * TSZ * 4;   // 40960 B
    cudaFuncSetAttribute(hmma4_gemm_kernel<0>, cudaFuncAttributeMaxDynamicSharedMemorySize, SMEM_GEMM);
    cudaFuncSetAttribute(hmma4_gemm_kernel<2>, cudaFuncAttributeMaxDynamicSharedMemorySize, SMEM_GEMM);
    cudaFuncSetAttribute(hmma4_gemm_kernel<3>, cudaFuncAttributeMaxDynamicSharedMemorySize, SMEM_GEMM);
    cudaFuncSetAttribute(hmma4_gemm_kernel<4>, cudaFuncAttributeMaxDynamicSharedMemorySize, SMEM_GEMM);
    cudaFuncSetAttribute(hmma4_gemm_kernel<5>, cudaFuncAttributeMaxDynamicSharedMemorySize, SMEM_GEMM);
    cudaFuncSetAttribute(hmma4_gemm_kernel<6>, cudaFuncAttributeMaxDynamicSharedMemorySize, SMEM_GEMM);

    const long n_elem = (long)BATCH * C * S;
    const int MT = (BS + 127) / 128;   // 46 row tiles

    // 1) qkv weight conversion first
    wconv_kernel<<<dim3(3 * C / 32, C / 32), 256>>>(qkv_w, p_wt + OFF_QKV, C, 3 * C, 1, 0);

    // 2-3) LayerNorm (+ counter reset)
    stats_kernel<<<BATCH, 256>>>(x);
    ln_kernel<<<(int)((n_elem + 255) / 256), 256>>>(x, ln_w, ln_b);

    // 4) qkv GEMM with fused q/k/v split epilogue
    hmma4_gemm_kernel<2><<<dim3(3 * C / 128, MT, 1), 256, SMEM_GEMM>>>(
        p_t1h, p_wt + OFF_QKV,
        nullptr, nullptr, nullptr, nullptr, nullptr, 0, nullptr, nullptr,
        BS, 3 * C, C, C, C, 0, 0, 0, 0, 0, 0, 0, 1);

    // 5) scores: per (b,h) 729x729 = q @ k^T
    hmma4_gemm_kernel<0><<<dim3(6, 6, BH), 256, SMEM_GEMM>>>(
        p_qh, p_kh,
        p_attn, nullptr, nullptr, nullptr, nullptr, 0, nullptr, nullptr,
        S, S, DH, DH, DH, SP,
        (long)NH * S * DH, (long)S * DH,
        (long)NH * S * DH, (long)S * DH,
        (long)NH * S * SP, (long)S * SP, NH);

    // 6) softmax -> fp16 P
    softmax_bf_kernel<<<BH * S, 256>>>();

    // 7+) remaining weight conversions
    wconv_kernel<<<dim3(C / 32, C / 32), 256>>>(proj_w, p_wt + OFF_PROJ, C, C, 1, 0);
    for (int e = 0; e < NEXP; e++) {
        wconv_kernel<<<dim3(HID / 32, C / 32), 256>>>(
            gate_w + (long)e * C * HID, p_wt + OFF_GU + e * WSZ_GU2, C, HID, 2, 0);
        wconv_kernel<<<dim3(HID / 32, C / 32), 256>>>(
            up_w + (long)e * C * HID,   p_wt + OFF_GU + e * WSZ_GU2, C, HID, 2, 1);
        wconv_kernel<<<dim3(C / 32, HID / 32), 256>>>(
            down_w + (long)e * HID * C, p_wt + OFF_DOWN + e * WSZ_DN, HID, C, 1, 0);
    }

    // PV: per (b,h) 729x96 = P @ V, fp16 out
    hmma4_gemm_kernel<5><<<dim3(1, 6, BH), 256, SMEM_GEMM>>>(
        p_ph, p_vth,
        nullptr, p_oh, nullptr, nullptr, nullptr, 0, nullptr, nullptr,
        S, DH, SP, SP, SP, C,
        (long)NH * S * SP, (long)S * SP,
        (long)NH * DH * SP, (long)DH * SP,
        (long)S * C, DH, NH);

    // proj GEMM + fused residual (writes out, tok2 fp32 + fp16)
    hmma4_gemm_kernel<4><<<dim3(C / 128, MT, 1), 256, SMEM_GEMM>>>(
        p_oh, p_wt + OFF_PROJ,
        p_tok2, p_t2h, x, out, nullptr, 0, nullptr, nullptr,
        BS, C, C, C, C, C, 0, 0, 0, 0, 0, 0, 1);

    // router (weights + token lists)
    {
        dim3 blk(32, 8);
        router_kernel<<<(BS + 7) / 8, blk>>>(router_w);
    }

    // MoE experts: gather -> fused gate+up GEMM -> down GEMM (scatter)
    for (int e = 0; e < NEXP; e++) {
        gather_kernel<<<(BS + 7) / 8, 256>>>(e);

        hmma4_gemm_kernel<3><<<dim3(2 * HID / 128, MT, 1), 256, SMEM_GEMM>>>(
            p_agh, p_wt + OFF_GU + e * WSZ_GU2,
            nullptr, p_hh, nullptr, nullptr, p_gw, e, p_cnt + e, p_tlist + e * BS,
            BS, 2 * HID, C, C, C, 0, 0, 0, 0, 0, 0, 0, 1);

        hmma4_gemm_kernel<6><<<dim3(C / 128, MT, 1), 256, SMEM_GEMM>>>(
            p_hh, p_wt + OFF_DOWN + e * WSZ_DN,
            p_moe2, nullptr, nullptr, nullptr, nullptr, 0, p_cnt + e, p_tlist + e * BS,
            BS, C, HID, HID, HID, C, 0, 0, 0, 0, 0, 0, 1);
    }

    // final add
    final_kernel<<<(int)((n_elem + 255) / 256), 256>>>(out);
}

// round 15
// speedup vs baseline: 4.8924x; 1.0033x over previous
#include <cuda_runtime.h>
#include <cuda_fp16.h>
#include <cstdint>

// ---------------- problem constants ----------------
#define BATCH 8
#define C 768
#define S 729               // 9^3
#define SP 736              // S padded to multiple of 32
#define NH 8
#define DH 96               // C / NH
#define HID 2048
#define NEXP 3
#define BS (BATCH * S)      // 5832 tokens
#define BH (BATCH * NH)     // 64
#define EPS 1e-5f

// weight pool offsets (elements) in transposed (N,K) fp16 pool
#define OFF_QKV  0L
#define OFF_PROJ 1769472L
#define OFF_GU   2359296L          // interleaved gate/up, stride 2*C*HID per expert
#define WSZ_GU2  3145728L
#define OFF_DOWN 11796480L
#define WSZ_DN   1572864L
#define WPOOL    16515072L

// ---------------- static device scratch (no allocs allowed) ----------------
__device__ __half g_tok1h[(long)BS * C];
__device__ float g_attn[(long)BH * S * SP];               // scores, padded cols
__device__ __half g_ph[(long)BH * S * SP];
__device__ __half g_qh[(long)BH * S * DH];
__device__ __half g_kh[(long)BH * S * DH];
__device__ __half g_vth[(long)BH * DH * SP];
__device__ __half g_oh[(long)BS * C];
__device__ float g_tok2[(long)BS * C];
__device__ __half g_tok2h[(long)BS * C];
__device__ __half g_hidh[(long)BS * HID];
__device__ float g_moe2[(long)BS * 2 * C];                // per-token slot outputs
__device__ float g_w   [(long)BS * NEXP];
__device__ float g_stats[BATCH * 2];
__device__ __half g_wt[WPOOL];                            // weights fp16
// MoE routing lists
__device__ int g_cnt[NEXP];
__device__ int g_tlist[NEXP * BS];                        // encoded t*2 + slot
__device__ __half g_agh[(long)BS * C];                    // gathered A

__device__ __forceinline__ void mma16816(float* c, const uint32_t* a, const uint32_t* b) {
    asm volatile(
        "mma.sync.aligned.m16n8k16.row.col.f32.f16.f16.f32 "
        "{%0,%1,%2,%3}, {%4,%5,%6,%7}, {%8,%9}, {%0,%1,%2,%3};"
        : "+f"(c[0]), "+f"(c[1]), "+f"(c[2]), "+f"(c[3])
        : "r"(a[0]), "r"(a[1]), "r"(a[2]), "r"(a[3]), "r"(b[0]), "r"(b[1]));
}

__device__ __forceinline__ void ldsm4(uint32_t* r, uint32_t addr) {
    asm volatile("ldmatrix.sync.aligned.m8n8.x4.shared.b16 {%0,%1,%2,%3}, [%4];"
                 : "=r"(r[0]), "=r"(r[1]), "=r"(r[2]), "=r"(r[3]) : "r"(addr));
}
__device__ __forceinline__ void ldsm2(uint32_t* r, uint32_t addr) {
    asm volatile("ldmatrix.sync.aligned.m8n8.x2.shared.b16 {%0,%1}, [%2];"
                 : "=r"(r[0]), "=r"(r[1]) : "r"(addr));
}

// ================== weight transpose+convert: W(K,N) fp32 -> Wt(N,K) fp16 ==================
__global__ void wconv_kernel(const float* __restrict__ W,
                             __half* __restrict__ th,
                             int K, int N, int mul, int add) {
    __shared__ float t[32][33];
    int nt = blockIdx.x * 32, kt = blockIdx.y * 32;
    int tx = threadIdx.x & 31, ty = threadIdx.x >> 5;
    for (int r = ty; r < 32; r += 8)
        t[r][tx] = W[(long)(kt + r) * N + nt + tx];
    __syncthreads();
    for (int r = ty; r < 32; r += 8) {
        long o = ((long)(nt + r) * mul + add) * K + kt + tx;
        th[o] = __float2half_rn(t[tx][r]);
    }
}

// ================== epilogue dispatch ==================
// EPI: 0=store, 2=qkv split, 3=swiglu(list), 4=proj+residual, 5=fp16 out, 6=moe scatter
template<int EPI>
__device__ __forceinline__ void epi_store(
    int row, int col, float x, float y, int ldc,
    float* Cm, __half* Eh,
    const float* Xaux, float* Faux, const float* Wrow, int eidx, const int* Tl)
{
    if (EPI == 0) {
        *reinterpret_cast<float2*>(Cm + (long)row * ldc + col) = make_float2(x, y);
    } else if (EPI == 2) {
        int b = row / S, s = row - b * S;
        int which = col / C;
        int hd = col - which * C;
        int h = hd / DH, d = hd - h * DH;
        if (which == 2) {
            long o = ((long)(b * NH + h) * DH + d) * SP + s;
            g_vth[o] = __float2half_rn(x);
            g_vth[o + SP] = __float2half_rn(y);
        } else {
            long o = ((long)(b * NH + h) * S + s) * DH + d;
            __half* H = which ? g_kh : g_qh;
            H[o] = __float2half_rn(x);
            H[o + 1] = __float2half_rn(y);
        }
    } else if (EPI == 3) {
        int te = Tl[row] >> 1;
        float w = Wrow[te * 3 + eidx];
        float sig = 1.f / (1.f + __expf(-x));
        float v = x * sig * y * w;
        long o = (long)row * HID + (col >> 1);
        Eh[o] = __float2half_rn(v);
    } else if (EPI == 4) {
        int b = row / S, s = row - b * S;
        long xo = ((long)b * C + col) * S + s;
        float v0 = x + Xaux[xo];
        float v1 = y + Xaux[xo + S];
        Faux[xo] = v0; Faux[xo + S] = v1;
        *reinterpret_cast<float2*>(Cm + (long)row * ldc + col) = make_float2(v0, v1);
        Eh[(long)row * ldc + col] = __float2half_rn(v0);
        Eh[(long)row * ldc + col + 1] = __float2half_rn(v1);
    } else if (EPI == 5) {
        Eh[(long)row * ldc + col] = __float2half_rn(x);
        Eh[(long)row * ldc + col + 1] = __float2half_rn(y);
    } else {  // 6: MoE scatter to slot buffer
        int enc = Tl[row];
        int t = enc >> 1, slot = enc & 1;
        *reinterpret_cast<float2*>(Cm + ((long)t * 2 + slot) * C + col) = make_float2(x, y);
    }
}

// ================== 4-stage pipelined HMMA fp16 GEMM, single sync/iter ==================
// D = A @ B^T, both fp16.  2 SMEM tiles per stage (A, B).
#define LDT 20
#define TSZ (128 * LDT)
#define STAGES 4

__device__ __forceinline__ void load_chunks(
    uint32_t sb32, int stage, int k0, int tid, int m0, int n0, int M, int N,
    int lda, int ldb,
    const __half* __restrict__ Ah, const __half* __restrict__ Bh)
{
#pragma unroll
    for (int j = 0; j < 4; j++) {
        int c = tid + j * 256;
        int mat = c >> 9;          // 0:A 1:B
        int idx = c & 511;
        int row = idx >> 2;
        int seg = idx & 3;
        const __half* g;
        int vb = 16;
        if (mat == 0) {
            int r = m0 + row;
            if (r >= M) { r = M - 1; vb = 0; }
            g = Ah + (long)r * lda;
        } else {
            int r = n0 + row;
            if (r >= N) { r = N - 1; vb = 0; }
            g = Bh + (long)r * ldb;
        }
        g += k0 + seg * 8;
        uint32_t dst = sb32 + (uint32_t)((stage * 2 * TSZ + mat * TSZ + row * LDT + seg * 4) * 4);
        asm volatile("cp.async.ca.shared.global [%0], [%1], 16, %2;"
                     :: "r"(dst), "l"(g), "r"(vb) : "memory");
    }
}

template<int EPI>
__global__ void __launch_bounds__(256, 2)
hmma4_gemm_kernel(const __half* __restrict__ Ah, const __half* __restrict__ Bh,
                  float* __restrict__ Cm, __half* __restrict__ Eh,
                  const float* __restrict__ Xaux, float* __restrict__ Faux,
                  const float* __restrict__ Wrow, int eidx,
                  const int* __restrict__ Mdyn, const int* __restrict__ Tl,
                  int M, int N, int K, int lda, int ldb, int ldc,
                  long sA1, long sA2, long sB1, long sB2, long sC1, long sC2, int div)
{
    extern __shared__ uint32_t smp[];
    if (Mdyn) M = *Mdyn;
    const int m0 = blockIdx.y * 128;
    if (m0 >= M) return;
    const int tid = threadIdx.x;
    const int lane = tid & 31;
    const int w = tid >> 5;
    const int wm = w & 3;
    const int wn = w >> 2;
    const int gid = lane >> 2;
    const int tig = lane & 3;
    const int n0 = blockIdx.x * 128;
    uint32_t sb32 = (uint32_t)__cvta_generic_to_shared(smp);

    int z = blockIdx.z;
    int z1 = z / div, z2 = z % div;
    Ah += z1 * sA1 + z2 * sA2;
    Bh += z1 * sB1 + z2 * sB2;
    Cm += z1 * sC1 + z2 * sC2;
    if (EPI == 5) { Eh += z1 * sC1 + z2 * sC2; }

    // ldmatrix per-lane row offsets (u32 units within a tile)
    const int la7 = lane & 7;
    const uint32_t a_off = (uint32_t)((wm * 32 + la7 + ((lane >> 3) & 1) * 8) * LDT + (lane >> 4) * 4);
    const uint32_t b_off = (uint32_t)((wn * 64 + la7) * LDT + ((lane >> 3) & 1) * 4);

    float acc[2][8][4];
#pragma unroll
    for (int i = 0; i < 2; i++)
#pragma unroll
        for (int j = 0; j < 8; j++)
#pragma unroll
            for (int q = 0; q < 4; q++) acc[i][j][q] = 0.f;

    const int NKB = K >> 5;

    // prologue: up to 3 stages in flight
#pragma unroll
    for (int s = 0; s < 3; s++) {
        if (s < NKB) {
            load_chunks(sb32, s, s << 5, tid, m0, n0, M, N, lda, ldb, Ah, Bh);
            asm volatile("cp.async.commit_group;" ::: "memory");
        }
    }

    for (int kb = 0; kb < NKB; kb++) {
        int rem = NKB - 1 - kb;           // loads still pending beyond kb
        if (rem >= 2)      asm volatile("cp.async.wait_group 2;" ::: "memory");
        else if (rem == 1) asm volatile("cp.async.wait_group 1;" ::: "memory");
        else               asm volatile("cp.async.wait_group 0;" ::: "memory");
        __syncthreads();

        if (kb + 3 < NKB) {
            load_chunks(sb32, (kb + 3) & 3, (kb + 3) << 5, tid, m0, n0, M, N, lda, ldb, Ah, Bh);
            asm volatile("cp.async.commit_group;" ::: "memory");
        }

        const uint32_t stg = sb32 + (uint32_t)((kb & 3) * 2 * TSZ * 4);

#pragma unroll
        for (int k16 = 0; k16 < 2; k16++) {
            const uint32_t kb8 = (uint32_t)(k16 * 8);
            uint32_t ahi[2][4];
            {
                uint32_t aaddr = stg + (a_off + kb8) * 4;
                ldsm4(ahi[0], aaddr);
                ldsm4(ahi[1], aaddr + 16 * LDT * 4);
            }
#pragma unroll
            for (int nt = 0; nt < 8; nt++) {
                uint32_t baddr = stg + TSZ * 4 + (b_off + (uint32_t)(nt * 8 * LDT) + kb8) * 4;
                uint32_t bh[2];
                ldsm2(bh, baddr);
#pragma unroll
                for (int mt = 0; mt < 2; mt++)
                    mma16816(acc[mt][nt], ahi[mt], bh);
            }
        }
        // no trailing sync: next iteration's barrier protects stage reuse
    }

    // ---- fused epilogue ----
#pragma unroll
    for (int mt = 0; mt < 2; mt++) {
        int row = m0 + wm * 32 + mt * 16 + gid;
#pragma unroll
        for (int nt = 0; nt < 8; nt++) {
            int col = n0 + wn * 64 + nt * 8 + tig * 2;
            if (col >= N) continue;
            if (row < M)
                epi_store<EPI>(row, col, acc[mt][nt][0], acc[mt][nt][1], ldc,
                               Cm, Eh, Xaux, Faux, Wrow, eidx, Tl);
            if (row + 8 < M)
                epi_store<EPI>(row + 8, col, acc[mt][nt][2], acc[mt][nt][3], ldc,
                               Cm, Eh, Xaux, Faux, Wrow, eidx, Tl);
        }
    }
}

// ---------------- LayerNorm statistics (also zero MoE counters) ----------------
__global__ void stats_kernel(const float* __restrict__ x) {
    int b = blockIdx.x;
    if (b == 0 && threadIdx.x < NEXP) g_cnt[threadIdx.x] = 0;
    const float* xb = x + (long)b * C * S;
    const int N = C * S;
    float s = 0.f, s2 = 0.f;
    for (int i = threadIdx.x; i < N; i += blockDim.x) {
        float v = xb[i];
        s += v; s2 += v * v;
    }
    __shared__ float sh[256], sh2[256];
    int tid = threadIdx.x;
    sh[tid] = s; sh2[tid] = s2;
    __syncthreads();
    for (int st = 128; st > 0; st >>= 1) {
        if (tid < st) { sh[tid] += sh[tid + st]; sh2[tid] += sh2[tid + st]; }
        __syncthreads();
    }
    if (tid == 0) {
        float m = sh[0] / (float)N;
        g_stats[b * 2 + 0] = m;
        g_stats[b * 2 + 1] = sh2[0] / (float)N - m * m;
    }
}

// ---------------- LN apply + transpose + fp16 ----------------
__global__ void ln_kernel(const float* __restrict__ x,
                          const float* __restrict__ w,
                          const float* __restrict__ bia) {
    long idx = (long)blockIdx.x * blockDim.x + threadIdx.x;
    if (idx >= (long)BATCH * C * S) return;
    int b   = (int)(idx / ((long)C * S));
    int rem = (int)(idx % ((long)C * S));
    int c = rem / S, s = rem % S;
    float m   = g_stats[b * 2 + 0];
    float var = g_stats[b * 2 + 1];
    float y = (x[idx] - m) * rsqrtf(var + EPS) * w[rem] + bia[rem];
    g_tok1h[((long)b * S + s) * C + c] = __float2half_rn(y);
}

// ---------------- fused one-pass softmax -> fp16 P (padded) ----------------
__global__ void softmax_bf_kernel() {
    long row = blockIdx.x;                    // BH * S rows
    const float* p = g_attn + row * SP;
    __half* ph = g_ph + row * SP;
    int tid = threadIdx.x;
    __shared__ float sw[8];

    int i2 = tid + 512;
    float v0 = p[tid];
    float v1 = p[tid + 256];
    float v2 = (i2 < S) ? p[i2] : -1e30f;

    float mx = fmaxf(v0, fmaxf(v1, v2));
#pragma unroll
    for (int o = 16; o > 0; o >>= 1) mx = fmaxf(mx, __shfl_xor_sync(~0u, mx, o));
    if ((tid & 31) == 0) sw[tid >> 5] = mx;
    __syncthreads();
    if (tid < 32) {
        float m = (tid < 8) ? sw[tid] : -1e30f;
#pragma unroll
        for (int o = 4; o > 0; o >>= 1) m = fmaxf(m, __shfl_xor_sync(~0u, m, o));
        if (tid == 0) sw[0] = m;
    }
    __syncthreads();
    mx = sw[0];
    __syncthreads();

    float e0 = __expf(v0 - mx);
    float e1 = __expf(v1 - mx);
    float e2 = (i2 < S) ? __expf(v2 - mx) : 0.f;
    float sum = e0 + e1 + e2;
#pragma unroll
    for (int o = 16; o > 0; o >>= 1) sum += __shfl_xor_sync(~0u, sum, o);
    if ((tid & 31) == 0) sw[tid >> 5] = sum;
    __syncthreads();
    if (tid < 32) {
        float s = (tid < 8) ? sw[tid] : 0.f;
#pragma unroll
        for (int o = 4; o > 0; o >>= 1) s += __shfl_xor_sync(~0u, s, o);
        if (tid == 0) sw[0] = s;
    }
    __syncthreads();
    float inv = 1.f / sw[0];

    ph[tid]       = __float2half_rn(e0 * inv);
    ph[tid + 256] = __float2half_rn(e1 * inv);
    if (i2 < SP)
        ph[i2] = __float2half_rn((i2 < S) ? e2 * inv : 0.f);
}

// ---------------- router: weights + per-expert token lists ----------------
__global__ void router_kernel(const float* __restrict__ rw) {
    int t = blockIdx.x * blockDim.y + threadIdx.y;
    if (t >= BS) return;
    const float* tok = g_tok2 + (long)t * C;
    float l0 = 0.f, l1 = 0.f, l2 = 0.f;
    for (int c = threadIdx.x; c < C; c += 32) {
        float v = tok[c];
        l0 += v * rw[c * 3 + 0];
        l1 += v * rw[c * 3 + 1];
        l2 += v * rw[c * 3 + 2];
    }
#pragma unroll
    for (int off = 16; off > 0; off >>= 1) {
        l0 += __shfl_down_sync(0xFFFFFFFFu, l0, off);
        l1 += __shfl_down_sync(0xFFFFFFFFu, l1, off);
        l2 += __shfl_down_sync(0xFFFFFFFFu, l2, off);
    }
    if (threadIdx.x == 0) {
        float mx = fmaxf(l0, fmaxf(l1, l2));
        float e0 = __expf(l0 - mx), e1 = __expf(l1 - mx), e2 = __expf(l2 - mx);
        float tot = e0 + e1 + e2;
        float p[3] = { e0 / tot, e1 / tot, e2 / tot };
        int i1 = 0;
        if (p[1] > p[i1]) i1 = 1;
        if (p[2] > p[i1]) i1 = 2;
        int i2 = -1;
        for (int i = 0; i < 3; i++) {
            if (i == i1) continue;
            if (i2 < 0 || p[i] > p[i2]) i2 = i;
        }
        float den = p[i1] + p[i2];
        float w[3] = { 0.f, 0.f, 0.f };
        w[i1] = p[i1] / den;
        w[i2] = p[i2] / den;
        g_w[t * 3 + 0] = w[0];
        g_w[t * 3 + 1] = w[1];
        g_w[t * 3 + 2] = w[2];
        int p1 = atomicAdd(&g_cnt[i1], 1);
        g_tlist[i1 * BS + p1] = t * 2;
        int p2 = atomicAdd(&g_cnt[i2], 1);
        g_tlist[i2 * BS + p2] = t * 2 + 1;
    }
}

// ---------------- gather tok2 fp16 rows for expert e ----------------
__global__ void gather_kernel(int e) {
    int p = blockIdx.x * 8 + (threadIdx.x >> 5);
    if (p >= g_cnt[e]) return;
    int t = g_tlist[e * BS + p] >> 1;
    int lane = threadIdx.x & 31;
    const uint32_t* sh = reinterpret_cast<const uint32_t*>(g_tok2h + (long)t * C);
    uint32_t* dh = reinterpret_cast<uint32_t*>(g_agh + (long)p * C);
#pragma unroll
    for (int i = 0; i < 12; i++)
        dh[lane + i * 32] = sh[lane + i * 32];
}

// ---------------- out(b,c,s) += slot0 + slot1 ----------------
__global__ void final_kernel(float* __restrict__ out) {
    long idx = (long)blockIdx.x * blockDim.x + threadIdx.x;
    if (idx >= (long)BATCH * C * S) return;
    int b   = (int)(idx / ((long)C * S));
    int rem = (int)(idx % ((long)C * S));
    int c = rem / S, s = rem % S;
    long t = (long)b * S + s;
    out[idx] += g_moe2[t * 2 * C + c] + g_moe2[t * 2 * C + C + c];
}

// ---------------- launcher ----------------
extern "C" void kernel_launch(void* const* d_in, const int* in_sizes, int n_in,
                              void* d_out, int out_size) {
    const float* x        = (const float*)d_in[0];
    const float* ln_w     = (const float*)d_in[1];
    const float* ln_b     = (const float*)d_in[2];
    const float* qkv_w    = (const float*)d_in[3];
    const float* proj_w   = (const float*)d_in[4];
    const float* router_w = (const float*)d_in[5];
    const float* gate_w   = (const float*)d_in[6];
    const float* up_w     = (const float*)d_in[7];
    const float* down_w   = (const float*)d_in[8];
    float* out = (float*)d_out;

    float *p_attn, *p_tok2, *p_moe2, *p_gw;
    __half *p_t1h, *p_oh, *p_t2h, *p_hh, *p_wt;
    __half *p_ph, *p_qh, *p_kh, *p_vth, *p_agh;
    int *p_cnt, *p_tlist;
    cudaGetSymbolAddress((void**)&p_attn, g_attn);
    cudaGetSymbolAddress((void**)&p_tok2, g_tok2);
    cudaGetSymbolAddress((void**)&p_moe2, g_moe2);
    cudaGetSymbolAddress((void**)&p_gw,   g_w);
    cudaGetSymbolAddress((void**)&p_t1h, g_tok1h);
    cudaGetSymbolAddress((void**)&p_oh,  g_oh);
    cudaGetSymbolAddress((void**)&p_t2h, g_tok2h);
    cudaGetSymbolAddress((void**)&p_hh,  g_hidh);
    cudaGetSymbolAddress((void**)&p_wt,  g_wt);
    cudaGetSymbolAddress((void**)&p_ph,  g_ph);
    cudaGetSymbolAddress((void**)&p_qh,  g_qh);
    cudaGetSymbolAddress((void**)&p_kh,  g_kh);
    cudaGetSymbolAddress((void**)&p_vth, g_vth);
    cudaGetSymbolAddress((void**)&p_agh, g_agh);
    cudaGetSymbolAddress((void**)&p_cnt, g_cnt);
    cudaGetSymbolAddress((void**)&p_tlist, g_tlist);

    const int SMEM_GEMM = STAGES * 2 * TSZ * 4;   // 81920 B
    cudaFuncSetAttribute(hmma4_gemm_kernel<0>, cudaFuncAttributeMaxDynamicSharedMemorySize, SMEM_GEMM);
    cudaFuncSetAttribute(hmma4_gemm_kernel<2>, cudaFuncAttributeMaxDynamicSharedMemorySize, SMEM_GEMM);
    cudaFuncSetAttribute(hmma4_gemm_kernel<3>, cudaFuncAttributeMaxDynamicSharedMemorySize, SMEM_GEMM);
    cudaFuncSetAttribute(hmma4_gemm_kernel<4>, cudaFuncAttributeMaxDynamicSharedMemorySize, SMEM_GEMM);
    cudaFuncSetAttribute(hmma4_gemm_kernel<5>, cudaFuncAttributeMaxDynamicSharedMemorySize, SMEM_GEMM);
    cudaFuncSetAttribute(hmma4_gemm_kernel<6>, cudaFuncAttributeMaxDynamicSharedMemorySize, SMEM_GEMM);

    const long n_elem = (long)BATCH * C * S;
    const int MT = (BS + 127) / 128;   // 46 row tiles

    // 1) qkv weight conversion first
    wconv_kernel<<<dim3(3 * C / 32, C / 32), 256>>>(qkv_w, p_wt + OFF_QKV, C, 3 * C, 1, 0);

    // 2-3) LayerNorm (+ counter reset)
    stats_kernel<<<BATCH, 256>>>(x);
    ln_kernel<<<(int)((n_elem + 255) / 256), 256>>>(x, ln_w, ln_b);

    // 4) qkv GEMM with fused q/k/v split epilogue
    hmma4_gemm_kernel<2><<<dim3(3 * C / 128, MT, 1), 256, SMEM_GEMM>>>(
        p_t1h, p_wt + OFF_QKV,
        nullptr, nullptr, nullptr, nullptr, nullptr, 0, nullptr, nullptr,
        BS, 3 * C, C, C, C, 0, 0, 0, 0, 0, 0, 0, 1);

    // 5) scores: per (b,h) 729x729 = q @ k^T
    hmma4_gemm_kernel<0><<<dim3(6, 6, BH), 256, SMEM_GEMM>>>(
        p_qh, p_kh,
        p_attn, nullptr, nullptr, nullptr, nullptr, 0, nullptr, nullptr,
        S, S, DH, DH, DH, SP,
        (long)NH * S * DH, (long)S * DH,
        (long)NH * S * DH, (long)S * DH,
        (long)NH * S * SP, (long)S * SP, NH);

    // 6) softmax -> fp16 P
    softmax_bf_kernel<<<BH * S, 256>>>();

    // 7+) remaining weight conversions
    wconv_kernel<<<dim3(C / 32, C / 32), 256>>>(proj_w, p_wt + OFF_PROJ, C, C, 1, 0);
    for (int e = 0; e < NEXP; e++) {
        wconv_kernel<<<dim3(HID / 32, C / 32), 256>>>(
            gate_w + (long)e * C * HID, p_wt + OFF_GU + e * WSZ_GU2, C, HID, 2, 0);
        wconv_kernel<<<dim3(HID / 32, C / 32), 256>>>(
            up_w + (long)e * C * HID,   p_wt + OFF_GU + e * WSZ_GU2, C, HID, 2, 1);
        wconv_kernel<<<dim3(C / 32, HID / 32), 256>>>(
            down_w + (long)e * HID * C, p_wt + OFF_DOWN + e * WSZ_DN, HID, C, 1, 0);
    }

    // PV: per (b,h) 729x96 = P @ V, fp16 out
    hmma4_gemm_kernel<5><<<dim3(1, 6, BH), 256, SMEM_GEMM>>>(
        p_ph, p_vth,
        nullptr, p_oh, nullptr, nullptr, nullptr, 0, nullptr, nullptr,
        S, DH, SP, SP, SP, C,
        (long)NH * S * SP, (long)S * SP,
        (long)NH * DH * SP, (long)DH * SP,
        (long)S * C, DH, NH);

    // proj GEMM + fused residual (writes out, tok2 fp32 + fp16)
    hmma4_gemm_kernel<4><<<dim3(C / 128, MT, 1), 256, SMEM_GEMM>>>(
        p_oh, p_wt + OFF_PROJ,
        p_tok2, p_t2h, x, out, nullptr, 0, nullptr, nullptr,
        BS, C, C, C, C, C, 0, 0, 0, 0, 0, 0, 1);

    // router (weights + token lists)
    {
        dim3 blk(32, 8);
        router_kernel<<<(BS + 7) / 8, blk>>>(router_w);
    }

    // MoE experts: gather -> fused gate+up GEMM -> down GEMM (scatter)
    for (int e = 0; e < NEXP; e++) {
        gather_kernel<<<(BS + 7) / 8, 256>>>(e);

        hmma4_gemm_kernel<3><<<dim3(2 * HID / 128, MT, 1), 256, SMEM_GEMM>>>(
            p_agh, p_wt + OFF_GU + e * WSZ_GU2,
            nullptr, p_hh, nullptr, nullptr, p_gw, e, p_cnt + e, p_tlist + e * BS,
            BS, 2 * HID, C, C, C, 0, 0, 0, 0, 0, 0, 0, 1);

        hmma4_gemm_kernel<6><<<dim3(C / 128, MT, 1), 256, SMEM_GEMM>>>(
            p_hh, p_wt + OFF_DOWN + e * WSZ_DN,
            p_moe2, nullptr, nullptr, nullptr, nullptr, 0, p_cnt + e, p_tlist + e * BS,
            BS, C, HID, HID, HID, C, 0, 0, 0, 0, 0, 0, 1);
    }

    // final add
    final_kernel<<<(int)((n_elem + 255) / 256), 256>>>(out);
}

// round 16
// speedup vs baseline: 5.6253x; 1.1498x over previous
#include <cuda_runtime.h>
#include <cuda_fp16.h>
#include <cstdint>

// ---------------- problem constants ----------------
#define BATCH 8
#define C 768
#define S 729               // 9^3
#define SP 736              // S padded to multiple of 32
#define NH 8
#define DH 96               // C / NH
#define HID 2048
#define NEXP 3
#define BS (BATCH * S)      // 5832 tokens
#define BH (BATCH * NH)     // 64
#define EPS 1e-5f

// weight pool offsets (elements) in transposed (N,K) fp16 pool
#define OFF_QKV  0L
#define OFF_PROJ 1769472L
#define OFF_GU   2359296L          // interleaved gate/up, stride 2*C*HID per expert
#define WSZ_GU2  3145728L
#define OFF_DOWN 11796480L
#define WSZ_DN   1572864L
#define WPOOL    16515072L

// ---------------- static device scratch (no allocs allowed) ----------------
__device__ __half g_tok1h[(long)BS * C];
__device__ float g_attn[(long)BH * S * SP];               // scores, padded cols
__device__ __half g_ph[(long)BH * S * SP];
__device__ __half g_qh[(long)BH * S * DH];
__device__ __half g_kh[(long)BH * S * DH];
__device__ __half g_vth[(long)BH * DH * SP];
__device__ __half g_oh[(long)BS * C];
__device__ float g_tok2[(long)BS * C];
__device__ __half g_tok2h[(long)BS * C];
__device__ __half g_hid[(long)NEXP * BS * HID];           // per-expert hid
__device__ float g_moe2[(long)BS * 2 * C];                // per-token slot outputs
__device__ float g_w   [(long)BS * NEXP];
__device__ float g_stats[BATCH * 2];
__device__ __half g_wt[WPOOL];                            // weights fp16
// MoE routing lists
__device__ int g_cnt[NEXP];
__device__ int g_tlist[NEXP * BS];                        // encoded t*2 + slot
__device__ __half g_ag[(long)NEXP * BS * C];              // per-expert gathered A

__device__ __forceinline__ void mma16816(float* c, const uint32_t* a, const uint32_t* b) {
    asm volatile(
        "mma.sync.aligned.m16n8k16.row.col.f32.f16.f16.f32 "
        "{%0,%1,%2,%3}, {%4,%5,%6,%7}, {%8,%9}, {%0,%1,%2,%3};"
        : "+f"(c[0]), "+f"(c[1]), "+f"(c[2]), "+f"(c[3])
        : "r"(a[0]), "r"(a[1]), "r"(a[2]), "r"(a[3]), "r"(b[0]), "r"(b[1]));
}

__device__ __forceinline__ void ldsm4(uint32_t* r, uint32_t addr) {
    asm volatile("ldmatrix.sync.aligned.m8n8.x4.shared.b16 {%0,%1,%2,%3}, [%4];"
                 : "=r"(r[0]), "=r"(r[1]), "=r"(r[2]), "=r"(r[3]) : "r"(addr));
}

// ================== weight transpose+convert: W(K,N) fp32 -> Wt(N,K) fp16 ==================
// grid.z selects expert: W += z*wstride, th += z*tstride
__global__ void wconv_kernel(const float* __restrict__ W,
                             __half* __restrict__ th,
                             int K, int N, int mul, int add,
                             long wstride, long tstride) {
    __shared__ float t[32][33];
    W  += (long)blockIdx.z * wstride;
    th += (long)blockIdx.z * tstride;
    int nt = blockIdx.x * 32, kt = blockIdx.y * 32;
    int tx = threadIdx.x & 31, ty = threadIdx.x >> 5;
    for (int r = ty; r < 32; r += 8)
        t[r][tx] = W[(long)(kt + r) * N + nt + tx];
    __syncthreads();
    for (int r = ty; r < 32; r += 8) {
        long o = ((long)(nt + r) * mul + add) * K + kt + tx;
        th[o] = __float2half_rn(t[tx][r]);
    }
}

// ================== epilogue dispatch ==================
// EPI: 0=store, 2=qkv split, 3=swiglu(list), 4=proj+residual, 5=fp16 out, 6=moe scatter
template<int EPI>
__device__ __forceinline__ void epi_store(
    int row, int col, float x, float y, int ldc,
    float* Cm, __half* Eh,
    const float* Xaux, float* Faux, const float* Wrow, int eidx, const int* Tl)
{
    if (EPI == 0) {
        *reinterpret_cast<float2*>(Cm + (long)row * ldc + col) = make_float2(x, y);
    } else if (EPI == 2) {
        int b = row / S, s = row - b * S;
        int which = col / C;
        int hd = col - which * C;
        int h = hd / DH, d = hd - h * DH;
        if (which == 2) {
            long o = ((long)(b * NH + h) * DH + d) * SP + s;
            g_vth[o] = __float2half_rn(x);
            g_vth[o + SP] = __float2half_rn(y);
        } else {
            long o = ((long)(b * NH + h) * S + s) * DH + d;
            __half* H = which ? g_kh : g_qh;
            H[o] = __float2half_rn(x);
            H[o + 1] = __float2half_rn(y);
        }
    } else if (EPI == 3) {
        int te = Tl[row] >> 1;
        float w = Wrow[te * 3 + eidx];
        float sig = 1.f / (1.f + __expf(-x));
        float v = x * sig * y * w;
        long o = (long)row * HID + (col >> 1);
        Eh[o] = __float2half_rn(v);
    } else if (EPI == 4) {
        int b = row / S, s = row - b * S;
        long xo = ((long)b * C + col) * S + s;
        float v0 = x + Xaux[xo];
        float v1 = y + Xaux[xo + S];
        Faux[xo] = v0; Faux[xo + S] = v1;
        *reinterpret_cast<float2*>(Cm + (long)row * ldc + col) = make_float2(v0, v1);
        Eh[(long)row * ldc + col] = __float2half_rn(v0);
        Eh[(long)row * ldc + col + 1] = __float2half_rn(v1);
    } else if (EPI == 5) {
        Eh[(long)row * ldc + col] = __float2half_rn(x);
        Eh[(long)row * ldc + col + 1] = __float2half_rn(y);
    } else {  // 6: MoE scatter to slot buffer
        int enc = Tl[row];
        int t = enc >> 1, slot = enc & 1;
        *reinterpret_cast<float2*>(Cm + ((long)t * 2 + slot) * C + col) = make_float2(x, y);
    }
}

// ================== 4-stage pipelined HMMA fp16 GEMM, single sync/iter ==================
// D = A @ B^T, both fp16.  2 SMEM tiles per stage (A, B).
#define LDT 20
#define TSZ (128 * LDT)
#define STAGES 4

__device__ __forceinline__ void load_chunks(
    uint32_t sb32, int stage, int k0, int tid, int m0, int n0, int M, int N,
    int lda, int ldb,
    const __half* __restrict__ Ah, const __half* __restrict__ Bh)
{
#pragma unroll
    for (int j = 0; j < 4; j++) {
        int c = tid + j * 256;
        int mat = c >> 9;          // 0:A 1:B
        int idx = c & 511;
        int row = idx >> 2;
        int seg = idx & 3;
        const __half* g;
        int vb = 16;
        if (mat == 0) {
            int r = m0 + row;
            if (r >= M) { r = M - 1; vb = 0; }
            g = Ah + (long)r * lda;
        } else {
            int r = n0 + row;
            if (r >= N) { r = N - 1; vb = 0; }
            g = Bh + (long)r * ldb;
        }
        g += k0 + seg * 8;
        uint32_t dst = sb32 + (uint32_t)((stage * 2 * TSZ + mat * TSZ + row * LDT + seg * 4) * 4);
        asm volatile("cp.async.ca.shared.global [%0], [%1], 16, %2;"
                     :: "r"(dst), "l"(g), "r"(vb) : "memory");
    }
}

template<int EPI>
__global__ void __launch_bounds__(256, 2)
hmma4_gemm_kernel(const __half* __restrict__ Ah, const __half* __restrict__ Bh,
                  float* __restrict__ Cm, __half* __restrict__ Eh,
                  const float* __restrict__ Xaux, float* __restrict__ Faux,
                  const float* __restrict__ Wrow, int eidx,
                  const int* __restrict__ Mdyn, const int* __restrict__ Tl,
                  int M, int N, int K, int lda, int ldb, int ldc,
                  long sA1, long sA2, long sB1, long sB2, long sC1, long sC2, int div)
{
    extern __shared__ uint32_t smp[];
    int z = blockIdx.z;
    int z1 = z / div, z2 = z % div;
    if (Mdyn) { M = Mdyn[z1]; Tl += (long)z1 * BS; }
    const int m0 = blockIdx.y * 128;
    if (m0 >= M) return;
    const int tid = threadIdx.x;
    const int lane = tid & 31;
    const int w = tid >> 5;
    const int wm = w & 3;
    const int wn = w >> 2;
    const int gid = lane >> 2;
    const int tig = lane & 3;
    const int n0 = blockIdx.x * 128;
    uint32_t sb32 = (uint32_t)__cvta_generic_to_shared(smp);

    Ah += z1 * sA1 + z2 * sA2;
    Bh += z1 * sB1 + z2 * sB2;
    Cm += z1 * sC1 + z2 * sC2;
    if (EPI == 5) { Eh += z1 * sC1 + z2 * sC2; }
    if (EPI == 3) { Eh += (long)z1 * BS * HID; eidx = z1; }

    // ldmatrix per-lane row offsets (u32 units within a tile)
    const int la7 = lane & 7;
    const uint32_t a_off = (uint32_t)((wm * 32 + la7 + ((lane >> 3) & 1) * 8) * LDT + (lane >> 4) * 4);
    const uint32_t b_off = (uint32_t)((wn * 64 + la7 + ((lane >> 4) & 1) * 8) * LDT + ((lane >> 3) & 1) * 4);

    float acc[2][8][4];
#pragma unroll
    for (int i = 0; i < 2; i++)
#pragma unroll
        for (int j = 0; j < 8; j++)
#pragma unroll
            for (int q = 0; q < 4; q++) acc[i][j][q] = 0.f;

    const int NKB = K >> 5;

    // prologue: up to 3 stages in flight
#pragma unroll
    for (int s = 0; s < 3; s++) {
        if (s < NKB) {
            load_chunks(sb32, s, s << 5, tid, m0, n0, M, N, lda, ldb, Ah, Bh);
            asm volatile("cp.async.commit_group;" ::: "memory");
        }
    }

    for (int kb = 0; kb < NKB; kb++) {
        int rem = NKB - 1 - kb;           // loads still pending beyond kb
        if (rem >= 2)      asm volatile("cp.async.wait_group 2;" ::: "memory");
        else if (rem == 1) asm volatile("cp.async.wait_group 1;" ::: "memory");
        else               asm volatile("cp.async.wait_group 0;" ::: "memory");
        __syncthreads();

        if (kb + 3 < NKB) {
            load_chunks(sb32, (kb + 3) & 3, (kb + 3) << 5, tid, m0, n0, M, N, lda, ldb, Ah, Bh);
            asm volatile("cp.async.commit_group;" ::: "memory");
        }

        const uint32_t stg = sb32 + (uint32_t)((kb & 3) * 2 * TSZ * 4);

#pragma unroll
        for (int k16 = 0; k16 < 2; k16++) {
            const uint32_t kb8 = (uint32_t)(k16 * 8);
            uint32_t ahi[2][4];
            {
                uint32_t aaddr = stg + (a_off + kb8) * 4;
                ldsm4(ahi[0], aaddr);
                ldsm4(ahi[1], aaddr + 16 * LDT * 4);
            }
#pragma unroll
            for (int ntp = 0; ntp < 4; ntp++) {
                uint32_t bq[4];
                ldsm4(bq, stg + TSZ * 4 + (b_off + (uint32_t)(ntp * 16 * LDT) + kb8) * 4);
#pragma unroll
                for (int mt = 0; mt < 2; mt++) {
                    mma16816(acc[mt][ntp * 2],     ahi[mt], bq);
                    mma16816(acc[mt][ntp * 2 + 1], ahi[mt], bq + 2);
                }
            }
        }
        // no trailing sync: next iteration's barrier protects stage reuse
    }

    // ---- fused epilogue ----
#pragma unroll
    for (int mt = 0; mt < 2; mt++) {
        int row = m0 + wm * 32 + mt * 16 + gid;
#pragma unroll
        for (int nt = 0; nt < 8; nt++) {
            int col = n0 + wn * 64 + nt * 8 + tig * 2;
            if (col >= N) continue;
            if (row < M)
                epi_store<EPI>(row, col, acc[mt][nt][0], acc[mt][nt][1], ldc,
                               Cm, Eh, Xaux, Faux, Wrow, eidx, Tl);
            if (row + 8 < M)
                epi_store<EPI>(row + 8, col, acc[mt][nt][2], acc[mt][nt][3], ldc,
                               Cm, Eh, Xaux, Faux, Wrow, eidx, Tl);
        }
    }
}

// ---------------- LayerNorm statistics (also zero MoE counters) ----------------
__global__ void stats_kernel(const float* __restrict__ x) {
    int b = blockIdx.x;
    if (b == 0 && threadIdx.x < NEXP) g_cnt[threadIdx.x] = 0;
    const float* xb = x + (long)b * C * S;
    const int N = C * S;
    float s = 0.f, s2 = 0.f;
    for (int i = threadIdx.x; i < N; i += blockDim.x) {
        float v = xb[i];
        s += v; s2 += v * v;
    }
    __shared__ float sh[256], sh2[256];
    int tid = threadIdx.x;
    sh[tid] = s; sh2[tid] = s2;
    __syncthreads();
    for (int st = 128; st > 0; st >>= 1) {
        if (tid < st) { sh[tid] += sh[tid + st]; sh2[tid] += sh2[tid + st]; }
        __syncthreads();
    }
    if (tid == 0) {
        float m = sh[0] / (float)N;
        g_stats[b * 2 + 0] = m;
        g_stats[b * 2 + 1] = sh2[0] / (float)N - m * m;
    }
}

// ---------------- LN apply + transpose + fp16 ----------------
__global__ void ln_kernel(const float* __restrict__ x,
                          const float* __restrict__ w,
                          const float* __restrict__ bia) {
    long idx = (long)blockIdx.x * blockDim.x + threadIdx.x;
    if (idx >= (long)BATCH * C * S) return;
    int b   = (int)(idx / ((long)C * S));
    int rem = (int)(idx % ((long)C * S));
    int c = rem / S, s = rem % S;
    float m   = g_stats[b * 2 + 0];
    float var = g_stats[b * 2 + 1];
    float y = (x[idx] - m) * rsqrtf(var + EPS) * w[rem] + bia[rem];
    g_tok1h[((long)b * S + s) * C + c] = __float2half_rn(y);
}

// ---------------- fused one-pass softmax -> fp16 P (padded) ----------------
__global__ void softmax_bf_kernel() {
    long row = blockIdx.x;                    // BH * S rows
    const float* p = g_attn + row * SP;
    __half* ph = g_ph + row * SP;
    int tid = threadIdx.x;
    __shared__ float sw[8];

    int i2 = tid + 512;
    float v0 = p[tid];
    float v1 = p[tid + 256];
    float v2 = (i2 < S) ? p[i2] : -1e30f;

    float mx = fmaxf(v0, fmaxf(v1, v2));
#pragma unroll
    for (int o = 16; o > 0; o >>= 1) mx = fmaxf(mx, __shfl_xor_sync(~0u, mx, o));
    if ((tid & 31) == 0) sw[tid >> 5] = mx;
    __syncthreads();
    if (tid < 32) {
        float m = (tid < 8) ? sw[tid] : -1e30f;
#pragma unroll
        for (int o = 4; o > 0; o >>= 1) m = fmaxf(m, __shfl_xor_sync(~0u, m, o));
        if (tid == 0) sw[0] = m;
    }
    __syncthreads();
    mx = sw[0];
    __syncthreads();

    float e0 = __expf(v0 - mx);
    float e1 = __expf(v1 - mx);
    float e2 = (i2 < S) ? __expf(v2 - mx) : 0.f;
    float sum = e0 + e1 + e2;
#pragma unroll
    for (int o = 16; o > 0; o >>= 1) sum += __shfl_xor_sync(~0u, sum, o);
    if ((tid & 31) == 0) sw[tid >> 5] = sum;
    __syncthreads();
    if (tid < 32) {
        float s = (tid < 8) ? sw[tid] : 0.f;
#pragma unroll
        for (int o = 4; o > 0; o >>= 1) s += __shfl_xor_sync(~0u, s, o);
        if (tid == 0) sw[0] = s;
    }
    __syncthreads();
    float inv = 1.f / sw[0];

    ph[tid]       = __float2half_rn(e0 * inv);
    ph[tid + 256] = __float2half_rn(e1 * inv);
    if (i2 < SP)
        ph[i2] = __float2half_rn((i2 < S) ? e2 * inv : 0.f);
}

// ---------------- router: weights + per-expert token lists ----------------
__global__ void router_kernel(const float* __restrict__ rw) {
    int t = blockIdx.x * blockDim.y + threadIdx.y;
    if (t >= BS) return;
    const float* tok = g_tok2 + (long)t * C;
    float l0 = 0.f, l1 = 0.f, l2 = 0.f;
    for (int c = threadIdx.x; c < C; c += 32) {
        float v = tok[c];
        l0 += v * rw[c * 3 + 0];
        l1 += v * rw[c * 3 + 1];
        l2 += v * rw[c * 3 + 2];
    }
#pragma unroll
    for (int off = 16; off > 0; off >>= 1) {
        l0 += __shfl_down_sync(0xFFFFFFFFu, l0, off);
        l1 += __shfl_down_sync(0xFFFFFFFFu, l1, off);
        l2 += __shfl_down_sync(0xFFFFFFFFu, l2, off);
    }
    if (threadIdx.x == 0) {
        float mx = fmaxf(l0, fmaxf(l1, l2));
        float e0 = __expf(l0 - mx), e1 = __expf(l1 - mx), e2 = __expf(l2 - mx);
        float tot = e0 + e1 + e2;
        float p[3] = { e0 / tot, e1 / tot, e2 / tot };
        int i1 = 0;
        if (p[1] > p[i1]) i1 = 1;
        if (p[2] > p[i1]) i1 = 2;
        int i2 = -1;
        for (int i = 0; i < 3; i++) {
            if (i == i1) continue;
            if (i2 < 0 || p[i] > p[i2]) i2 = i;
        }
        float den = p[i1] + p[i2];
        float w[3] = { 0.f, 0.f, 0.f };
        w[i1] = p[i1] / den;
        w[i2] = p[i2] / den;
        g_w[t * 3 + 0] = w[0];
        g_w[t * 3 + 1] = w[1];
        g_w[t * 3 + 2] = w[2];
        int p1 = atomicAdd(&g_cnt[i1], 1);
        g_tlist[i1 * BS + p1] = t * 2;
        int p2 = atomicAdd(&g_cnt[i2], 1);
        g_tlist[i2 * BS + p2] = t * 2 + 1;
    }
}

// ---------------- gather tok2 fp16 rows for all experts (grid.y = e) ----------------
__global__ void gather_kernel() {
    int e = blockIdx.y;
    int p = blockIdx.x * 8 + (threadIdx.x >> 5);
    if (p >= g_cnt[e]) return;
    int t = g_tlist[e * BS + p] >> 1;
    int lane = threadIdx.x & 31;
    const uint32_t* sh = reinterpret_cast<const uint32_t*>(g_tok2h + (long)t * C);
    uint32_t* dh = reinterpret_cast<uint32_t*>(g_ag + ((long)e * BS + p) * C);
#pragma unroll
    for (int i = 0; i < 12; i++)
        dh[lane + i * 32] = sh[lane + i * 32];
}

// ---------------- out(b,c,s) += slot0 + slot1 ----------------
__global__ void final_kernel(float* __restrict__ out) {
    long idx = (long)blockIdx.x * blockDim.x + threadIdx.x;
    if (idx >= (long)BATCH * C * S) return;
    int b   = (int)(idx / ((long)C * S));
    int rem = (int)(idx % ((long)C * S));
    int c = rem / S, s = rem % S;
    long t = (long)b * S + s;
    out[idx] += g_moe2[t * 2 * C + c] + g_moe2[t * 2 * C + C + c];
}

// ---------------- launcher ----------------
extern "C" void kernel_launch(void* const* d_in, const int* in_sizes, int n_in,
                              void* d_out, int out_size) {
    const float* x        = (const float*)d_in[0];
    const float* ln_w     = (const float*)d_in[1];
    const float* ln_b     = (const float*)d_in[2];
    const float* qkv_w    = (const float*)d_in[3];
    const float* proj_w   = (const float*)d_in[4];
    const float* router_w = (const float*)d_in[5];
    const float* gate_w   = (const float*)d_in[6];
    const float* up_w     = (const float*)d_in[7];
    const float* down_w   = (const float*)d_in[8];
    float* out = (float*)d_out;

    float *p_attn, *p_tok2, *p_moe2, *p_gw;
    __half *p_t1h, *p_oh, *p_t2h, *p_hid, *p_wt;
    __half *p_ph, *p_qh, *p_kh, *p_vth, *p_ag;
    int *p_cnt, *p_tlist;
    cudaGetSymbolAddress((void**)&p_attn, g_attn);
    cudaGetSymbolAddress((void**)&p_tok2, g_tok2);
    cudaGetSymbolAddress((void**)&p_moe2, g_moe2);
    cudaGetSymbolAddress((void**)&p_gw,   g_w);
    cudaGetSymbolAddress((void**)&p_t1h, g_tok1h);
    cudaGetSymbolAddress((void**)&p_oh,  g_oh);
    cudaGetSymbolAddress((void**)&p_t2h, g_tok2h);
    cudaGetSymbolAddress((void**)&p_hid, g_hid);
    cudaGetSymbolAddress((void**)&p_wt,  g_wt);
    cudaGetSymbolAddress((void**)&p_ph,  g_ph);
    cudaGetSymbolAddress((void**)&p_qh,  g_qh);
    cudaGetSymbolAddress((void**)&p_kh,  g_kh);
    cudaGetSymbolAddress((void**)&p_vth, g_vth);
    cudaGetSymbolAddress((void**)&p_ag,  g_ag);
    cudaGetSymbolAddress((void**)&p_cnt, g_cnt);
    cudaGetSymbolAddress((void**)&p_tlist, g_tlist);

    const int SMEM_GEMM = STAGES * 2 * TSZ * 4;   // 81920 B
    cudaFuncSetAttribute(hmma4_gemm_kernel<0>, cudaFuncAttributeMaxDynamicSharedMemorySize, SMEM_GEMM);
    cudaFuncSetAttribute(hmma4_gemm_kernel<2>, cudaFuncAttributeMaxDynamicSharedMemorySize, SMEM_GEMM);
    cudaFuncSetAttribute(hmma4_gemm_kernel<3>, cudaFuncAttributeMaxDynamicSharedMemorySize, SMEM_GEMM);
    cudaFuncSetAttribute(hmma4_gemm_kernel<4>, cudaFuncAttributeMaxDynamicSharedMemorySize, SMEM_GEMM);
    cudaFuncSetAttribute(hmma4_gemm_kernel<5>, cudaFuncAttributeMaxDynamicSharedMemorySize, SMEM_GEMM);
    cudaFuncSetAttribute(hmma4_gemm_kernel<6>, cudaFuncAttributeMaxDynamicSharedMemorySize, SMEM_GEMM);

    const long n_elem = (long)BATCH * C * S;
    const int MT = (BS + 127) / 128;   // 46 row tiles

    // 1) qkv weight conversion first
    wconv_kernel<<<dim3(3 * C / 32, C / 32, 1), 256>>>(qkv_w, p_wt + OFF_QKV, C, 3 * C, 1, 0, 0, 0);

    // 2-3) LayerNorm (+ counter reset)
    stats_kernel<<<BATCH, 256>>>(x);
    ln_kernel<<<(int)((n_elem + 255) / 256), 256>>>(x, ln_w, ln_b);

    // 4) qkv GEMM with fused q/k/v split epilogue
    hmma4_gemm_kernel<2><<<dim3(3 * C / 128, MT, 1), 256, SMEM_GEMM>>>(
        p_t1h, p_wt + OFF_QKV,
        nullptr, nullptr, nullptr, nullptr, nullptr, 0, nullptr, nullptr,
        BS, 3 * C, C, C, C, 0, 0, 0, 0, 0, 0, 0, 1);

    // 5) scores: per (b,h) 729x729 = q @ k^T
    hmma4_gemm_kernel<0><<<dim3(6, 6, BH), 256, SMEM_GEMM>>>(
        p_qh, p_kh,
        p_attn, nullptr, nullptr, nullptr, nullptr, 0, nullptr, nullptr,
        S, S, DH, DH, DH, SP,
        (long)NH * S * DH, (long)S * DH,
        (long)NH * S * DH, (long)S * DH,
        (long)NH * S * SP, (long)S * SP, NH);

    // 6) softmax -> fp16 P
    softmax_bf_kernel<<<BH * S, 256>>>();

    // 7-10) remaining weight conversions (batched over experts)
    wconv_kernel<<<dim3(C / 32, C / 32, 1), 256>>>(proj_w, p_wt + OFF_PROJ, C, C, 1, 0, 0, 0);
    wconv_kernel<<<dim3(HID / 32, C / 32, NEXP), 256>>>(
        gate_w, p_wt + OFF_GU, C, HID, 2, 0, (long)C * HID, WSZ_GU2);
    wconv_kernel<<<dim3(HID / 32, C / 32, NEXP), 256>>>(
        up_w,   p_wt + OFF_GU, C, HID, 2, 1, (long)C * HID, WSZ_GU2);
    wconv_kernel<<<dim3(C / 32, HID / 32, NEXP), 256>>>(
        down_w, p_wt + OFF_DOWN, HID, C, 1, 0, (long)HID * C, WSZ_DN);

    // PV: per (b,h) 729x96 = P @ V, fp16 out
    hmma4_gemm_kernel<5><<<dim3(1, 6, BH), 256, SMEM_GEMM>>>(
        p_ph, p_vth,
        nullptr, p_oh, nullptr, nullptr, nullptr, 0, nullptr, nullptr,
        S, DH, SP, SP, SP, C,
        (long)NH * S * SP, (long)S * SP,
        (long)NH * DH * SP, (long)DH * SP,
        (long)S * C, DH, NH);

    // proj GEMM + fused residual (writes out, tok2 fp32 + fp16)
    hmma4_gemm_kernel<4><<<dim3(C / 128, MT, 1), 256, SMEM_GEMM>>>(
        p_oh, p_wt + OFF_PROJ,
        p_tok2, p_t2h, x, out, nullptr, 0, nullptr, nullptr,
        BS, C, C, C, C, C, 0, 0, 0, 0, 0, 0, 1);

    // router (weights + token lists)
    {
        dim3 blk(32, 8);
        router_kernel<<<(BS + 7) / 8, blk>>>(router_w);
    }

    // MoE: one gather, one gate/up GEMM, one down GEMM (all batched over experts)
    gather_kernel<<<dim3((BS + 7) / 8, NEXP), 256>>>();

    hmma4_gemm_kernel<3><<<dim3(2 * HID / 128, MT, NEXP), 256, SMEM_GEMM>>>(
        p_ag, p_wt + OFF_GU,
        nullptr, p_hid, nullptr, nullptr, p_gw, 0, p_cnt, p_tlist,
        BS, 2 * HID, C, C, C, 0,
        (long)BS * C, 0, WSZ_GU2, 0, 0, 0, 1);

    hmma4_gemm_kernel<6><<<dim3(C / 128, MT, NEXP), 256, SMEM_GEMM>>>(
        p_hid, p_wt + OFF_DOWN,
        p_moe2, nullptr, nullptr, nullptr, nullptr, 0, p_cnt, p_tlist,
        BS, C, HID, HID, HID, C,
        (long)BS * HID, 0, WSZ_DN, 0, 0, 0, 1);

    // final add
    final_kernel<<<(int)((n_elem + 255) / 256), 256>>>(out);
}